// round 2
// baseline (speedup 1.0000x reference)
#include <cuda_runtime.h>
#include <cstdint>

#define B_SZ   2
#define L_SEQ  2048
#define NH     16
#define FDIM   16
#define VDIM   64
#define DMODEL 1024
#define MTOT   (B_SZ * L_SEQ)   // 4096

// Scratch (device globals: allocation-free rule)
__device__ float g_Q[(size_t)MTOT * NH * FDIM];   // (b*l, 256)
__device__ float g_K[(size_t)MTOT * NH * FDIM];
__device__ float g_V[(size_t)MTOT * DMODEL];      // (b*l, h*64)
__device__ float g_Y[(size_t)MTOT * DMODEL];

// ---------------------------------------------------------------------------
// 128x128x16 fp32 SGEMM, 256 threads, 8x8 per-thread tile.
// blockIdx.z selects (B0,C0) vs (B1,C1) so Q and K projections fuse into one
// launch. M,N,K must be multiples of 128/128/16 (they are: 4096, 256|1024, 1024).
// ---------------------------------------------------------------------------
__global__ __launch_bounds__(256)
void sgemm128(const float* __restrict__ A,
              const float* __restrict__ B0, const float* __restrict__ B1,
              float* __restrict__ C0, float* __restrict__ C1,
              int M, int N, int K)
{
    const float* B = (blockIdx.z == 0) ? B0 : B1;
    float*       C = (blockIdx.z == 0) ? C0 : C1;

    __shared__ float As[16][128];   // transposed A tile: As[k][m]
    __shared__ float Bs[16][128];   // Bs[k][n]

    const int tid  = threadIdx.x;
    const int row0 = (tid >> 4) * 8;
    const int col0 = (tid & 15) * 8;
    const int rA = tid >> 2, cA = (tid & 3) << 2;   // rA in [0,64), 2 rows per thread
    const int rB = tid >> 5, cB = (tid & 31) << 2;  // rB in [0,8),  2 rows per thread

    const float* Ab = A + (size_t)blockIdx.y * 128 * K;
    const float* Bb = B + (size_t)blockIdx.x * 128;

    float acc[8][8];
    #pragma unroll
    for (int i = 0; i < 8; i++)
        #pragma unroll
        for (int j = 0; j < 8; j++) acc[i][j] = 0.f;

    for (int k0 = 0; k0 < K; k0 += 16) {
        // full tile loads: 128x16 A (512 float4), 16x128 B (512 float4), 2 each/thread
        float4 a0 = *(const float4*)(Ab + (size_t)rA * K + k0 + cA);
        float4 a1 = *(const float4*)(Ab + (size_t)(rA + 64) * K + k0 + cA);
        float4 b0 = *(const float4*)(Bb + (size_t)(k0 + rB) * N + cB);
        float4 b1 = *(const float4*)(Bb + (size_t)(k0 + rB + 8) * N + cB);
        __syncthreads();
        As[cA + 0][rA] = a0.x;  As[cA + 0][rA + 64] = a1.x;
        As[cA + 1][rA] = a0.y;  As[cA + 1][rA + 64] = a1.y;
        As[cA + 2][rA] = a0.z;  As[cA + 2][rA + 64] = a1.z;
        As[cA + 3][rA] = a0.w;  As[cA + 3][rA + 64] = a1.w;
        *(float4*)&Bs[rB][cB]     = b0;
        *(float4*)&Bs[rB + 8][cB] = b1;
        __syncthreads();

        #pragma unroll
        for (int kk = 0; kk < 16; kk++) {
            float av[8], bv[8];
            *(float4*)&av[0] = *(const float4*)&As[kk][row0];
            *(float4*)&av[4] = *(const float4*)&As[kk][row0 + 4];
            *(float4*)&bv[0] = *(const float4*)&Bs[kk][col0];
            *(float4*)&bv[4] = *(const float4*)&Bs[kk][col0 + 4];
            #pragma unroll
            for (int i = 0; i < 8; i++)
                #pragma unroll
                for (int j = 0; j < 8; j++)
                    acc[i][j] += av[i] * bv[j];
        }
    }

    float* Cb = C + (size_t)(blockIdx.y * 128 + row0) * N + blockIdx.x * 128 + col0;
    #pragma unroll
    for (int i = 0; i < 8; i++) {
        *(float4*)(Cb + (size_t)i * N)     = make_float4(acc[i][0], acc[i][1], acc[i][2], acc[i][3]);
        *(float4*)(Cb + (size_t)i * N + 4) = make_float4(acc[i][4], acc[i][5], acc[i][6], acc[i][7]);
    }
}

// ---------------------------------------------------------------------------
// Causal quadratic attention with Taylor-exp score.
// qf . kf  ==  1 + s + s^2/2,  s = (q.k)/sqrt(16) = 0.25*(q.k)
// y[n] = sum_{m<=n} phi(s_nm) v[m] / (sum_{m<=n} phi(s_nm) + 1e-12)
// Grid: (L/64, NH, B). Block: 256 threads; 64 q-rows x 64 v-dims output,
// 4x4 per-thread register tile.
// ---------------------------------------------------------------------------
__global__ __launch_bounds__(256)
void attn_kernel()
{
    __shared__ float qs[64][FDIM + 1];
    __shared__ float ks[64][FDIM + 1];
    __shared__ float vs[64][VDIM];
    __shared__ float as_[64][65];
    __shared__ float zrow[64];

    const int qt  = blockIdx.x;
    const int h   = blockIdx.y;
    const int b   = blockIdx.z;
    const int tid = threadIdx.x;
    const int tx  = tid & 15, ty = tid >> 4;
    const int row0 = ty * 4, col0 = tx * 4;

    // load q tile (64 x 16)
    {
        int r = tid >> 2, c = (tid & 3) << 2;
        float4 q4 = *(const float4*)&g_Q[((size_t)(b * L_SEQ + qt * 64 + r)) * (NH * FDIM) + h * FDIM + c];
        qs[r][c] = q4.x; qs[r][c + 1] = q4.y; qs[r][c + 2] = q4.z; qs[r][c + 3] = q4.w;
    }

    float acc[4][4];
    #pragma unroll
    for (int i = 0; i < 4; i++)
        #pragma unroll
        for (int j = 0; j < 4; j++) acc[i][j] = 0.f;
    float dden[4] = {0.f, 0.f, 0.f, 0.f};

    for (int kt = 0; kt <= qt; kt++) {
        __syncthreads();   // protect previous-iter reads of ks/vs/as_ (and qs on first iter)
        {
            int r = tid >> 2, c = (tid & 3) << 2;
            float4 k4 = *(const float4*)&g_K[((size_t)(b * L_SEQ + kt * 64 + r)) * (NH * FDIM) + h * FDIM + c];
            ks[r][c] = k4.x; ks[r][c + 1] = k4.y; ks[r][c + 2] = k4.z; ks[r][c + 3] = k4.w;
        }
        #pragma unroll
        for (int u = 0; u < 4; u++) {
            int lin = tid + u * 256;
            int r = lin >> 4, c = (lin & 15) << 2;
            *(float4*)&vs[r][c] =
                *(const float4*)&g_V[((size_t)(b * L_SEQ + kt * 64 + r)) * DMODEL + h * VDIM + c];
        }
        __syncthreads();

        // phase 1: scores -> smem, partial row sums for denominator
        const bool diag = (kt == qt);
        #pragma unroll
        for (int i = 0; i < 4; i++) {
            const int r = row0 + i;
            #pragma unroll
            for (int j = 0; j < 4; j++) {
                const int cl = col0 + j;
                float s = 0.f;
                #pragma unroll
                for (int f = 0; f < FDIM; f++) s += qs[r][f] * ks[cl][f];
                s *= 0.25f;
                float phi = 1.f + s + 0.5f * s * s;
                if (diag && cl > r) phi = 0.f;
                as_[r][cl] = phi;
                dden[i] += phi;
            }
        }
        __syncthreads();

        // phase 2: acc += A(64x64) @ V(64x64)
        #pragma unroll 8
        for (int kk = 0; kk < 64; kk++) {
            float a0 = as_[row0 + 0][kk];
            float a1 = as_[row0 + 1][kk];
            float a2 = as_[row0 + 2][kk];
            float a3 = as_[row0 + 3][kk];
            float4 bb = *(const float4*)&vs[kk][col0];
            acc[0][0] += a0 * bb.x; acc[0][1] += a0 * bb.y; acc[0][2] += a0 * bb.z; acc[0][3] += a0 * bb.w;
            acc[1][0] += a1 * bb.x; acc[1][1] += a1 * bb.y; acc[1][2] += a1 * bb.z; acc[1][3] += a1 * bb.w;
            acc[2][0] += a2 * bb.x; acc[2][1] += a2 * bb.y; acc[2][2] += a2 * bb.z; acc[2][3] += a2 * bb.w;
            acc[3][0] += a3 * bb.x; acc[3][1] += a3 * bb.y; acc[3][2] += a3 * bb.z; acc[3][3] += a3 * bb.w;
        }
    }

    // denominator: reduce dden across the 16 tx-threads sharing each row
    __syncthreads();
    #pragma unroll
    for (int i = 0; i < 4; i++) as_[row0 + i][tx] = dden[i];
    __syncthreads();
    if (tid < 64) {
        float s = 0.f;
        #pragma unroll
        for (int t = 0; t < 16; t++) s += as_[tid][t];
        zrow[tid] = 1.f / (s + 1e-12f);
    }
    __syncthreads();

    #pragma unroll
    for (int i = 0; i < 4; i++) {
        float z = zrow[row0 + i];
        float4 o = make_float4(acc[i][0] * z, acc[i][1] * z, acc[i][2] * z, acc[i][3] * z);
        *(float4*)&g_Y[((size_t)(b * L_SEQ + qt * 64 + row0 + i)) * DMODEL + h * VDIM + col0] = o;
    }
}

// ---------------------------------------------------------------------------
extern "C" void kernel_launch(void* const* d_in, const int* in_sizes, int n_in,
                              void* d_out, int out_size)
{
    const float* X  = (const float*)d_in[0];
    const float* Wq = (const float*)d_in[1];
    const float* Wk = (const float*)d_in[2];
    const float* Wv = (const float*)d_in[3];
    const float* Wo = (const float*)d_in[4];
    float* out = (float*)d_out;

    float *Q, *K, *V, *Y;
    cudaGetSymbolAddress((void**)&Q, g_Q);
    cudaGetSymbolAddress((void**)&K, g_K);
    cudaGetSymbolAddress((void**)&V, g_V);
    cudaGetSymbolAddress((void**)&Y, g_Y);

    dim3 blk(256);
    // Q and K projections fused via blockIdx.z: (4096 x 256) = (4096 x 1024) @ W
    sgemm128<<<dim3((NH * FDIM) / 128, MTOT / 128, 2), blk>>>(X, Wq, Wk, Q, K,
                                                              MTOT, NH * FDIM, DMODEL);
    // V projection: (4096 x 1024)
    sgemm128<<<dim3(DMODEL / 128, MTOT / 128, 1), blk>>>(X, Wv, Wv, V, V,
                                                         MTOT, DMODEL, DMODEL);
    // causal taylor-exp attention
    attn_kernel<<<dim3(L_SEQ / 64, NH, B_SZ), blk>>>();
    // output projection: (4096 x 1024) @ Wo -> d_out
    sgemm128<<<dim3(DMODEL / 128, MTOT / 128, 1), blk>>>(Y, Wo, Wo, out, out,
                                                         MTOT, DMODEL, DMODEL);
}

// round 4
// speedup vs baseline: 1.4438x; 1.4438x over previous
#include <cuda_runtime.h>
#include <cuda_bf16.h>
#include <cstdint>

#define B_SZ   2
#define L_SEQ  2048
#define NH     16
#define FDIM   16
#define VDIM   64
#define DMODEL 1024
#define MTOT   (B_SZ * L_SEQ)   // 4096
#define NQK    (NH * FDIM)      // 256

// ------------------------------ scratch (device globals) -------------------
__device__ float g_Q[(size_t)MTOT * NQK];
__device__ float g_K[(size_t)MTOT * NQK];
__device__ float g_V[(size_t)MTOT * DMODEL];
__device__ float g_Y[(size_t)MTOT * DMODEL];

__device__ __nv_bfloat16 g_Xhi[(size_t)MTOT * DMODEL];
__device__ __nv_bfloat16 g_Xlo[(size_t)MTOT * DMODEL];
__device__ __nv_bfloat16 g_Yhi[(size_t)MTOT * DMODEL];
__device__ __nv_bfloat16 g_Ylo[(size_t)MTOT * DMODEL];

__device__ __nv_bfloat16 g_WqT_hi[(size_t)NQK * DMODEL];
__device__ __nv_bfloat16 g_WqT_lo[(size_t)NQK * DMODEL];
__device__ __nv_bfloat16 g_WkT_hi[(size_t)NQK * DMODEL];
__device__ __nv_bfloat16 g_WkT_lo[(size_t)NQK * DMODEL];
__device__ __nv_bfloat16 g_WvT_hi[(size_t)DMODEL * DMODEL];
__device__ __nv_bfloat16 g_WvT_lo[(size_t)DMODEL * DMODEL];
__device__ __nv_bfloat16 g_WoT_hi[(size_t)DMODEL * DMODEL];
__device__ __nv_bfloat16 g_WoT_lo[(size_t)DMODEL * DMODEL];

// ------------------------------ helpers ------------------------------------
__device__ __forceinline__ uint32_t smem_u32(const void* p) {
    uint32_t a;
    asm("{ .reg .u64 t; cvta.to.shared.u64 t, %1; cvt.u32.u64 %0, t; }" : "=r"(a) : "l"(p));
    return a;
}
__device__ __forceinline__ void cp_async16(uint32_t s, const void* g) {
    asm volatile("cp.async.cg.shared.global [%0], [%1], 16;" :: "r"(s), "l"(g));
}
#define CP_COMMIT() asm volatile("cp.async.commit_group;" ::: "memory")
#define CP_WAIT1()  asm volatile("cp.async.wait_group 1;" ::: "memory")

__device__ __forceinline__ void ldmatrix_x4(uint32_t& r0, uint32_t& r1, uint32_t& r2, uint32_t& r3,
                                            uint32_t addr) {
    asm volatile("ldmatrix.sync.aligned.m8n8.x4.shared.b16 {%0,%1,%2,%3}, [%4];"
                 : "=r"(r0), "=r"(r1), "=r"(r2), "=r"(r3) : "r"(addr));
}
__device__ __forceinline__ void mma16816(float* d, const uint32_t* a, const uint32_t* b) {
    asm volatile(
        "mma.sync.aligned.m16n8k16.row.col.f32.bf16.bf16.f32 "
        "{%0,%1,%2,%3},{%4,%5,%6,%7},{%8,%9},{%0,%1,%2,%3};"
        : "+f"(d[0]), "+f"(d[1]), "+f"(d[2]), "+f"(d[3])
        : "r"(a[0]), "r"(a[1]), "r"(a[2]), "r"(a[3]), "r"(b[0]), "r"(b[1]));
}

// ------------------------------ prep kernels -------------------------------
__global__ void split_bf16(const float4* __restrict__ x,
                           uint2* __restrict__ hi, uint2* __restrict__ lo, int n4)
{
    int i = blockIdx.x * blockDim.x + threadIdx.x;
    if (i >= n4) return;
    float4 v = x[i];
    float f[4] = {v.x, v.y, v.z, v.w};
    unsigned short h[4], l[4];
    #pragma unroll
    for (int c = 0; c < 4; c++) {
        __nv_bfloat16 hb = __float2bfloat16(f[c]);
        float r = f[c] - __bfloat162float(hb);
        h[c] = __bfloat16_as_ushort(hb);
        l[c] = __bfloat16_as_ushort(__float2bfloat16(r));
    }
    hi[i] = make_uint2((uint32_t)h[0] | ((uint32_t)h[1] << 16),
                       (uint32_t)h[2] | ((uint32_t)h[3] << 16));
    lo[i] = make_uint2((uint32_t)l[0] | ((uint32_t)l[1] << 16),
                       (uint32_t)l[2] | ((uint32_t)l[3] << 16));
}

// W: (K x N) row-major -> T: (N x K) bf16 hi/lo
__global__ void transpose_split(const float* __restrict__ W,
                                __nv_bfloat16* __restrict__ Thi,
                                __nv_bfloat16* __restrict__ Tlo, int K, int N)
{
    __shared__ float t[32][33];
    int n0 = blockIdx.x * 32, k0 = blockIdx.y * 32;
    t[threadIdx.y][threadIdx.x] = W[(size_t)(k0 + threadIdx.y) * N + n0 + threadIdx.x];
    __syncthreads();
    float v = t[threadIdx.x][threadIdx.y];    // = W[k0+tx][n0+ty]
    int n = n0 + threadIdx.y, k = k0 + threadIdx.x;
    __nv_bfloat16 hb = __float2bfloat16(v);
    float r = v - __bfloat162float(hb);
    Thi[(size_t)n * K + k] = hb;
    Tlo[(size_t)n * K + k] = __float2bfloat16(r);
}

// ------------------------------ HMMA GEMM ----------------------------------
// C(M x Nw) = A(M x K) @ B(Nw x K)^T, fp32 out, bf16 hi/lo split inputs.
// 128x128 CTA tile, 8 warps of 32x64, KC=32 double-buffered via cp.async.
// Smem row pitch 80 B (32 bf16 data + pad) -> ldmatrix conflict-free.
#define KC        32
#define ROWB      80
#define ARR_BYTES (128 * ROWB)          // 10240
#define BUF_BYTES (4 * ARR_BYTES)       // 40960: Ah, Al, Bh, Bl
#define GEMM_SMEM (2 * BUF_BYTES)       // 81920

__global__ __launch_bounds__(256, 1)
void gemm_mma(const __nv_bfloat16* __restrict__ Ahi, const __nv_bfloat16* __restrict__ Alo,
              const __nv_bfloat16* __restrict__ Bhi0, const __nv_bfloat16* __restrict__ Blo0,
              const __nv_bfloat16* __restrict__ Bhi1, const __nv_bfloat16* __restrict__ Blo1,
              float* __restrict__ C0, float* __restrict__ C1,
              int Nw, int K)
{
    const __nv_bfloat16* Bhi = blockIdx.z ? Bhi1 : Bhi0;
    const __nv_bfloat16* Blo = blockIdx.z ? Blo1 : Blo0;
    float* C = blockIdx.z ? C1 : C0;

    extern __shared__ char smem[];
    const uint32_t sb = smem_u32(smem);

    const int tid = threadIdx.x, lane = tid & 31, wid = tid >> 5;
    const int warp_m = wid & 3, warp_n = wid >> 2;
    const int m0 = blockIdx.y * 128, n0 = blockIdx.x * 128;
    const int nchunk = K / KC;

    // global->smem fill: per array 512 uint4, 2 per thread
    const int frow0 = tid >> 2, fcol = tid & 3;

    auto issue_chunk = [&](int c) {
        const uint32_t base = sb + (c & 1) * BUF_BYTES;
        const int k0 = c * KC;
        #pragma unroll
        for (int i = 0; i < 2; i++) {
            const int row = frow0 + i * 64;
            const uint32_t soff = (uint32_t)row * ROWB + fcol * 16;
            const size_t ga = (size_t)(m0 + row) * K + k0 + fcol * 8;
            const size_t gb = (size_t)(n0 + row) * K + k0 + fcol * 8;
            cp_async16(base + soff,                 Ahi + ga);
            cp_async16(base + ARR_BYTES + soff,     Alo + ga);
            cp_async16(base + 2 * ARR_BYTES + soff, Bhi + gb);
            cp_async16(base + 3 * ARR_BYTES + soff, Blo + gb);
        }
    };

    float acc[2][8][4];
    #pragma unroll
    for (int mt = 0; mt < 2; mt++)
        #pragma unroll
        for (int j = 0; j < 8; j++)
            #pragma unroll
            for (int q = 0; q < 4; q++) acc[mt][j][q] = 0.f;

    issue_chunk(0);
    CP_COMMIT();

    // ldmatrix source coords (see fragment-layout derivation)
    const int arow_l = (lane & 15);
    const int akc_l  = (lane >> 4) << 3;
    const int brow_l = (lane & 7) + ((lane & 16) ? 8 : 0);
    const int bkc_l  = (lane & 8) ? 8 : 0;

    for (int c = 0; c < nchunk; c++) {
        if (c + 1 < nchunk) issue_chunk(c + 1);
        CP_COMMIT();
        CP_WAIT1();
        __syncthreads();

        const uint32_t base = sb + (c & 1) * BUF_BYTES;
        #pragma unroll
        for (int ks = 0; ks < 2; ks++) {
            uint32_t ah[2][4], al[2][4];
            #pragma unroll
            for (int mt = 0; mt < 2; mt++) {
                uint32_t addr = base + (uint32_t)(warp_m * 32 + mt * 16 + arow_l) * ROWB
                              + (ks * 16 + akc_l) * 2;
                ldmatrix_x4(ah[mt][0], ah[mt][1], ah[mt][2], ah[mt][3], addr);
                ldmatrix_x4(al[mt][0], al[mt][1], al[mt][2], al[mt][3], addr + ARR_BYTES);
            }
            #pragma unroll
            for (int jp = 0; jp < 4; jp++) {
                uint32_t baddr = base + 2 * ARR_BYTES
                               + (uint32_t)(warp_n * 64 + jp * 16 + brow_l) * ROWB
                               + (ks * 16 + bkc_l) * 2;
                uint32_t bh[4], bl[4];
                ldmatrix_x4(bh[0], bh[1], bh[2], bh[3], baddr);
                ldmatrix_x4(bl[0], bl[1], bl[2], bl[3], baddr + ARR_BYTES);
                #pragma unroll
                for (int sub = 0; sub < 2; sub++) {
                    const int j = jp * 2 + sub;
                    #pragma unroll
                    for (int mt = 0; mt < 2; mt++) {
                        mma16816(acc[mt][j], ah[mt], &bh[sub * 2]);
                        mma16816(acc[mt][j], ah[mt], &bl[sub * 2]);
                        mma16816(acc[mt][j], al[mt], &bh[sub * 2]);
                    }
                }
            }
        }
        __syncthreads();
    }

    // epilogue: c0,c1 -> (row, col..col+1); c2,c3 -> row+8
    #pragma unroll
    for (int mt = 0; mt < 2; mt++) {
        const int r0 = m0 + warp_m * 32 + mt * 16 + (lane >> 2);
        #pragma unroll
        for (int j = 0; j < 8; j++) {
            const int col = n0 + warp_n * 64 + j * 8 + (lane & 3) * 2;
            *(float2*)&C[(size_t)r0 * Nw + col]       = make_float2(acc[mt][j][0], acc[mt][j][1]);
            *(float2*)&C[(size_t)(r0 + 8) * Nw + col] = make_float2(acc[mt][j][2], acc[mt][j][3]);
        }
    }
}

// ------------------------------ attention (unchanged) ----------------------
__global__ __launch_bounds__(256)
void attn_kernel()
{
    __shared__ float qs[64][FDIM + 1];
    __shared__ float ks[64][FDIM + 1];
    __shared__ float vs[64][VDIM];
    __shared__ float as_[64][65];
    __shared__ float zrow[64];

    const int qt  = blockIdx.x;
    const int h   = blockIdx.y;
    const int b   = blockIdx.z;
    const int tid = threadIdx.x;
    const int tx  = tid & 15, ty = tid >> 4;
    const int row0 = ty * 4, col0 = tx * 4;

    {
        int r = tid >> 2, c = (tid & 3) << 2;
        float4 q4 = *(const float4*)&g_Q[((size_t)(b * L_SEQ + qt * 64 + r)) * NQK + h * FDIM + c];
        qs[r][c] = q4.x; qs[r][c + 1] = q4.y; qs[r][c + 2] = q4.z; qs[r][c + 3] = q4.w;
    }

    float acc[4][4];
    #pragma unroll
    for (int i = 0; i < 4; i++)
        #pragma unroll
        for (int j = 0; j < 4; j++) acc[i][j] = 0.f;
    float dden[4] = {0.f, 0.f, 0.f, 0.f};

    for (int kt = 0; kt <= qt; kt++) {
        __syncthreads();
        {
            int r = tid >> 2, c = (tid & 3) << 2;
            float4 k4 = *(const float4*)&g_K[((size_t)(b * L_SEQ + kt * 64 + r)) * NQK + h * FDIM + c];
            ks[r][c] = k4.x; ks[r][c + 1] = k4.y; ks[r][c + 2] = k4.z; ks[r][c + 3] = k4.w;
        }
        #pragma unroll
        for (int u = 0; u < 4; u++) {
            int lin = tid + u * 256;
            int r = lin >> 4, c = (lin & 15) << 2;
            *(float4*)&vs[r][c] =
                *(const float4*)&g_V[((size_t)(b * L_SEQ + kt * 64 + r)) * DMODEL + h * VDIM + c];
        }
        __syncthreads();

        const bool diag = (kt == qt);
        #pragma unroll
        for (int i = 0; i < 4; i++) {
            const int r = row0 + i;
            #pragma unroll
            for (int j = 0; j < 4; j++) {
                const int cl = col0 + j;
                float s = 0.f;
                #pragma unroll
                for (int f = 0; f < FDIM; f++) s += qs[r][f] * ks[cl][f];
                s *= 0.25f;
                float phi = 1.f + s + 0.5f * s * s;
                if (diag && cl > r) phi = 0.f;
                as_[r][cl] = phi;
                dden[i] += phi;
            }
        }
        __syncthreads();

        #pragma unroll 8
        for (int kk = 0; kk < 64; kk++) {
            float a0 = as_[row0 + 0][kk];
            float a1 = as_[row0 + 1][kk];
            float a2 = as_[row0 + 2][kk];
            float a3 = as_[row0 + 3][kk];
            float4 bb = *(const float4*)&vs[kk][col0];
            acc[0][0] += a0 * bb.x; acc[0][1] += a0 * bb.y; acc[0][2] += a0 * bb.z; acc[0][3] += a0 * bb.w;
            acc[1][0] += a1 * bb.x; acc[1][1] += a1 * bb.y; acc[1][2] += a1 * bb.z; acc[1][3] += a1 * bb.w;
            acc[2][0] += a2 * bb.x; acc[2][1] += a2 * bb.y; acc[2][2] += a2 * bb.z; acc[2][3] += a2 * bb.w;
            acc[3][0] += a3 * bb.x; acc[3][1] += a3 * bb.y; acc[3][2] += a3 * bb.z; acc[3][3] += a3 * bb.w;
        }
    }

    __syncthreads();
    #pragma unroll
    for (int i = 0; i < 4; i++) as_[row0 + i][tx] = dden[i];
    __syncthreads();
    if (tid < 64) {
        float s = 0.f;
        #pragma unroll
        for (int t = 0; t < 16; t++) s += as_[tid][t];
        zrow[tid] = 1.f / (s + 1e-12f);
    }
    __syncthreads();

    #pragma unroll
    for (int i = 0; i < 4; i++) {
        float z = zrow[row0 + i];
        float4 o = make_float4(acc[i][0] * z, acc[i][1] * z, acc[i][2] * z, acc[i][3] * z);
        *(float4*)&g_Y[((size_t)(b * L_SEQ + qt * 64 + row0 + i)) * DMODEL + h * VDIM + col0] = o;
    }
}

// ---------------------------------------------------------------------------
extern "C" void kernel_launch(void* const* d_in, const int* in_sizes, int n_in,
                              void* d_out, int out_size)
{
    const float* X  = (const float*)d_in[0];
    const float* Wq = (const float*)d_in[1];
    const float* Wk = (const float*)d_in[2];
    const float* Wv = (const float*)d_in[3];
    const float* Wo = (const float*)d_in[4];
    float* out = (float*)d_out;

    float *Q, *K, *V, *Y;
    __nv_bfloat16 *Xhi, *Xlo, *Yhi, *Ylo;
    __nv_bfloat16 *WqTh, *WqTl, *WkTh, *WkTl, *WvTh, *WvTl, *WoTh, *WoTl;
    cudaGetSymbolAddress((void**)&Q, g_Q);
    cudaGetSymbolAddress((void**)&K, g_K);
    cudaGetSymbolAddress((void**)&V, g_V);
    cudaGetSymbolAddress((void**)&Y, g_Y);
    cudaGetSymbolAddress((void**)&Xhi, g_Xhi);
    cudaGetSymbolAddress((void**)&Xlo, g_Xlo);
    cudaGetSymbolAddress((void**)&Yhi, g_Yhi);
    cudaGetSymbolAddress((void**)&Ylo, g_Ylo);
    cudaGetSymbolAddress((void**)&WqTh, g_WqT_hi);
    cudaGetSymbolAddress((void**)&WqTl, g_WqT_lo);
    cudaGetSymbolAddress((void**)&WkTh, g_WkT_hi);
    cudaGetSymbolAddress((void**)&WkTl, g_WkT_lo);
    cudaGetSymbolAddress((void**)&WvTh, g_WvT_hi);
    cudaGetSymbolAddress((void**)&WvTl, g_WvT_lo);
    cudaGetSymbolAddress((void**)&WoTh, g_WoT_hi);
    cudaGetSymbolAddress((void**)&WoTl, g_WoT_lo);

    cudaFuncSetAttribute(gemm_mma, cudaFuncAttributeMaxDynamicSharedMemorySize, GEMM_SMEM);

    const int n4 = MTOT * DMODEL / 4;
    split_bf16<<<(n4 + 255) / 256, 256>>>((const float4*)X, (uint2*)Xhi, (uint2*)Xlo, n4);
    transpose_split<<<dim3(NQK / 32,    DMODEL / 32), dim3(32, 32)>>>(Wq, WqTh, WqTl, DMODEL, NQK);
    transpose_split<<<dim3(NQK / 32,    DMODEL / 32), dim3(32, 32)>>>(Wk, WkTh, WkTl, DMODEL, NQK);
    transpose_split<<<dim3(DMODEL / 32, DMODEL / 32), dim3(32, 32)>>>(Wv, WvTh, WvTl, DMODEL, DMODEL);
    transpose_split<<<dim3(DMODEL / 32, DMODEL / 32), dim3(32, 32)>>>(Wo, WoTh, WoTl, DMODEL, DMODEL);

    // Q & K projections (z-fused): C(4096 x 256)
    gemm_mma<<<dim3(NQK / 128, MTOT / 128, 2), 256, GEMM_SMEM>>>(
        Xhi, Xlo, WqTh, WqTl, WkTh, WkTl, Q, K, NQK, DMODEL);
    // V projection: C(4096 x 1024)
    gemm_mma<<<dim3(DMODEL / 128, MTOT / 128, 1), 256, GEMM_SMEM>>>(
        Xhi, Xlo, WvTh, WvTl, WvTh, WvTl, V, V, DMODEL, DMODEL);
    // causal taylor-exp attention
    attn_kernel<<<dim3(L_SEQ / 64, NH, B_SZ), 256>>>();
    // split Y and output projection
    split_bf16<<<(n4 + 255) / 256, 256>>>((const float4*)Y, (uint2*)Yhi, (uint2*)Ylo, n4);
    gemm_mma<<<dim3(DMODEL / 128, MTOT / 128, 1), 256, GEMM_SMEM>>>(
        Yhi, Ylo, WoTh, WoTl, WoTh, WoTl, out, out, DMODEL, DMODEL);
}

// round 5
// speedup vs baseline: 1.8878x; 1.3075x over previous
#include <cuda_runtime.h>
#include <cuda_bf16.h>
#include <cstdint>

#define B_SZ   2
#define L_SEQ  2048
#define NH     16
#define FDIM   16
#define VDIM   64
#define DMODEL 1024
#define MTOT   (B_SZ * L_SEQ)   // 4096
#define NQK    (NH * FDIM)      // 256

// ------------------------------ scratch (device globals) -------------------
__device__ float g_Q[(size_t)MTOT * NQK];
__device__ float g_K[(size_t)MTOT * NQK];

__device__ __nv_bfloat16 g_Xhi[(size_t)MTOT * DMODEL];
__device__ __nv_bfloat16 g_Xlo[(size_t)MTOT * DMODEL];
__device__ __nv_bfloat16 g_Vhi[(size_t)MTOT * DMODEL];
__device__ __nv_bfloat16 g_Vlo[(size_t)MTOT * DMODEL];
__device__ __nv_bfloat16 g_Yhi[(size_t)MTOT * DMODEL];
__device__ __nv_bfloat16 g_Ylo[(size_t)MTOT * DMODEL];

__device__ __nv_bfloat16 g_WqT_hi[(size_t)NQK * DMODEL];
__device__ __nv_bfloat16 g_WqT_lo[(size_t)NQK * DMODEL];
__device__ __nv_bfloat16 g_WkT_hi[(size_t)NQK * DMODEL];
__device__ __nv_bfloat16 g_WkT_lo[(size_t)NQK * DMODEL];
__device__ __nv_bfloat16 g_WvT_hi[(size_t)DMODEL * DMODEL];
__device__ __nv_bfloat16 g_WvT_lo[(size_t)DMODEL * DMODEL];
__device__ __nv_bfloat16 g_WoT_hi[(size_t)DMODEL * DMODEL];
__device__ __nv_bfloat16 g_WoT_lo[(size_t)DMODEL * DMODEL];

// ------------------------------ helpers ------------------------------------
__device__ __forceinline__ uint32_t smem_u32(const void* p) {
    uint32_t a;
    asm("{ .reg .u64 t; cvta.to.shared.u64 t, %1; cvt.u32.u64 %0, t; }" : "=r"(a) : "l"(p));
    return a;
}
__device__ __forceinline__ void cp_async16(uint32_t s, const void* g) {
    asm volatile("cp.async.cg.shared.global [%0], [%1], 16;" :: "r"(s), "l"(g));
}
#define CP_COMMIT() asm volatile("cp.async.commit_group;" ::: "memory")
#define CP_WAIT1()  asm volatile("cp.async.wait_group 1;" ::: "memory")
#define CP_WAIT0()  asm volatile("cp.async.wait_group 0;" ::: "memory")

__device__ __forceinline__ void ldmatrix_x4(uint32_t& r0, uint32_t& r1, uint32_t& r2, uint32_t& r3,
                                            uint32_t addr) {
    asm volatile("ldmatrix.sync.aligned.m8n8.x4.shared.b16 {%0,%1,%2,%3}, [%4];"
                 : "=r"(r0), "=r"(r1), "=r"(r2), "=r"(r3) : "r"(addr));
}
__device__ __forceinline__ void ldmatrix_x4_t(uint32_t& r0, uint32_t& r1, uint32_t& r2, uint32_t& r3,
                                              uint32_t addr) {
    asm volatile("ldmatrix.sync.aligned.m8n8.x4.trans.shared.b16 {%0,%1,%2,%3}, [%4];"
                 : "=r"(r0), "=r"(r1), "=r"(r2), "=r"(r3) : "r"(addr));
}
__device__ __forceinline__ void mma16816(float* d, const uint32_t* a, const uint32_t* b) {
    asm volatile(
        "mma.sync.aligned.m16n8k16.row.col.f32.bf16.bf16.f32 "
        "{%0,%1,%2,%3},{%4,%5,%6,%7},{%8,%9},{%0,%1,%2,%3};"
        : "+f"(d[0]), "+f"(d[1]), "+f"(d[2]), "+f"(d[3])
        : "r"(a[0]), "r"(a[1]), "r"(a[2]), "r"(a[3]), "r"(b[0]), "r"(b[1]));
}
__device__ __forceinline__ void split2(float y0, float y1, uint32_t& hi, uint32_t& lo) {
    __nv_bfloat16 h0 = __float2bfloat16(y0);
    __nv_bfloat16 h1 = __float2bfloat16(y1);
    float r0 = y0 - __bfloat162float(h0);
    float r1 = y1 - __bfloat162float(h1);
    hi = (uint32_t)__bfloat16_as_ushort(h0) | ((uint32_t)__bfloat16_as_ushort(h1) << 16);
    lo = (uint32_t)__bfloat16_as_ushort(__float2bfloat16(r0))
       | ((uint32_t)__bfloat16_as_ushort(__float2bfloat16(r1)) << 16);
}

// ------------------------------ prep kernels -------------------------------
__global__ void split_bf16(const float4* __restrict__ x,
                           uint2* __restrict__ hi, uint2* __restrict__ lo, int n4)
{
    int i = blockIdx.x * blockDim.x + threadIdx.x;
    if (i >= n4) return;
    float4 v = x[i];
    float f[4] = {v.x, v.y, v.z, v.w};
    unsigned short h[4], l[4];
    #pragma unroll
    for (int c = 0; c < 4; c++) {
        __nv_bfloat16 hb = __float2bfloat16(f[c]);
        float r = f[c] - __bfloat162float(hb);
        h[c] = __bfloat16_as_ushort(hb);
        l[c] = __bfloat16_as_ushort(__float2bfloat16(r));
    }
    hi[i] = make_uint2((uint32_t)h[0] | ((uint32_t)h[1] << 16),
                       (uint32_t)h[2] | ((uint32_t)h[3] << 16));
    lo[i] = make_uint2((uint32_t)l[0] | ((uint32_t)l[1] << 16),
                       (uint32_t)l[2] | ((uint32_t)l[3] << 16));
}

// W: (K x N) row-major -> T: (N x K) bf16 hi/lo
__global__ void transpose_split(const float* __restrict__ W,
                                __nv_bfloat16* __restrict__ Thi,
                                __nv_bfloat16* __restrict__ Tlo, int K, int N)
{
    __shared__ float t[32][33];
    int n0 = blockIdx.x * 32, k0 = blockIdx.y * 32;
    t[threadIdx.y][threadIdx.x] = W[(size_t)(k0 + threadIdx.y) * N + n0 + threadIdx.x];
    __syncthreads();
    float v = t[threadIdx.x][threadIdx.y];
    int n = n0 + threadIdx.y, k = k0 + threadIdx.x;
    __nv_bfloat16 hb = __float2bfloat16(v);
    float r = v - __bfloat162float(hb);
    Thi[(size_t)n * K + k] = hb;
    Tlo[(size_t)n * K + k] = __float2bfloat16(r);
}

// ------------------------------ HMMA GEMM ----------------------------------
#define KC        32
#define ROWB      80
#define ARR_BYTES (128 * ROWB)
#define BUF_BYTES (4 * ARR_BYTES)
#define GEMM_SMEM (2 * BUF_BYTES)

__global__ __launch_bounds__(256, 1)
void gemm_mma(const __nv_bfloat16* __restrict__ Ahi, const __nv_bfloat16* __restrict__ Alo,
              const __nv_bfloat16* __restrict__ Bhi0, const __nv_bfloat16* __restrict__ Blo0,
              const __nv_bfloat16* __restrict__ Bhi1, const __nv_bfloat16* __restrict__ Blo1,
              float* __restrict__ C0, float* __restrict__ C1,
              __nv_bfloat16* __restrict__ Ohi, __nv_bfloat16* __restrict__ Olo,
              int split_out, int Nw, int K)
{
    const __nv_bfloat16* Bhi = blockIdx.z ? Bhi1 : Bhi0;
    const __nv_bfloat16* Blo = blockIdx.z ? Blo1 : Blo0;
    float* C = blockIdx.z ? C1 : C0;

    extern __shared__ char smem[];
    const uint32_t sb = smem_u32(smem);

    const int tid = threadIdx.x, lane = tid & 31, wid = tid >> 5;
    const int warp_m = wid & 3, warp_n = wid >> 2;
    const int m0 = blockIdx.y * 128, n0 = blockIdx.x * 128;
    const int nchunk = K / KC;

    const int frow0 = tid >> 2, fcol = tid & 3;

    auto issue_chunk = [&](int c) {
        const uint32_t base = sb + (c & 1) * BUF_BYTES;
        const int k0 = c * KC;
        #pragma unroll
        for (int i = 0; i < 2; i++) {
            const int row = frow0 + i * 64;
            const uint32_t soff = (uint32_t)row * ROWB + fcol * 16;
            const size_t ga = (size_t)(m0 + row) * K + k0 + fcol * 8;
            const size_t gb = (size_t)(n0 + row) * K + k0 + fcol * 8;
            cp_async16(base + soff,                 Ahi + ga);
            cp_async16(base + ARR_BYTES + soff,     Alo + ga);
            cp_async16(base + 2 * ARR_BYTES + soff, Bhi + gb);
            cp_async16(base + 3 * ARR_BYTES + soff, Blo + gb);
        }
    };

    float acc[2][8][4];
    #pragma unroll
    for (int mt = 0; mt < 2; mt++)
        #pragma unroll
        for (int j = 0; j < 8; j++)
            #pragma unroll
            for (int q = 0; q < 4; q++) acc[mt][j][q] = 0.f;

    issue_chunk(0);
    CP_COMMIT();

    const int arow_l = (lane & 15);
    const int akc_l  = (lane >> 4) << 3;
    const int brow_l = (lane & 7) + ((lane & 16) ? 8 : 0);
    const int bkc_l  = (lane & 8) ? 8 : 0;

    for (int c = 0; c < nchunk; c++) {
        if (c + 1 < nchunk) issue_chunk(c + 1);
        CP_COMMIT();
        CP_WAIT1();
        __syncthreads();

        const uint32_t base = sb + (c & 1) * BUF_BYTES;
        #pragma unroll
        for (int ks = 0; ks < 2; ks++) {
            uint32_t ah[2][4], al[2][4];
            #pragma unroll
            for (int mt = 0; mt < 2; mt++) {
                uint32_t addr = base + (uint32_t)(warp_m * 32 + mt * 16 + arow_l) * ROWB
                              + (ks * 16 + akc_l) * 2;
                ldmatrix_x4(ah[mt][0], ah[mt][1], ah[mt][2], ah[mt][3], addr);
                ldmatrix_x4(al[mt][0], al[mt][1], al[mt][2], al[mt][3], addr + ARR_BYTES);
            }
            #pragma unroll
            for (int jp = 0; jp < 4; jp++) {
                uint32_t baddr = base + 2 * ARR_BYTES
                               + (uint32_t)(warp_n * 64 + jp * 16 + brow_l) * ROWB
                               + (ks * 16 + bkc_l) * 2;
                uint32_t bh[4], bl[4];
                ldmatrix_x4(bh[0], bh[1], bh[2], bh[3], baddr);
                ldmatrix_x4(bl[0], bl[1], bl[2], bl[3], baddr + ARR_BYTES);
                #pragma unroll
                for (int sub = 0; sub < 2; sub++) {
                    const int j = jp * 2 + sub;
                    #pragma unroll
                    for (int mt = 0; mt < 2; mt++) {
                        mma16816(acc[mt][j], ah[mt], &bh[sub * 2]);
                        mma16816(acc[mt][j], ah[mt], &bl[sub * 2]);
                        mma16816(acc[mt][j], al[mt], &bh[sub * 2]);
                    }
                }
            }
        }
        __syncthreads();
    }

    #pragma unroll
    for (int mt = 0; mt < 2; mt++) {
        const int r0 = m0 + warp_m * 32 + mt * 16 + (lane >> 2);
        #pragma unroll
        for (int j = 0; j < 8; j++) {
            const int col = n0 + warp_n * 64 + j * 8 + (lane & 3) * 2;
            if (!split_out) {
                *(float2*)&C[(size_t)r0 * Nw + col]       = make_float2(acc[mt][j][0], acc[mt][j][1]);
                *(float2*)&C[(size_t)(r0 + 8) * Nw + col] = make_float2(acc[mt][j][2], acc[mt][j][3]);
            } else {
                uint32_t h0, l0, h1, l1;
                split2(acc[mt][j][0], acc[mt][j][1], h0, l0);
                split2(acc[mt][j][2], acc[mt][j][3], h1, l1);
                *(uint32_t*)&Ohi[(size_t)r0 * Nw + col]       = h0;
                *(uint32_t*)&Olo[(size_t)r0 * Nw + col]       = l0;
                *(uint32_t*)&Ohi[(size_t)(r0 + 8) * Nw + col] = h1;
                *(uint32_t*)&Olo[(size_t)(r0 + 8) * Nw + col] = l1;
            }
        }
    }
}

// ------------------------------ attention ----------------------------------
// Phase 1 (SIMT fp32): S = Q K^T scores -> phi = 1 + s + s^2/2 (s = 0.25 q.k),
// causal-masked, written to smem as bf16 hi/lo; denominator accumulated fp32.
// Phase 2 (HMMA): acc += (Ah+Al) @ (Vh+Vl) via 3-pass split mma.
// Output written directly as split bf16 (g_Yhi/g_Ylo).
#define APITCH 144   // 64 bf16 = 128B data + 16B pad; multiple of 16; 144%128 != 0

__global__ __launch_bounds__(256)
void attn_kernel()
{
    __shared__ float qs[64][FDIM + 1];
    __shared__ float ks[64][FDIM + 1];
    __shared__ __align__(16) char ah_s[64 * APITCH];
    __shared__ __align__(16) char al_s[64 * APITCH];
    __shared__ __align__(16) char vh_s[64 * APITCH];
    __shared__ __align__(16) char vl_s[64 * APITCH];
    __shared__ float zrow[64];

    const int qt  = blockIdx.x;
    const int h   = blockIdx.y;
    const int b   = blockIdx.z;
    const int tid = threadIdx.x;
    const int lane = tid & 31, wid = tid >> 5;
    const int tx  = tid & 15, ty = tid >> 4;
    const int row0 = ty * 4, col0 = tx * 4;
    const int wm = wid & 3, wn = wid >> 2;

    const uint32_t ah_b = smem_u32(ah_s), al_b = smem_u32(al_s);
    const uint32_t vh_b = smem_u32(vh_s), vl_b = smem_u32(vl_s);

    // load q tile (64 x 16) fp32
    {
        int r = tid >> 2, c = (tid & 3) << 2;
        float4 q4 = *(const float4*)&g_Q[((size_t)(b * L_SEQ + qt * 64 + r)) * NQK + h * FDIM + c];
        qs[r][c] = q4.x; qs[r][c + 1] = q4.y; qs[r][c + 2] = q4.z; qs[r][c + 3] = q4.w;
    }

    float acc[4][4];
    #pragma unroll
    for (int j = 0; j < 4; j++)
        #pragma unroll
        for (int q = 0; q < 4; q++) acc[j][q] = 0.f;
    float dden[4] = {0.f, 0.f, 0.f, 0.f};

    for (int kt = 0; kt <= qt; kt++) {
        __syncthreads();   // prior phase-2 reads of vh/vl/ah/al done; ks reusable

        // prefetch V hi/lo tile (64 x 64 bf16 each) via cp.async
        #pragma unroll
        for (int i = 0; i < 4; i++) {
            int idx = tid + i * 256;         // 0..1023
            int arr = idx >> 9;              // 0 = hi, 1 = lo
            int rem = idx & 511;
            int row = rem >> 3, seg = rem & 7;
            uint32_t sdst = (arr ? vl_b : vh_b) + (uint32_t)row * APITCH + seg * 16;
            const __nv_bfloat16* src = (arr ? g_Vlo : g_Vhi)
                + ((size_t)(b * L_SEQ + kt * 64 + row)) * DMODEL + h * VDIM + seg * 8;
            cp_async16(sdst, src);
        }
        CP_COMMIT();

        // load k tile (64 x 16) fp32
        {
            int r = tid >> 2, c = (tid & 3) << 2;
            float4 k4 = *(const float4*)&g_K[((size_t)(b * L_SEQ + kt * 64 + r)) * NQK + h * FDIM + c];
            ks[r][c] = k4.x; ks[r][c + 1] = k4.y; ks[r][c + 2] = k4.z; ks[r][c + 3] = k4.w;
        }
        __syncthreads();

        // phase 1: phi -> bf16 hi/lo smem + fp32 denominator
        const bool diag = (kt == qt);
        #pragma unroll
        for (int i = 0; i < 4; i++) {
            const int r = row0 + i;
            #pragma unroll
            for (int j = 0; j < 4; j++) {
                const int cl = col0 + j;
                float s = 0.f;
                #pragma unroll
                for (int f = 0; f < FDIM; f++) s += qs[r][f] * ks[cl][f];
                s *= 0.25f;
                float phi = 1.f + s + 0.5f * s * s;
                if (diag && cl > r) phi = 0.f;
                __nv_bfloat16 hb = __float2bfloat16(phi);
                float rres = phi - __bfloat162float(hb);
                *(__nv_bfloat16*)(ah_s + r * APITCH + cl * 2) = hb;
                *(__nv_bfloat16*)(al_s + r * APITCH + cl * 2) = __float2bfloat16(rres);
                dden[i] += phi;
            }
        }
        CP_WAIT0();
        __syncthreads();

        // phase 2: acc += A(64x64) @ V(64x64), 3-pass split HMMA
        #pragma unroll
        for (int ksi = 0; ksi < 4; ksi++) {
            uint32_t a_off = (uint32_t)(wm * 16 + (lane & 15)) * APITCH
                           + (ksi * 16 + ((lane >> 4) << 3)) * 2;
            uint32_t ah4[4], al4[4];
            ldmatrix_x4(ah4[0], ah4[1], ah4[2], ah4[3], ah_b + a_off);
            ldmatrix_x4(al4[0], al4[1], al4[2], al4[3], al_b + a_off);
            #pragma unroll
            for (int jp = 0; jp < 2; jp++) {
                uint32_t b_off = (uint32_t)(ksi * 16 + (lane & 15)) * APITCH
                               + (wn * 32 + jp * 16 + ((lane >> 4) << 3)) * 2;
                uint32_t bh4[4], bl4[4];
                ldmatrix_x4_t(bh4[0], bh4[1], bh4[2], bh4[3], vh_b + b_off);
                ldmatrix_x4_t(bl4[0], bl4[1], bl4[2], bl4[3], vl_b + b_off);
                #pragma unroll
                for (int sub = 0; sub < 2; sub++) {
                    const int j = jp * 2 + sub;
                    mma16816(acc[j], ah4, &bh4[sub * 2]);
                    mma16816(acc[j], ah4, &bl4[sub * 2]);
                    mma16816(acc[j], al4, &bh4[sub * 2]);
                }
            }
        }
    }

    // denominator reduction (reuse ks as scratch)
    __syncthreads();
    #pragma unroll
    for (int i = 0; i < 4; i++) ks[row0 + i][tx] = dden[i];
    __syncthreads();
    if (tid < 64) {
        float s = 0.f;
        #pragma unroll
        for (int t = 0; t < 16; t++) s += ks[tid][t];
        zrow[tid] = 1.f / (s + 1e-12f);
    }
    __syncthreads();

    // epilogue: scale by 1/z, split to bf16 hi/lo, write g_Yhi/g_Ylo
    {
        const int r_in = lane >> 2;
        const int lr0 = wm * 16 + r_in;
        const float z0 = zrow[lr0], z1 = zrow[lr0 + 8];
        const size_t grow0 = (size_t)(b * L_SEQ + qt * 64 + lr0);
        #pragma unroll
        for (int j = 0; j < 4; j++) {
            const int col = h * VDIM + wn * 32 + j * 8 + (lane & 3) * 2;
            uint32_t h0, l0, h1, l1;
            split2(acc[j][0] * z0, acc[j][1] * z0, h0, l0);
            split2(acc[j][2] * z1, acc[j][3] * z1, h1, l1);
            *(uint32_t*)&g_Yhi[grow0 * DMODEL + col]       = h0;
            *(uint32_t*)&g_Ylo[grow0 * DMODEL + col]       = l0;
            *(uint32_t*)&g_Yhi[(grow0 + 8) * DMODEL + col] = h1;
            *(uint32_t*)&g_Ylo[(grow0 + 8) * DMODEL + col] = l1;
        }
    }
}

// ---------------------------------------------------------------------------
extern "C" void kernel_launch(void* const* d_in, const int* in_sizes, int n_in,
                              void* d_out, int out_size)
{
    const float* X  = (const float*)d_in[0];
    const float* Wq = (const float*)d_in[1];
    const float* Wk = (const float*)d_in[2];
    const float* Wv = (const float*)d_in[3];
    const float* Wo = (const float*)d_in[4];
    float* out = (float*)d_out;

    float *Q, *K;
    __nv_bfloat16 *Xhi, *Xlo, *Vhi, *Vlo, *Yhi, *Ylo;
    __nv_bfloat16 *WqTh, *WqTl, *WkTh, *WkTl, *WvTh, *WvTl, *WoTh, *WoTl;
    cudaGetSymbolAddress((void**)&Q, g_Q);
    cudaGetSymbolAddress((void**)&K, g_K);
    cudaGetSymbolAddress((void**)&Xhi, g_Xhi);
    cudaGetSymbolAddress((void**)&Xlo, g_Xlo);
    cudaGetSymbolAddress((void**)&Vhi, g_Vhi);
    cudaGetSymbolAddress((void**)&Vlo, g_Vlo);
    cudaGetSymbolAddress((void**)&Yhi, g_Yhi);
    cudaGetSymbolAddress((void**)&Ylo, g_Ylo);
    cudaGetSymbolAddress((void**)&WqTh, g_WqT_hi);
    cudaGetSymbolAddress((void**)&WqTl, g_WqT_lo);
    cudaGetSymbolAddress((void**)&WkTh, g_WkT_hi);
    cudaGetSymbolAddress((void**)&WkTl, g_WkT_lo);
    cudaGetSymbolAddress((void**)&WvTh, g_WvT_hi);
    cudaGetSymbolAddress((void**)&WvTl, g_WvT_lo);
    cudaGetSymbolAddress((void**)&WoTh, g_WoT_hi);
    cudaGetSymbolAddress((void**)&WoTl, g_WoT_lo);

    cudaFuncSetAttribute(gemm_mma, cudaFuncAttributeMaxDynamicSharedMemorySize, GEMM_SMEM);

    const int n4 = MTOT * DMODEL / 4;
    split_bf16<<<(n4 + 255) / 256, 256>>>((const float4*)X, (uint2*)Xhi, (uint2*)Xlo, n4);
    transpose_split<<<dim3(NQK / 32,    DMODEL / 32), dim3(32, 32)>>>(Wq, WqTh, WqTl, DMODEL, NQK);
    transpose_split<<<dim3(NQK / 32,    DMODEL / 32), dim3(32, 32)>>>(Wk, WkTh, WkTl, DMODEL, NQK);
    transpose_split<<<dim3(DMODEL / 32, DMODEL / 32), dim3(32, 32)>>>(Wv, WvTh, WvTl, DMODEL, DMODEL);
    transpose_split<<<dim3(DMODEL / 32, DMODEL / 32), dim3(32, 32)>>>(Wo, WoTh, WoTl, DMODEL, DMODEL);

    // Q & K projections (z-fused), fp32 out
    gemm_mma<<<dim3(NQK / 128, MTOT / 128, 2), 256, GEMM_SMEM>>>(
        Xhi, Xlo, WqTh, WqTl, WkTh, WkTl, Q, K, nullptr, nullptr, 0, NQK, DMODEL);
    // V projection, split bf16 out
    gemm_mma<<<dim3(DMODEL / 128, MTOT / 128, 1), 256, GEMM_SMEM>>>(
        Xhi, Xlo, WvTh, WvTl, WvTh, WvTl, nullptr, nullptr, Vhi, Vlo, 1, DMODEL, DMODEL);
    // causal taylor-exp attention (HMMA phase 2), split bf16 out
    attn_kernel<<<dim3(L_SEQ / 64, NH, B_SZ), 256>>>();
    // output projection, fp32 out -> d_out
    gemm_mma<<<dim3(DMODEL / 128, MTOT / 128, 1), 256, GEMM_SMEM>>>(
        Yhi, Ylo, WoTh, WoTl, WoTh, WoTl, out, out, nullptr, nullptr, 0, DMODEL, DMODEL);
}

// round 7
// speedup vs baseline: 2.1639x; 1.1463x over previous
#include <cuda_runtime.h>
#include <cuda_bf16.h>
#include <cstdint>

#define B_SZ   2
#define L_SEQ  2048
#define NH     16
#define FDIM   16
#define VDIM   64
#define DMODEL 1024
#define MTOT   (B_SZ * L_SEQ)   // 4096
#define NQK    (NH * FDIM)      // 256

// ------------------------------ scratch (device globals) -------------------
__device__ __nv_bfloat16 g_Qhi[(size_t)MTOT * NQK];
__device__ __nv_bfloat16 g_Qlo[(size_t)MTOT * NQK];
__device__ __nv_bfloat16 g_Khi[(size_t)MTOT * NQK];
__device__ __nv_bfloat16 g_Klo[(size_t)MTOT * NQK];

__device__ __nv_bfloat16 g_Xhi[(size_t)MTOT * DMODEL];
__device__ __nv_bfloat16 g_Xlo[(size_t)MTOT * DMODEL];
__device__ __nv_bfloat16 g_Vhi[(size_t)MTOT * DMODEL];
__device__ __nv_bfloat16 g_Vlo[(size_t)MTOT * DMODEL];
__device__ __nv_bfloat16 g_Yhi[(size_t)MTOT * DMODEL];
__device__ __nv_bfloat16 g_Ylo[(size_t)MTOT * DMODEL];

__device__ __nv_bfloat16 g_WqT_hi[(size_t)NQK * DMODEL];
__device__ __nv_bfloat16 g_WqT_lo[(size_t)NQK * DMODEL];
__device__ __nv_bfloat16 g_WkT_hi[(size_t)NQK * DMODEL];
__device__ __nv_bfloat16 g_WkT_lo[(size_t)NQK * DMODEL];
__device__ __nv_bfloat16 g_WvT_hi[(size_t)DMODEL * DMODEL];
__device__ __nv_bfloat16 g_WvT_lo[(size_t)DMODEL * DMODEL];
__device__ __nv_bfloat16 g_WoT_hi[(size_t)DMODEL * DMODEL];
__device__ __nv_bfloat16 g_WoT_lo[(size_t)DMODEL * DMODEL];

// ------------------------------ helpers ------------------------------------
__device__ __forceinline__ uint32_t smem_u32(const void* p) {
    uint32_t a;
    asm("{ .reg .u64 t; cvta.to.shared.u64 t, %1; cvt.u32.u64 %0, t; }" : "=r"(a) : "l"(p));
    return a;
}
__device__ __forceinline__ void cp_async16(uint32_t s, const void* g) {
    asm volatile("cp.async.cg.shared.global [%0], [%1], 16;" :: "r"(s), "l"(g));
}
#define CP_COMMIT() asm volatile("cp.async.commit_group;" ::: "memory")
#define CP_WAIT1()  asm volatile("cp.async.wait_group 1;" ::: "memory")
#define CP_WAIT0()  asm volatile("cp.async.wait_group 0;" ::: "memory")

__device__ __forceinline__ void ldmatrix_x4(uint32_t& r0, uint32_t& r1, uint32_t& r2, uint32_t& r3,
                                            uint32_t addr) {
    asm volatile("ldmatrix.sync.aligned.m8n8.x4.shared.b16 {%0,%1,%2,%3}, [%4];"
                 : "=r"(r0), "=r"(r1), "=r"(r2), "=r"(r3) : "r"(addr));
}
__device__ __forceinline__ void ldmatrix_x4_t(uint32_t& r0, uint32_t& r1, uint32_t& r2, uint32_t& r3,
                                              uint32_t addr) {
    asm volatile("ldmatrix.sync.aligned.m8n8.x4.trans.shared.b16 {%0,%1,%2,%3}, [%4];"
                 : "=r"(r0), "=r"(r1), "=r"(r2), "=r"(r3) : "r"(addr));
}
__device__ __forceinline__ void mma16816(float* d, const uint32_t* a, const uint32_t* b) {
    asm volatile(
        "mma.sync.aligned.m16n8k16.row.col.f32.bf16.bf16.f32 "
        "{%0,%1,%2,%3},{%4,%5,%6,%7},{%8,%9},{%0,%1,%2,%3};"
        : "+f"(d[0]), "+f"(d[1]), "+f"(d[2]), "+f"(d[3])
        : "r"(a[0]), "r"(a[1]), "r"(a[2]), "r"(a[3]), "r"(b[0]), "r"(b[1]));
}
__device__ __forceinline__ void split2(float y0, float y1, uint32_t& hi, uint32_t& lo) {
    __nv_bfloat16 h0 = __float2bfloat16(y0);
    __nv_bfloat16 h1 = __float2bfloat16(y1);
    float r0 = y0 - __bfloat162float(h0);
    float r1 = y1 - __bfloat162float(h1);
    hi = (uint32_t)__bfloat16_as_ushort(h0) | ((uint32_t)__bfloat16_as_ushort(h1) << 16);
    lo = (uint32_t)__bfloat16_as_ushort(__float2bfloat16(r0))
       | ((uint32_t)__bfloat16_as_ushort(__float2bfloat16(r1)) << 16);
}

// ------------------------------ prep kernels -------------------------------
__global__ void split_bf16(const float4* __restrict__ x,
                           uint2* __restrict__ hi, uint2* __restrict__ lo, int n4)
{
    int i = blockIdx.x * blockDim.x + threadIdx.x;
    if (i >= n4) return;
    float4 v = x[i];
    float f[4] = {v.x, v.y, v.z, v.w};
    unsigned short h[4], l[4];
    #pragma unroll
    for (int c = 0; c < 4; c++) {
        __nv_bfloat16 hb = __float2bfloat16(f[c]);
        float r = f[c] - __bfloat162float(hb);
        h[c] = __bfloat16_as_ushort(hb);
        l[c] = __bfloat16_as_ushort(__float2bfloat16(r));
    }
    hi[i] = make_uint2((uint32_t)h[0] | ((uint32_t)h[1] << 16),
                       (uint32_t)h[2] | ((uint32_t)h[3] << 16));
    lo[i] = make_uint2((uint32_t)l[0] | ((uint32_t)l[1] << 16),
                       (uint32_t)l[2] | ((uint32_t)l[3] << 16));
}

// W: (K x N) row-major -> T: (N x K) bf16 hi/lo
__global__ void transpose_split(const float* __restrict__ W,
                                __nv_bfloat16* __restrict__ Thi,
                                __nv_bfloat16* __restrict__ Tlo, int K, int N)
{
    __shared__ float t[32][33];
    int n0 = blockIdx.x * 32, k0 = blockIdx.y * 32;
    t[threadIdx.y][threadIdx.x] = W[(size_t)(k0 + threadIdx.y) * N + n0 + threadIdx.x];
    __syncthreads();
    float v = t[threadIdx.x][threadIdx.y];
    int n = n0 + threadIdx.y, k = k0 + threadIdx.x;
    __nv_bfloat16 hb = __float2bfloat16(v);
    float r = v - __bfloat162float(hb);
    Thi[(size_t)n * K + k] = hb;
    Tlo[(size_t)n * K + k] = __float2bfloat16(r);
}

// ------------------------------ HMMA GEMM ----------------------------------
#define KC        32
#define ROWB      80
#define ARR_BYTES (128 * ROWB)
#define BUF_BYTES (4 * ARR_BYTES)
#define GEMM_SMEM (2 * BUF_BYTES)

__global__ __launch_bounds__(256, 2)
void gemm_mma(const __nv_bfloat16* __restrict__ Ahi, const __nv_bfloat16* __restrict__ Alo,
              const __nv_bfloat16* __restrict__ Bhi0, const __nv_bfloat16* __restrict__ Blo0,
              const __nv_bfloat16* __restrict__ Bhi1, const __nv_bfloat16* __restrict__ Blo1,
              float* __restrict__ C0, float* __restrict__ C1,
              __nv_bfloat16* __restrict__ Ohi0, __nv_bfloat16* __restrict__ Olo0,
              __nv_bfloat16* __restrict__ Ohi1, __nv_bfloat16* __restrict__ Olo1,
              int split_out, int Nw, int K)
{
    const __nv_bfloat16* Bhi = blockIdx.z ? Bhi1 : Bhi0;
    const __nv_bfloat16* Blo = blockIdx.z ? Blo1 : Blo0;
    float* C = blockIdx.z ? C1 : C0;
    __nv_bfloat16* Ohi = blockIdx.z ? Ohi1 : Ohi0;
    __nv_bfloat16* Olo = blockIdx.z ? Olo1 : Olo0;

    extern __shared__ char smem[];
    const uint32_t sb = smem_u32(smem);

    const int tid = threadIdx.x, lane = tid & 31, wid = tid >> 5;
    const int warp_m = wid & 3, warp_n = wid >> 2;
    const int m0 = blockIdx.y * 128, n0 = blockIdx.x * 128;
    const int nchunk = K / KC;

    const int frow0 = tid >> 2, fcol = tid & 3;

    auto issue_chunk = [&](int c) {
        const uint32_t base = sb + (c & 1) * BUF_BYTES;
        const int k0 = c * KC;
        #pragma unroll
        for (int i = 0; i < 2; i++) {
            const int row = frow0 + i * 64;
            const uint32_t soff = (uint32_t)row * ROWB + fcol * 16;
            const size_t ga = (size_t)(m0 + row) * K + k0 + fcol * 8;
            const size_t gb = (size_t)(n0 + row) * K + k0 + fcol * 8;
            cp_async16(base + soff,                 Ahi + ga);
            cp_async16(base + ARR_BYTES + soff,     Alo + ga);
            cp_async16(base + 2 * ARR_BYTES + soff, Bhi + gb);
            cp_async16(base + 3 * ARR_BYTES + soff, Blo + gb);
        }
    };

    float acc[2][8][4];
    #pragma unroll
    for (int mt = 0; mt < 2; mt++)
        #pragma unroll
        for (int j = 0; j < 8; j++)
            #pragma unroll
            for (int q = 0; q < 4; q++) acc[mt][j][q] = 0.f;

    issue_chunk(0);
    CP_COMMIT();

    const int arow_l = (lane & 15);
    const int akc_l  = (lane >> 4) << 3;
    const int brow_l = (lane & 7) + ((lane & 16) ? 8 : 0);
    const int bkc_l  = (lane & 8) ? 8 : 0;

    for (int c = 0; c < nchunk; c++) {
        if (c + 1 < nchunk) issue_chunk(c + 1);
        CP_COMMIT();
        CP_WAIT1();
        __syncthreads();

        const uint32_t base = sb + (c & 1) * BUF_BYTES;
        #pragma unroll
        for (int ks = 0; ks < 2; ks++) {
            uint32_t ah[2][4], al[2][4];
            #pragma unroll
            for (int mt = 0; mt < 2; mt++) {
                uint32_t addr = base + (uint32_t)(warp_m * 32 + mt * 16 + arow_l) * ROWB
                              + (ks * 16 + akc_l) * 2;
                ldmatrix_x4(ah[mt][0], ah[mt][1], ah[mt][2], ah[mt][3], addr);
                ldmatrix_x4(al[mt][0], al[mt][1], al[mt][2], al[mt][3], addr + ARR_BYTES);
            }
            #pragma unroll
            for (int jp = 0; jp < 4; jp++) {
                uint32_t baddr = base + 2 * ARR_BYTES
                               + (uint32_t)(warp_n * 64 + jp * 16 + brow_l) * ROWB
                               + (ks * 16 + bkc_l) * 2;
                uint32_t bh[4], bl[4];
                ldmatrix_x4(bh[0], bh[1], bh[2], bh[3], baddr);
                ldmatrix_x4(bl[0], bl[1], bl[2], bl[3], baddr + ARR_BYTES);
                #pragma unroll
                for (int sub = 0; sub < 2; sub++) {
                    const int j = jp * 2 + sub;
                    #pragma unroll
                    for (int mt = 0; mt < 2; mt++) {
                        mma16816(acc[mt][j], ah[mt], &bh[sub * 2]);
                        mma16816(acc[mt][j], ah[mt], &bl[sub * 2]);
                        mma16816(acc[mt][j], al[mt], &bh[sub * 2]);
                    }
                }
            }
        }
        __syncthreads();
    }

    #pragma unroll
    for (int mt = 0; mt < 2; mt++) {
        const int r0 = m0 + warp_m * 32 + mt * 16 + (lane >> 2);
        #pragma unroll
        for (int j = 0; j < 8; j++) {
            const int col = n0 + warp_n * 64 + j * 8 + (lane & 3) * 2;
            if (!split_out) {
                *(float2*)&C[(size_t)r0 * Nw + col]       = make_float2(acc[mt][j][0], acc[mt][j][1]);
                *(float2*)&C[(size_t)(r0 + 8) * Nw + col] = make_float2(acc[mt][j][2], acc[mt][j][3]);
            } else {
                uint32_t h0, l0, h1, l1;
                split2(acc[mt][j][0], acc[mt][j][1], h0, l0);
                split2(acc[mt][j][2], acc[mt][j][3], h1, l1);
                *(uint32_t*)&Ohi[(size_t)r0 * Nw + col]       = h0;
                *(uint32_t*)&Olo[(size_t)r0 * Nw + col]       = l0;
                *(uint32_t*)&Ohi[(size_t)(r0 + 8) * Nw + col] = h1;
                *(uint32_t*)&Olo[(size_t)(r0 + 8) * Nw + col] = l1;
            }
        }
    }
}

// ------------------------------ attention ----------------------------------
// Phase 1 (HMMA): S = Q K^T via 3-pass split mma; Q fragments persistent.
// phi computed on fp32 C-fragments in registers; C-frag layout of two adjacent
// n8 tiles equals the m16k16 A-frag layout, so phi packs in-register into
// phase-2 A operands. Phase 1 is DUPLICATED across wn pairs; only wn==0
// contributes to the denominator (R6 bug: both halves were summed -> 2x den).
#define QK_PITCH 48
#define V_PITCH  144
#define SM_QH    0
#define SM_QL    3072
#define SM_KBUF(b) (6144 + (b) * 6144)      // KH +0, KL +3072
#define SM_VBUF(b) (18432 + (b) * 18432)    // VH +0, VL +9216
#define SM_DDEN  55296                       // [64][4] floats
#define SM_ZROW  57344
#define ATTN_SMEM 57600

__global__ __launch_bounds__(256)
void attn_kernel()
{
    extern __shared__ char sm[];
    const uint32_t sb = smem_u32(sm);
    float* dden_s = (float*)(sm + SM_DDEN);   // [64][4]
    float* zrow   = (float*)(sm + SM_ZROW);   // [64]

    const int qt = blockIdx.x, h = blockIdx.y, b = blockIdx.z;
    const int tid = threadIdx.x, lane = tid & 31, wid = tid >> 5;
    const int wm = wid & 3, wn = wid >> 2;
    const int g = lane >> 2, tg = lane & 3;

    const size_t tok0 = (size_t)(b * L_SEQ + qt * 64);

    auto issue_q = [&]() {
        int arr = tid >> 7, rem = tid & 127, row = rem >> 1, seg = rem & 1;
        uint32_t dst = sb + (arr ? SM_QL : SM_QH) + (uint32_t)row * QK_PITCH + seg * 16;
        const __nv_bfloat16* src = (arr ? g_Qlo : g_Qhi) + (tok0 + row) * NQK + h * FDIM + seg * 8;
        cp_async16(dst, src);
    };
    auto issue_kv = [&](int kt, int buf) {
        const size_t ktok = (size_t)(b * L_SEQ + kt * 64);
        {   // K: 256 x 16B, 1 per thread
            int arr = tid >> 7, rem = tid & 127, row = rem >> 1, seg = rem & 1;
            uint32_t dst = sb + SM_KBUF(buf) + arr * 3072 + (uint32_t)row * QK_PITCH + seg * 16;
            const __nv_bfloat16* src = (arr ? g_Klo : g_Khi) + (ktok + row) * NQK + h * FDIM + seg * 8;
            cp_async16(dst, src);
        }
        #pragma unroll
        for (int i = 0; i < 4; i++) {   // V: 1024 x 16B, 4 per thread
            int idx = tid + i * 256, arr = idx >> 9, rem = idx & 511, row = rem >> 3, seg = rem & 7;
            uint32_t dst = sb + SM_VBUF(buf) + arr * 9216 + (uint32_t)row * V_PITCH + seg * 16;
            const __nv_bfloat16* src = (arr ? g_Vlo : g_Vhi) + (ktok + row) * DMODEL + h * VDIM + seg * 8;
            cp_async16(dst, src);
        }
    };

    issue_q();
    issue_kv(0, 0);
    CP_COMMIT();
    CP_WAIT0();
    __syncthreads();

    // persistent Q fragments
    uint32_t qh4[4], ql4[4];
    {
        uint32_t off = (uint32_t)(wm * 16 + (lane & 15)) * QK_PITCH + ((lane >> 4) << 3) * 2;
        ldmatrix_x4(qh4[0], qh4[1], qh4[2], qh4[3], sb + SM_QH + off);
        ldmatrix_x4(ql4[0], ql4[1], ql4[2], ql4[3], sb + SM_QL + off);
    }

    if (qt > 0) { issue_kv(1, 1); CP_COMMIT(); }

    float acc[4][4];
    #pragma unroll
    for (int j = 0; j < 4; j++)
        #pragma unroll
        for (int q = 0; q < 4; q++) acc[j][q] = 0.f;
    float dden0 = 0.f, dden1 = 0.f;

    const int r0_ = wm * 16 + g;   // within-tile S rows r0_ and r0_+8

    for (int kt = 0; kt <= qt; kt++) {
        const int buf = kt & 1;
        if (kt > 0) {
            CP_WAIT0();
            __syncthreads();                       // buf ready; all warps done with buf^1
            if (kt < qt) { issue_kv(kt + 1, buf ^ 1); CP_COMMIT(); }
        }

        // ---- phase 1: S = Q K^T (16 rows x 64 cols per warp)
        float s_acc[8][4];
        #pragma unroll
        for (int j = 0; j < 8; j++)
            #pragma unroll
            for (int e = 0; e < 4; e++) s_acc[j][e] = 0.f;

        const uint32_t kh_b = sb + SM_KBUF(buf), kl_b = kh_b + 3072;
        #pragma unroll
        for (int jp2 = 0; jp2 < 4; jp2++) {
            uint32_t koff = (uint32_t)(jp2 * 16 + (lane & 7) + ((lane & 16) ? 8 : 0)) * QK_PITCH
                          + ((lane & 8) ? 16 : 0);
            uint32_t bh4[4], bl4[4];
            ldmatrix_x4(bh4[0], bh4[1], bh4[2], bh4[3], kh_b + koff);
            ldmatrix_x4(bl4[0], bl4[1], bl4[2], bl4[3], kl_b + koff);
            #pragma unroll
            for (int sub = 0; sub < 2; sub++) {
                const int j = jp2 * 2 + sub;
                mma16816(s_acc[j], qh4, &bh4[sub * 2]);
                mma16816(s_acc[j], qh4, &bl4[sub * 2]);
                mma16816(s_acc[j], ql4, &bh4[sub * 2]);
            }
        }

        // ---- phi + causal mask + denominator + in-register pack to A frags
        uint32_t pah[16], pal[16];
        const bool diag = (kt == qt);
        #pragma unroll
        for (int j = 0; j < 8; j++) {
            float ph[4];
            #pragma unroll
            for (int e = 0; e < 4; e++) {
                float s = s_acc[j][e] * 0.25f;
                float phi = fmaf(s, fmaf(0.5f, s, 1.f), 1.f);
                if (diag) {
                    int col = j * 8 + tg * 2 + (e & 1);
                    int row = r0_ + ((e >= 2) ? 8 : 0);
                    if (col > row) phi = 0.f;
                }
                ph[e] = phi;
            }
            dden0 += ph[0] + ph[1];
            dden1 += ph[2] + ph[3];
            split2(ph[0], ph[1], pah[j * 2 + 0], pal[j * 2 + 0]);
            split2(ph[2], ph[3], pah[j * 2 + 1], pal[j * 2 + 1]);
        }

        // ---- phase 2: acc += A(16x64) @ V(64x32)
        const uint32_t vh_b = sb + SM_VBUF(buf), vl_b = vh_b + 9216;
        #pragma unroll
        for (int ksi = 0; ksi < 4; ksi++) {
            const uint32_t* ah = &pah[ksi * 4];
            const uint32_t* al = &pal[ksi * 4];
            #pragma unroll
            for (int jp = 0; jp < 2; jp++) {
                uint32_t voff = (uint32_t)(ksi * 16 + (lane & 15)) * V_PITCH
                              + (wn * 32 + jp * 16 + ((lane >> 4) << 3)) * 2;
                uint32_t vh4[4], vl4[4];
                ldmatrix_x4_t(vh4[0], vh4[1], vh4[2], vh4[3], vh_b + voff);
                ldmatrix_x4_t(vl4[0], vl4[1], vl4[2], vl4[3], vl_b + voff);
                #pragma unroll
                for (int sub = 0; sub < 2; sub++) {
                    const int j2 = jp * 2 + sub;
                    mma16816(acc[j2], ah, &vh4[sub * 2]);
                    mma16816(acc[j2], ah, &vl4[sub * 2]);
                    mma16816(acc[j2], al, &vh4[sub * 2]);
                }
            }
        }
    }

    // ---- denominator reduction: ONLY wn==0 (phase 1 duplicated across wn)
    __syncthreads();
    if (wn == 0) {
        dden_s[(wm * 16 + g) * 4 + tg]     = dden0;
        dden_s[(wm * 16 + g + 8) * 4 + tg] = dden1;
    }
    __syncthreads();
    if (tid < 64) {
        float s = dden_s[tid * 4 + 0] + dden_s[tid * 4 + 1]
                + dden_s[tid * 4 + 2] + dden_s[tid * 4 + 3];
        zrow[tid] = 1.f / (s + 1e-12f);
    }
    __syncthreads();

    // ---- epilogue: scale, split, write Y
    {
        const int lr0 = wm * 16 + g;
        const float z0 = zrow[lr0], z1 = zrow[lr0 + 8];
        const size_t grow0 = tok0 + lr0;
        #pragma unroll
        for (int j = 0; j < 4; j++) {
            const int col = h * VDIM + wn * 32 + j * 8 + tg * 2;
            uint32_t h0, l0, h1, l1;
            split2(acc[j][0] * z0, acc[j][1] * z0, h0, l0);
            split2(acc[j][2] * z1, acc[j][3] * z1, h1, l1);
            *(uint32_t*)&g_Yhi[grow0 * DMODEL + col]       = h0;
            *(uint32_t*)&g_Ylo[grow0 * DMODEL + col]       = l0;
            *(uint32_t*)&g_Yhi[(grow0 + 8) * DMODEL + col] = h1;
            *(uint32_t*)&g_Ylo[(grow0 + 8) * DMODEL + col] = l1;
        }
    }
}

// ---------------------------------------------------------------------------
extern "C" void kernel_launch(void* const* d_in, const int* in_sizes, int n_in,
                              void* d_out, int out_size)
{
    const float* X  = (const float*)d_in[0];
    const float* Wq = (const float*)d_in[1];
    const float* Wk = (const float*)d_in[2];
    const float* Wv = (const float*)d_in[3];
    const float* Wo = (const float*)d_in[4];
    float* out = (float*)d_out;

    __nv_bfloat16 *Qhi, *Qlo, *Khi, *Klo;
    __nv_bfloat16 *Xhi, *Xlo, *Vhi, *Vlo, *Yhi, *Ylo;
    __nv_bfloat16 *WqTh, *WqTl, *WkTh, *WkTl, *WvTh, *WvTl, *WoTh, *WoTl;
    cudaGetSymbolAddress((void**)&Qhi, g_Qhi);
    cudaGetSymbolAddress((void**)&Qlo, g_Qlo);
    cudaGetSymbolAddress((void**)&Khi, g_Khi);
    cudaGetSymbolAddress((void**)&Klo, g_Klo);
    cudaGetSymbolAddress((void**)&Xhi, g_Xhi);
    cudaGetSymbolAddress((void**)&Xlo, g_Xlo);
    cudaGetSymbolAddress((void**)&Vhi, g_Vhi);
    cudaGetSymbolAddress((void**)&Vlo, g_Vlo);
    cudaGetSymbolAddress((void**)&Yhi, g_Yhi);
    cudaGetSymbolAddress((void**)&Ylo, g_Ylo);
    cudaGetSymbolAddress((void**)&WqTh, g_WqT_hi);
    cudaGetSymbolAddress((void**)&WqTl, g_WqT_lo);
    cudaGetSymbolAddress((void**)&WkTh, g_WkT_hi);
    cudaGetSymbolAddress((void**)&WkTl, g_WkT_lo);
    cudaGetSymbolAddress((void**)&WvTh, g_WvT_hi);
    cudaGetSymbolAddress((void**)&WvTl, g_WvT_lo);
    cudaGetSymbolAddress((void**)&WoTh, g_WoT_hi);
    cudaGetSymbolAddress((void**)&WoTl, g_WoT_lo);

    cudaFuncSetAttribute(gemm_mma, cudaFuncAttributeMaxDynamicSharedMemorySize, GEMM_SMEM);
    cudaFuncSetAttribute(attn_kernel, cudaFuncAttributeMaxDynamicSharedMemorySize, ATTN_SMEM);

    const int n4 = MTOT * DMODEL / 4;
    split_bf16<<<(n4 + 255) / 256, 256>>>((const float4*)X, (uint2*)Xhi, (uint2*)Xlo, n4);
    transpose_split<<<dim3(NQK / 32,    DMODEL / 32), dim3(32, 32)>>>(Wq, WqTh, WqTl, DMODEL, NQK);
    transpose_split<<<dim3(NQK / 32,    DMODEL / 32), dim3(32, 32)>>>(Wk, WkTh, WkTl, DMODEL, NQK);
    transpose_split<<<dim3(DMODEL / 32, DMODEL / 32), dim3(32, 32)>>>(Wv, WvTh, WvTl, DMODEL, DMODEL);
    transpose_split<<<dim3(DMODEL / 32, DMODEL / 32), dim3(32, 32)>>>(Wo, WoTh, WoTl, DMODEL, DMODEL);

    // Q & K projections (z-fused), split bf16 out
    gemm_mma<<<dim3(NQK / 128, MTOT / 128, 2), 256, GEMM_SMEM>>>(
        Xhi, Xlo, WqTh, WqTl, WkTh, WkTl, nullptr, nullptr,
        Qhi, Qlo, Khi, Klo, 1, NQK, DMODEL);
    // V projection, split bf16 out
    gemm_mma<<<dim3(DMODEL / 128, MTOT / 128, 1), 256, GEMM_SMEM>>>(
        Xhi, Xlo, WvTh, WvTl, WvTh, WvTl, nullptr, nullptr,
        Vhi, Vlo, Vhi, Vlo, 1, DMODEL, DMODEL);
    // causal taylor-exp attention (full HMMA), split bf16 out
    attn_kernel<<<dim3(L_SEQ / 64, NH, B_SZ), 256, ATTN_SMEM>>>();
    // output projection, fp32 out -> d_out
    gemm_mma<<<dim3(DMODEL / 128, MTOT / 128, 1), 256, GEMM_SMEM>>>(
        Yhi, Ylo, WoTh, WoTl, WoTh, WoTl, out, out,
        nullptr, nullptr, nullptr, nullptr, 0, DMODEL, DMODEL);
}

// round 8
// speedup vs baseline: 2.3001x; 1.0629x over previous
#include <cuda_runtime.h>
#include <cuda_bf16.h>
#include <cstdint>

#define B_SZ   2
#define L_SEQ  2048
#define NH     16
#define FDIM   16
#define VDIM   64
#define DMODEL 1024
#define MTOT   (B_SZ * L_SEQ)   // 4096
#define NQK    (NH * FDIM)      // 256

// ------------------------------ scratch (device globals) -------------------
__device__ __nv_bfloat16 g_Qhi[(size_t)MTOT * NQK];
__device__ __nv_bfloat16 g_Qlo[(size_t)MTOT * NQK];
__device__ __nv_bfloat16 g_Khi[(size_t)MTOT * NQK];
__device__ __nv_bfloat16 g_Klo[(size_t)MTOT * NQK];

__device__ __nv_bfloat16 g_Xhi[(size_t)MTOT * DMODEL];
__device__ __nv_bfloat16 g_Xlo[(size_t)MTOT * DMODEL];
__device__ __nv_bfloat16 g_Vhi[(size_t)MTOT * DMODEL];
__device__ __nv_bfloat16 g_Vlo[(size_t)MTOT * DMODEL];
__device__ __nv_bfloat16 g_Yhi[(size_t)MTOT * DMODEL];
__device__ __nv_bfloat16 g_Ylo[(size_t)MTOT * DMODEL];

__device__ __nv_bfloat16 g_WqT_hi[(size_t)NQK * DMODEL];
__device__ __nv_bfloat16 g_WqT_lo[(size_t)NQK * DMODEL];
__device__ __nv_bfloat16 g_WkT_hi[(size_t)NQK * DMODEL];
__device__ __nv_bfloat16 g_WkT_lo[(size_t)NQK * DMODEL];
__device__ __nv_bfloat16 g_WvT_hi[(size_t)DMODEL * DMODEL];
__device__ __nv_bfloat16 g_WvT_lo[(size_t)DMODEL * DMODEL];
__device__ __nv_bfloat16 g_WoT_hi[(size_t)DMODEL * DMODEL];
__device__ __nv_bfloat16 g_WoT_lo[(size_t)DMODEL * DMODEL];

// ------------------------------ helpers ------------------------------------
__device__ __forceinline__ uint32_t smem_u32(const void* p) {
    uint32_t a;
    asm("{ .reg .u64 t; cvta.to.shared.u64 t, %1; cvt.u32.u64 %0, t; }" : "=r"(a) : "l"(p));
    return a;
}
__device__ __forceinline__ void cp_async16(uint32_t s, const void* g) {
    asm volatile("cp.async.cg.shared.global [%0], [%1], 16;" :: "r"(s), "l"(g));
}
#define CP_COMMIT() asm volatile("cp.async.commit_group;" ::: "memory")
#define CP_WAIT1()  asm volatile("cp.async.wait_group 1;" ::: "memory")
#define CP_WAIT0()  asm volatile("cp.async.wait_group 0;" ::: "memory")

__device__ __forceinline__ void ldmatrix_x4(uint32_t& r0, uint32_t& r1, uint32_t& r2, uint32_t& r3,
                                            uint32_t addr) {
    asm volatile("ldmatrix.sync.aligned.m8n8.x4.shared.b16 {%0,%1,%2,%3}, [%4];"
                 : "=r"(r0), "=r"(r1), "=r"(r2), "=r"(r3) : "r"(addr));
}
__device__ __forceinline__ void ldmatrix_x4_t(uint32_t& r0, uint32_t& r1, uint32_t& r2, uint32_t& r3,
                                              uint32_t addr) {
    asm volatile("ldmatrix.sync.aligned.m8n8.x4.trans.shared.b16 {%0,%1,%2,%3}, [%4];"
                 : "=r"(r0), "=r"(r1), "=r"(r2), "=r"(r3) : "r"(addr));
}
__device__ __forceinline__ void mma16816(float* d, const uint32_t* a, const uint32_t* b) {
    asm volatile(
        "mma.sync.aligned.m16n8k16.row.col.f32.bf16.bf16.f32 "
        "{%0,%1,%2,%3},{%4,%5,%6,%7},{%8,%9},{%0,%1,%2,%3};"
        : "+f"(d[0]), "+f"(d[1]), "+f"(d[2]), "+f"(d[3])
        : "r"(a[0]), "r"(a[1]), "r"(a[2]), "r"(a[3]), "r"(b[0]), "r"(b[1]));
}
__device__ __forceinline__ void split2(float y0, float y1, uint32_t& hi, uint32_t& lo) {
    __nv_bfloat16 h0 = __float2bfloat16(y0);
    __nv_bfloat16 h1 = __float2bfloat16(y1);
    float r0 = y0 - __bfloat162float(h0);
    float r1 = y1 - __bfloat162float(h1);
    hi = (uint32_t)__bfloat16_as_ushort(h0) | ((uint32_t)__bfloat16_as_ushort(h1) << 16);
    lo = (uint32_t)__bfloat16_as_ushort(__float2bfloat16(r0))
       | ((uint32_t)__bfloat16_as_ushort(__float2bfloat16(r1)) << 16);
}

// ------------------------------ prep kernels -------------------------------
__global__ void split_bf16(const float4* __restrict__ x,
                           uint2* __restrict__ hi, uint2* __restrict__ lo, int n4)
{
    int i = blockIdx.x * blockDim.x + threadIdx.x;
    if (i >= n4) return;
    float4 v = x[i];
    float f[4] = {v.x, v.y, v.z, v.w};
    unsigned short h[4], l[4];
    #pragma unroll
    for (int c = 0; c < 4; c++) {
        __nv_bfloat16 hb = __float2bfloat16(f[c]);
        float r = f[c] - __bfloat162float(hb);
        h[c] = __bfloat16_as_ushort(hb);
        l[c] = __bfloat16_as_ushort(__float2bfloat16(r));
    }
    hi[i] = make_uint2((uint32_t)h[0] | ((uint32_t)h[1] << 16),
                       (uint32_t)h[2] | ((uint32_t)h[3] << 16));
    lo[i] = make_uint2((uint32_t)l[0] | ((uint32_t)l[1] << 16),
                       (uint32_t)l[2] | ((uint32_t)l[3] << 16));
}

// All 4 weight transposes fused: W (K x N) row-major -> T (N x K) bf16 hi/lo.
__global__ void transpose_split_all(const float* __restrict__ Wq, const float* __restrict__ Wk,
                                    const float* __restrict__ Wv, const float* __restrict__ Wo)
{
    __shared__ float t[32][33];
    const int z = blockIdx.z;
    const float* W;
    __nv_bfloat16 *Th, *Tl;
    int N;
    if (z == 0)      { W = Wq; Th = g_WqT_hi; Tl = g_WqT_lo; N = NQK; }
    else if (z == 1) { W = Wk; Th = g_WkT_hi; Tl = g_WkT_lo; N = NQK; }
    else if (z == 2) { W = Wv; Th = g_WvT_hi; Tl = g_WvT_lo; N = DMODEL; }
    else             { W = Wo; Th = g_WoT_hi; Tl = g_WoT_lo; N = DMODEL; }
    const int n0 = blockIdx.x * 32;
    if (n0 >= N) return;
    const int k0 = blockIdx.y * 32;
    t[threadIdx.y][threadIdx.x] = W[(size_t)(k0 + threadIdx.y) * N + n0 + threadIdx.x];
    __syncthreads();
    float v = t[threadIdx.x][threadIdx.y];
    int n = n0 + threadIdx.y, k = k0 + threadIdx.x;
    __nv_bfloat16 hb = __float2bfloat16(v);
    float r = v - __bfloat162float(hb);
    Th[(size_t)n * DMODEL + k] = hb;
    Tl[(size_t)n * DMODEL + k] = __float2bfloat16(r);
}

// ------------------------------ HMMA GEMM ----------------------------------
#define KC        32
#define ROWB      80
#define ARR_BYTES (128 * ROWB)
#define BUF_BYTES (4 * ARR_BYTES)
#define GEMM_SMEM (2 * BUF_BYTES)

__global__ __launch_bounds__(256, 2)
void gemm_mma(const __nv_bfloat16* __restrict__ Ahi, const __nv_bfloat16* __restrict__ Alo,
              const __nv_bfloat16* __restrict__ Bhi0, const __nv_bfloat16* __restrict__ Blo0,
              const __nv_bfloat16* __restrict__ Bhi1, const __nv_bfloat16* __restrict__ Blo1,
              float* __restrict__ C0, float* __restrict__ C1,
              __nv_bfloat16* __restrict__ Ohi0, __nv_bfloat16* __restrict__ Olo0,
              __nv_bfloat16* __restrict__ Ohi1, __nv_bfloat16* __restrict__ Olo1,
              int split_out, int Nw, int K)
{
    const __nv_bfloat16* Bhi = blockIdx.z ? Bhi1 : Bhi0;
    const __nv_bfloat16* Blo = blockIdx.z ? Blo1 : Blo0;
    float* C = blockIdx.z ? C1 : C0;
    __nv_bfloat16* Ohi = blockIdx.z ? Ohi1 : Ohi0;
    __nv_bfloat16* Olo = blockIdx.z ? Olo1 : Olo0;

    extern __shared__ char smem[];
    const uint32_t sb = smem_u32(smem);

    const int tid = threadIdx.x, lane = tid & 31, wid = tid >> 5;
    const int warp_m = wid & 3, warp_n = wid >> 2;
    const int m0 = blockIdx.y * 128, n0 = blockIdx.x * 128;
    const int nchunk = K / KC;

    const int frow0 = tid >> 2, fcol = tid & 3;

    auto issue_chunk = [&](int c) {
        const uint32_t base = sb + (c & 1) * BUF_BYTES;
        const int k0 = c * KC;
        #pragma unroll
        for (int i = 0; i < 2; i++) {
            const int row = frow0 + i * 64;
            const uint32_t soff = (uint32_t)row * ROWB + fcol * 16;
            const size_t ga = (size_t)(m0 + row) * K + k0 + fcol * 8;
            const size_t gb = (size_t)(n0 + row) * K + k0 + fcol * 8;
            cp_async16(base + soff,                 Ahi + ga);
            cp_async16(base + ARR_BYTES + soff,     Alo + ga);
            cp_async16(base + 2 * ARR_BYTES + soff, Bhi + gb);
            cp_async16(base + 3 * ARR_BYTES + soff, Blo + gb);
        }
    };

    float acc[2][8][4];
    #pragma unroll
    for (int mt = 0; mt < 2; mt++)
        #pragma unroll
        for (int j = 0; j < 8; j++)
            #pragma unroll
            for (int q = 0; q < 4; q++) acc[mt][j][q] = 0.f;

    issue_chunk(0);
    CP_COMMIT();

    const int arow_l = (lane & 15);
    const int akc_l  = (lane >> 4) << 3;
    const int brow_l = (lane & 7) + ((lane & 16) ? 8 : 0);
    const int bkc_l  = (lane & 8) ? 8 : 0;

    for (int c = 0; c < nchunk; c++) {
        if (c + 1 < nchunk) issue_chunk(c + 1);
        CP_COMMIT();
        CP_WAIT1();
        __syncthreads();

        const uint32_t base = sb + (c & 1) * BUF_BYTES;
        #pragma unroll
        for (int ks = 0; ks < 2; ks++) {
            uint32_t ah[2][4], al[2][4];
            #pragma unroll
            for (int mt = 0; mt < 2; mt++) {
                uint32_t addr = base + (uint32_t)(warp_m * 32 + mt * 16 + arow_l) * ROWB
                              + (ks * 16 + akc_l) * 2;
                ldmatrix_x4(ah[mt][0], ah[mt][1], ah[mt][2], ah[mt][3], addr);
                ldmatrix_x4(al[mt][0], al[mt][1], al[mt][2], al[mt][3], addr + ARR_BYTES);
            }
            #pragma unroll
            for (int jp = 0; jp < 4; jp++) {
                uint32_t baddr = base + 2 * ARR_BYTES
                               + (uint32_t)(warp_n * 64 + jp * 16 + brow_l) * ROWB
                               + (ks * 16 + bkc_l) * 2;
                uint32_t bh[4], bl[4];
                ldmatrix_x4(bh[0], bh[1], bh[2], bh[3], baddr);
                ldmatrix_x4(bl[0], bl[1], bl[2], bl[3], baddr + ARR_BYTES);
                #pragma unroll
                for (int sub = 0; sub < 2; sub++) {
                    const int j = jp * 2 + sub;
                    #pragma unroll
                    for (int mt = 0; mt < 2; mt++) {
                        mma16816(acc[mt][j], ah[mt], &bh[sub * 2]);
                        mma16816(acc[mt][j], ah[mt], &bl[sub * 2]);
                        mma16816(acc[mt][j], al[mt], &bh[sub * 2]);
                    }
                }
            }
        }
        __syncthreads();
    }

    #pragma unroll
    for (int mt = 0; mt < 2; mt++) {
        const int r0 = m0 + warp_m * 32 + mt * 16 + (lane >> 2);
        #pragma unroll
        for (int j = 0; j < 8; j++) {
            const int col = n0 + warp_n * 64 + j * 8 + (lane & 3) * 2;
            if (!split_out) {
                *(float2*)&C[(size_t)r0 * Nw + col]       = make_float2(acc[mt][j][0], acc[mt][j][1]);
                *(float2*)&C[(size_t)(r0 + 8) * Nw + col] = make_float2(acc[mt][j][2], acc[mt][j][3]);
            } else {
                uint32_t h0, l0, h1, l1;
                split2(acc[mt][j][0], acc[mt][j][1], h0, l0);
                split2(acc[mt][j][2], acc[mt][j][3], h1, l1);
                *(uint32_t*)&Ohi[(size_t)r0 * Nw + col]       = h0;
                *(uint32_t*)&Olo[(size_t)r0 * Nw + col]       = l0;
                *(uint32_t*)&Ohi[(size_t)(r0 + 8) * Nw + col] = h1;
                *(uint32_t*)&Olo[(size_t)(r0 + 8) * Nw + col] = l1;
            }
        }
    }
}

// ------------------------------ attention ----------------------------------
// 128-row q tiles, 8 warps; each warp owns 16 q-rows x ALL 64 v-cols.
// No phase-1 duplication; denominator is warp-local (2x shfl_xor, no smem).
// Phase 1 (HMMA, 3-pass split): S = Q K^T, Q fragments persistent.
// phi computed on fp32 C-frags in registers, repacked in-register to A frags.
// Phase 2 (HMMA, 3-pass split): acc += A @ (Vh+Vl). 1 syncthreads per k-tile.
#define QPITCH   48
#define V_PITCH  144
#define SM_QH    0
#define SM_QL    6144
#define SM_KBUF(b) (12288 + (b) * 6144)     // KH +0, KL +3072
#define SM_VBUF(b) (24576 + (b) * 18432)    // VH +0, VL +9216
#define ATTN_SMEM 61440

__global__ __launch_bounds__(256)
void attn_kernel()
{
    extern __shared__ char sm[];
    const uint32_t sb = smem_u32(sm);

    const int qt = blockIdx.x, h = blockIdx.y, b = blockIdx.z;   // qt: 128-row tile
    const int tid = threadIdx.x, lane = tid & 31, wid = tid >> 5; // wid = warp m-tile
    const int g = lane >> 2, tg = lane & 3;

    const size_t tok0 = (size_t)(b * L_SEQ + qt * 128);
    const int row_base = qt * 128 + wid * 16;   // global q row of this warp's g=0

    auto issue_q = [&]() {
        #pragma unroll
        for (int i = 0; i < 2; i++) {   // 512 x 16B, 2 per thread
            int idx = tid + i * 256;
            int arr = idx >> 8, rem = idx & 255, row = rem >> 1, seg = rem & 1;
            uint32_t dst = sb + (arr ? SM_QL : SM_QH) + (uint32_t)row * QPITCH + seg * 16;
            const __nv_bfloat16* src = (arr ? g_Qlo : g_Qhi)
                + (tok0 + row) * NQK + h * FDIM + seg * 8;
            cp_async16(dst, src);
        }
    };
    auto issue_kv = [&](int kt, int buf) {
        const size_t ktok = (size_t)(b * L_SEQ + kt * 64);
        {   // K: 256 x 16B, 1 per thread
            int arr = tid >> 7, rem = tid & 127, row = rem >> 1, seg = rem & 1;
            uint32_t dst = sb + SM_KBUF(buf) + arr * 3072 + (uint32_t)row * QPITCH + seg * 16;
            const __nv_bfloat16* src = (arr ? g_Klo : g_Khi) + (ktok + row) * NQK + h * FDIM + seg * 8;
            cp_async16(dst, src);
        }
        #pragma unroll
        for (int i = 0; i < 4; i++) {   // V: 1024 x 16B, 4 per thread
            int idx = tid + i * 256, arr = idx >> 9, rem = idx & 511, row = rem >> 3, seg = rem & 7;
            uint32_t dst = sb + SM_VBUF(buf) + arr * 9216 + (uint32_t)row * V_PITCH + seg * 16;
            const __nv_bfloat16* src = (arr ? g_Vlo : g_Vhi) + (ktok + row) * DMODEL + h * VDIM + seg * 8;
            cp_async16(dst, src);
        }
    };

    issue_q();
    issue_kv(0, 0);
    CP_COMMIT();
    CP_WAIT0();
    __syncthreads();

    // persistent Q fragments (m16k16 per warp)
    uint32_t qh4[4], ql4[4];
    {
        uint32_t off = (uint32_t)(wid * 16 + (lane & 15)) * QPITCH + ((lane >> 4) << 3) * 2;
        ldmatrix_x4(qh4[0], qh4[1], qh4[2], qh4[3], sb + SM_QH + off);
        ldmatrix_x4(ql4[0], ql4[1], ql4[2], ql4[3], sb + SM_QL + off);
    }

    const int ktmax = 2 * qt + 1;
    issue_kv(1, 1);            // ktmax >= 1 always
    CP_COMMIT();

    float acc[8][4];
    #pragma unroll
    for (int j = 0; j < 8; j++)
        #pragma unroll
        for (int q = 0; q < 4; q++) acc[j][q] = 0.f;
    float dden0 = 0.f, dden1 = 0.f;

    for (int kt = 0; kt <= ktmax; kt++) {
        const int buf = kt & 1;
        if (kt > 0) {
            CP_WAIT0();
            __syncthreads();
            if (kt < ktmax) { issue_kv(kt + 1, buf ^ 1); CP_COMMIT(); }
        }

        // warp early-out: every col in this k-tile exceeds every row of this warp
        if (kt * 64 > row_base + 15) continue;

        // ---- phase 1: S = Q K^T (16 rows x 64 cols)
        float s_acc[8][4];
        #pragma unroll
        for (int j = 0; j < 8; j++)
            #pragma unroll
            for (int e = 0; e < 4; e++) s_acc[j][e] = 0.f;

        const uint32_t kh_b = sb + SM_KBUF(buf), kl_b = kh_b + 3072;
        #pragma unroll
        for (int jp2 = 0; jp2 < 4; jp2++) {
            uint32_t koff = (uint32_t)(jp2 * 16 + (lane & 7) + ((lane & 16) ? 8 : 0)) * QPITCH
                          + ((lane & 8) ? 16 : 0);
            uint32_t bh4[4], bl4[4];
            ldmatrix_x4(bh4[0], bh4[1], bh4[2], bh4[3], kh_b + koff);
            ldmatrix_x4(bl4[0], bl4[1], bl4[2], bl4[3], kl_b + koff);
            #pragma unroll
            for (int sub = 0; sub < 2; sub++) {
                const int j = jp2 * 2 + sub;
                mma16816(s_acc[j], qh4, &bh4[sub * 2]);
                mma16816(s_acc[j], qh4, &bl4[sub * 2]);
                mma16816(s_acc[j], ql4, &bh4[sub * 2]);
            }
        }

        // ---- phi + causal mask + denominator + in-register repack to A frags
        uint32_t pah[16], pal[16];
        const bool need_mask = (kt * 64 + 63 > row_base);
        #pragma unroll
        for (int j = 0; j < 8; j++) {
            float ph[4];
            #pragma unroll
            for (int e = 0; e < 4; e++) {
                float s = s_acc[j][e] * 0.25f;
                float phi = fmaf(s, fmaf(0.5f, s, 1.f), 1.f);
                if (need_mask) {
                    int col = kt * 64 + j * 8 + tg * 2 + (e & 1);
                    int row = row_base + g + ((e >= 2) ? 8 : 0);
                    if (col > row) phi = 0.f;
                }
                ph[e] = phi;
            }
            dden0 += ph[0] + ph[1];
            dden1 += ph[2] + ph[3];
            split2(ph[0], ph[1], pah[j * 2 + 0], pal[j * 2 + 0]);
            split2(ph[2], ph[3], pah[j * 2 + 1], pal[j * 2 + 1]);
        }

        // ---- phase 2: acc += A(16x64) @ V(64x64)
        const uint32_t vh_b = sb + SM_VBUF(buf), vl_b = vh_b + 9216;
        #pragma unroll
        for (int ksi = 0; ksi < 4; ksi++) {
            const uint32_t* ah = &pah[ksi * 4];
            const uint32_t* al = &pal[ksi * 4];
            #pragma unroll
            for (int jp = 0; jp < 4; jp++) {
                uint32_t voff = (uint32_t)(ksi * 16 + (lane & 15)) * V_PITCH
                              + (jp * 16 + ((lane >> 4) << 3)) * 2;
                uint32_t vh4[4], vl4[4];
                ldmatrix_x4_t(vh4[0], vh4[1], vh4[2], vh4[3], vh_b + voff);
                ldmatrix_x4_t(vl4[0], vl4[1], vl4[2], vl4[3], vl_b + voff);
                #pragma unroll
                for (int sub = 0; sub < 2; sub++) {
                    const int j2 = jp * 2 + sub;
                    mma16816(acc[j2], ah, &vh4[sub * 2]);
                    mma16816(acc[j2], ah, &vl4[sub * 2]);
                    mma16816(acc[j2], al, &vh4[sub * 2]);
                }
            }
        }
    }

    // ---- denominator: quad shuffle reduction (rows are warp-exclusive)
    dden0 += __shfl_xor_sync(0xffffffff, dden0, 1);
    dden0 += __shfl_xor_sync(0xffffffff, dden0, 2);
    dden1 += __shfl_xor_sync(0xffffffff, dden1, 1);
    dden1 += __shfl_xor_sync(0xffffffff, dden1, 2);
    const float z0 = 1.f / (dden0 + 1e-12f);
    const float z1 = 1.f / (dden1 + 1e-12f);

    // ---- epilogue: scale, split, write Y
    {
        const size_t grow0 = tok0 + wid * 16 + g;
        #pragma unroll
        for (int j = 0; j < 8; j++) {
            const int col = h * VDIM + j * 8 + tg * 2;
            uint32_t h0, l0, h1, l1;
            split2(acc[j][0] * z0, acc[j][1] * z0, h0, l0);
            split2(acc[j][2] * z1, acc[j][3] * z1, h1, l1);
            *(uint32_t*)&g_Yhi[grow0 * DMODEL + col]       = h0;
            *(uint32_t*)&g_Ylo[grow0 * DMODEL + col]       = l0;
            *(uint32_t*)&g_Yhi[(grow0 + 8) * DMODEL + col] = h1;
            *(uint32_t*)&g_Ylo[(grow0 + 8) * DMODEL + col] = l1;
        }
    }
}

// ---------------------------------------------------------------------------
extern "C" void kernel_launch(void* const* d_in, const int* in_sizes, int n_in,
                              void* d_out, int out_size)
{
    const float* X  = (const float*)d_in[0];
    const float* Wq = (const float*)d_in[1];
    const float* Wk = (const float*)d_in[2];
    const float* Wv = (const float*)d_in[3];
    const float* Wo = (const float*)d_in[4];
    float* out = (float*)d_out;

    __nv_bfloat16 *Qhi, *Qlo, *Khi, *Klo;
    __nv_bfloat16 *Xhi, *Xlo, *Vhi, *Vlo, *Yhi, *Ylo;
    __nv_bfloat16 *WqTh, *WqTl, *WkTh, *WkTl, *WvTh, *WvTl, *WoTh, *WoTl;
    cudaGetSymbolAddress((void**)&Qhi, g_Qhi);
    cudaGetSymbolAddress((void**)&Qlo, g_Qlo);
    cudaGetSymbolAddress((void**)&Khi, g_Khi);
    cudaGetSymbolAddress((void**)&Klo, g_Klo);
    cudaGetSymbolAddress((void**)&Xhi, g_Xhi);
    cudaGetSymbolAddress((void**)&Xlo, g_Xlo);
    cudaGetSymbolAddress((void**)&Vhi, g_Vhi);
    cudaGetSymbolAddress((void**)&Vlo, g_Vlo);
    cudaGetSymbolAddress((void**)&Yhi, g_Yhi);
    cudaGetSymbolAddress((void**)&Ylo, g_Ylo);
    cudaGetSymbolAddress((void**)&WqTh, g_WqT_hi);
    cudaGetSymbolAddress((void**)&WqTl, g_WqT_lo);
    cudaGetSymbolAddress((void**)&WkTh, g_WkT_hi);
    cudaGetSymbolAddress((void**)&WkTl, g_WkT_lo);
    cudaGetSymbolAddress((void**)&WvTh, g_WvT_hi);
    cudaGetSymbolAddress((void**)&WvTl, g_WvT_lo);
    cudaGetSymbolAddress((void**)&WoTh, g_WoT_hi);
    cudaGetSymbolAddress((void**)&WoTl, g_WoT_lo);

    cudaFuncSetAttribute(gemm_mma, cudaFuncAttributeMaxDynamicSharedMemorySize, GEMM_SMEM);
    cudaFuncSetAttribute(attn_kernel, cudaFuncAttributeMaxDynamicSharedMemorySize, ATTN_SMEM);

    const int n4 = MTOT * DMODEL / 4;
    split_bf16<<<(n4 + 255) / 256, 256>>>((const float4*)X, (uint2*)Xhi, (uint2*)Xlo, n4);
    transpose_split_all<<<dim3(32, 32, 4), dim3(32, 32)>>>(Wq, Wk, Wv, Wo);

    // Q & K projections (z-fused), split bf16 out
    gemm_mma<<<dim3(NQK / 128, MTOT / 128, 2), 256, GEMM_SMEM>>>(
        Xhi, Xlo, WqTh, WqTl, WkTh, WkTl, nullptr, nullptr,
        Qhi, Qlo, Khi, Klo, 1, NQK, DMODEL);
    // V projection, split bf16 out
    gemm_mma<<<dim3(DMODEL / 128, MTOT / 128, 1), 256, GEMM_SMEM>>>(
        Xhi, Xlo, WvTh, WvTl, WvTh, WvTl, nullptr, nullptr,
        Vhi, Vlo, Vhi, Vlo, 1, DMODEL, DMODEL);
    // causal taylor-exp attention (full HMMA), split bf16 out
    attn_kernel<<<dim3(L_SEQ / 128, NH, B_SZ), 256, ATTN_SMEM>>>();
    // output projection, fp32 out -> d_out
    gemm_mma<<<dim3(DMODEL / 128, MTOT / 128, 1), 256, GEMM_SMEM>>>(
        Yhi, Ylo, WoTh, WoTl, WoTh, WoTl, out, out,
        nullptr, nullptr, nullptr, nullptr, 0, DMODEL, DMODEL);
}

// round 9
// speedup vs baseline: 2.4266x; 1.0550x over previous
#include <cuda_runtime.h>
#include <cuda_bf16.h>
#include <cstdint>

#define B_SZ   2
#define L_SEQ  2048
#define NH     16
#define FDIM   16
#define VDIM   64
#define DMODEL 1024
#define MTOT   (B_SZ * L_SEQ)   // 4096
#define NQK    (NH * FDIM)      // 256

// ------------------------------ scratch (device globals) -------------------
__device__ __nv_bfloat16 g_Qhi[(size_t)MTOT * NQK];
__device__ __nv_bfloat16 g_Qlo[(size_t)MTOT * NQK];
__device__ __nv_bfloat16 g_Khi[(size_t)MTOT * NQK];
__device__ __nv_bfloat16 g_Klo[(size_t)MTOT * NQK];

__device__ __nv_bfloat16 g_Xhi[(size_t)MTOT * DMODEL];
__device__ __nv_bfloat16 g_Xlo[(size_t)MTOT * DMODEL];
__device__ __nv_bfloat16 g_Vhi[(size_t)MTOT * DMODEL];
__device__ __nv_bfloat16 g_Vlo[(size_t)MTOT * DMODEL];
__device__ __nv_bfloat16 g_Yhi[(size_t)MTOT * DMODEL];
__device__ __nv_bfloat16 g_Ylo[(size_t)MTOT * DMODEL];

__device__ __nv_bfloat16 g_WqT_hi[(size_t)NQK * DMODEL];
__device__ __nv_bfloat16 g_WqT_lo[(size_t)NQK * DMODEL];
__device__ __nv_bfloat16 g_WkT_hi[(size_t)NQK * DMODEL];
__device__ __nv_bfloat16 g_WkT_lo[(size_t)NQK * DMODEL];
__device__ __nv_bfloat16 g_WvT_hi[(size_t)DMODEL * DMODEL];
__device__ __nv_bfloat16 g_WvT_lo[(size_t)DMODEL * DMODEL];
__device__ __nv_bfloat16 g_WoT_hi[(size_t)DMODEL * DMODEL];
__device__ __nv_bfloat16 g_WoT_lo[(size_t)DMODEL * DMODEL];

// ------------------------------ helpers ------------------------------------
__device__ __forceinline__ uint32_t smem_u32(const void* p) {
    uint32_t a;
    asm("{ .reg .u64 t; cvta.to.shared.u64 t, %1; cvt.u32.u64 %0, t; }" : "=r"(a) : "l"(p));
    return a;
}
__device__ __forceinline__ void cp_async16(uint32_t s, const void* g) {
    asm volatile("cp.async.cg.shared.global [%0], [%1], 16;" :: "r"(s), "l"(g));
}
#define CP_COMMIT() asm volatile("cp.async.commit_group;" ::: "memory")
#define CP_WAIT0()  asm volatile("cp.async.wait_group 0;" ::: "memory")

__device__ __forceinline__ void ldmatrix_x4(uint32_t& r0, uint32_t& r1, uint32_t& r2, uint32_t& r3,
                                            uint32_t addr) {
    asm volatile("ldmatrix.sync.aligned.m8n8.x4.shared.b16 {%0,%1,%2,%3}, [%4];"
                 : "=r"(r0), "=r"(r1), "=r"(r2), "=r"(r3) : "r"(addr));
}
__device__ __forceinline__ void ldmatrix_x4_t(uint32_t& r0, uint32_t& r1, uint32_t& r2, uint32_t& r3,
                                              uint32_t addr) {
    asm volatile("ldmatrix.sync.aligned.m8n8.x4.trans.shared.b16 {%0,%1,%2,%3}, [%4];"
                 : "=r"(r0), "=r"(r1), "=r"(r2), "=r"(r3) : "r"(addr));
}
__device__ __forceinline__ void mma16816(float* d, const uint32_t* a, const uint32_t* b) {
    asm volatile(
        "mma.sync.aligned.m16n8k16.row.col.f32.bf16.bf16.f32 "
        "{%0,%1,%2,%3},{%4,%5,%6,%7},{%8,%9},{%0,%1,%2,%3};"
        : "+f"(d[0]), "+f"(d[1]), "+f"(d[2]), "+f"(d[3])
        : "r"(a[0]), "r"(a[1]), "r"(a[2]), "r"(a[3]), "r"(b[0]), "r"(b[1]));
}
__device__ __forceinline__ void split2(float y0, float y1, uint32_t& hi, uint32_t& lo) {
    __nv_bfloat16 h0 = __float2bfloat16(y0);
    __nv_bfloat16 h1 = __float2bfloat16(y1);
    float r0 = y0 - __bfloat162float(h0);
    float r1 = y1 - __bfloat162float(h1);
    hi = (uint32_t)__bfloat16_as_ushort(h0) | ((uint32_t)__bfloat16_as_ushort(h1) << 16);
    lo = (uint32_t)__bfloat16_as_ushort(__float2bfloat16(r0))
       | ((uint32_t)__bfloat16_as_ushort(__float2bfloat16(r1)) << 16);
}

// ------------------------------ prep kernels -------------------------------
__global__ void split_bf16(const float4* __restrict__ x,
                           uint2* __restrict__ hi, uint2* __restrict__ lo, int n4)
{
    int i = blockIdx.x * blockDim.x + threadIdx.x;
    if (i >= n4) return;
    float4 v = x[i];
    float f[4] = {v.x, v.y, v.z, v.w};
    unsigned short h[4], l[4];
    #pragma unroll
    for (int c = 0; c < 4; c++) {
        __nv_bfloat16 hb = __float2bfloat16(f[c]);
        float r = f[c] - __bfloat162float(hb);
        h[c] = __bfloat16_as_ushort(hb);
        l[c] = __bfloat16_as_ushort(__float2bfloat16(r));
    }
    hi[i] = make_uint2((uint32_t)h[0] | ((uint32_t)h[1] << 16),
                       (uint32_t)h[2] | ((uint32_t)h[3] << 16));
    lo[i] = make_uint2((uint32_t)l[0] | ((uint32_t)l[1] << 16),
                       (uint32_t)l[2] | ((uint32_t)l[3] << 16));
}

// All 4 weight transposes fused: W (K x N) row-major -> T (N x K) bf16 hi/lo.
__global__ void transpose_split_all(const float* __restrict__ Wq, const float* __restrict__ Wk,
                                    const float* __restrict__ Wv, const float* __restrict__ Wo)
{
    __shared__ float t[32][33];
    const int z = blockIdx.z;
    const float* W;
    __nv_bfloat16 *Th, *Tl;
    int N;
    if (z == 0)      { W = Wq; Th = g_WqT_hi; Tl = g_WqT_lo; N = NQK; }
    else if (z == 1) { W = Wk; Th = g_WkT_hi; Tl = g_WkT_lo; N = NQK; }
    else if (z == 2) { W = Wv; Th = g_WvT_hi; Tl = g_WvT_lo; N = DMODEL; }
    else             { W = Wo; Th = g_WoT_hi; Tl = g_WoT_lo; N = DMODEL; }
    const int n0 = blockIdx.x * 32;
    if (n0 >= N) return;
    const int k0 = blockIdx.y * 32;
    t[threadIdx.y][threadIdx.x] = W[(size_t)(k0 + threadIdx.y) * N + n0 + threadIdx.x];
    __syncthreads();
    float v = t[threadIdx.x][threadIdx.y];
    int n = n0 + threadIdx.y, k = k0 + threadIdx.x;
    __nv_bfloat16 hb = __float2bfloat16(v);
    float r = v - __bfloat162float(hb);
    Th[(size_t)n * DMODEL + k] = hb;
    Tl[(size_t)n * DMODEL + k] = __float2bfloat16(r);
}

// ------------------------------ HMMA GEMM body -----------------------------
// 128x128 CTA tile, K=1024 in KC=32 chunks, double-buffered cp.async,
// ONE syncthreads per chunk (sync both publishes buf(c) and retires buf(c-1)).
#define KC        32
#define ROWB      80
#define ARR_BYTES (128 * ROWB)
#define BUF_BYTES (4 * ARR_BYTES)
#define GEMM_SMEM (2 * BUF_BYTES)

__device__ __forceinline__ void gemm_body(
    const __nv_bfloat16* __restrict__ Ahi, const __nv_bfloat16* __restrict__ Alo,
    const __nv_bfloat16* __restrict__ Bhi, const __nv_bfloat16* __restrict__ Blo,
    float* __restrict__ C, __nv_bfloat16* __restrict__ Ohi, __nv_bfloat16* __restrict__ Olo,
    int split_out, int m0, int n0, int Nw, char* smem)
{
    const uint32_t sb = smem_u32(smem);
    const int tid = threadIdx.x, lane = tid & 31, wid = tid >> 5;
    const int warp_m = wid & 3, warp_n = wid >> 2;
    const int nchunk = DMODEL / KC;
    const int frow0 = tid >> 2, fcol = tid & 3;

    auto issue_chunk = [&](int c) {
        const uint32_t base = sb + (c & 1) * BUF_BYTES;
        const int k0 = c * KC;
        #pragma unroll
        for (int i = 0; i < 2; i++) {
            const int row = frow0 + i * 64;
            const uint32_t soff = (uint32_t)row * ROWB + fcol * 16;
            const size_t ga = (size_t)(m0 + row) * DMODEL + k0 + fcol * 8;
            const size_t gb = (size_t)(n0 + row) * DMODEL + k0 + fcol * 8;
            cp_async16(base + soff,                 Ahi + ga);
            cp_async16(base + ARR_BYTES + soff,     Alo + ga);
            cp_async16(base + 2 * ARR_BYTES + soff, Bhi + gb);
            cp_async16(base + 3 * ARR_BYTES + soff, Blo + gb);
        }
    };

    float acc[2][8][4];
    #pragma unroll
    for (int mt = 0; mt < 2; mt++)
        #pragma unroll
        for (int j = 0; j < 8; j++)
            #pragma unroll
            for (int q = 0; q < 4; q++) acc[mt][j][q] = 0.f;

    issue_chunk(0);
    CP_COMMIT();

    const int arow_l = (lane & 15);
    const int akc_l  = (lane >> 4) << 3;
    const int brow_l = (lane & 7) + ((lane & 16) ? 8 : 0);
    const int bkc_l  = (lane & 8) ? 8 : 0;

    for (int c = 0; c < nchunk; c++) {
        CP_WAIT0();
        __syncthreads();
        if (c + 1 < nchunk) { issue_chunk(c + 1); CP_COMMIT(); }

        const uint32_t base = sb + (c & 1) * BUF_BYTES;
        #pragma unroll
        for (int ks = 0; ks < 2; ks++) {
            uint32_t ah[2][4], al[2][4];
            #pragma unroll
            for (int mt = 0; mt < 2; mt++) {
                uint32_t addr = base + (uint32_t)(warp_m * 32 + mt * 16 + arow_l) * ROWB
                              + (ks * 16 + akc_l) * 2;
                ldmatrix_x4(ah[mt][0], ah[mt][1], ah[mt][2], ah[mt][3], addr);
                ldmatrix_x4(al[mt][0], al[mt][1], al[mt][2], al[mt][3], addr + ARR_BYTES);
            }
            #pragma unroll
            for (int jp = 0; jp < 4; jp++) {
                uint32_t baddr = base + 2 * ARR_BYTES
                               + (uint32_t)(warp_n * 64 + jp * 16 + brow_l) * ROWB
                               + (ks * 16 + bkc_l) * 2;
                uint32_t bh[4], bl[4];
                ldmatrix_x4(bh[0], bh[1], bh[2], bh[3], baddr);
                ldmatrix_x4(bl[0], bl[1], bl[2], bl[3], baddr + ARR_BYTES);
                #pragma unroll
                for (int sub = 0; sub < 2; sub++) {
                    const int j = jp * 2 + sub;
                    #pragma unroll
                    for (int mt = 0; mt < 2; mt++) {
                        mma16816(acc[mt][j], ah[mt], &bh[sub * 2]);
                        mma16816(acc[mt][j], ah[mt], &bl[sub * 2]);
                        mma16816(acc[mt][j], al[mt], &bh[sub * 2]);
                    }
                }
            }
        }
    }

    #pragma unroll
    for (int mt = 0; mt < 2; mt++) {
        const int r0 = m0 + warp_m * 32 + mt * 16 + (lane >> 2);
        #pragma unroll
        for (int j = 0; j < 8; j++) {
            const int col = n0 + warp_n * 64 + j * 8 + (lane & 3) * 2;
            if (!split_out) {
                *(float2*)&C[(size_t)r0 * Nw + col]       = make_float2(acc[mt][j][0], acc[mt][j][1]);
                *(float2*)&C[(size_t)(r0 + 8) * Nw + col] = make_float2(acc[mt][j][2], acc[mt][j][3]);
            } else {
                uint32_t h0, l0, h1, l1;
                split2(acc[mt][j][0], acc[mt][j][1], h0, l0);
                split2(acc[mt][j][2], acc[mt][j][3], h1, l1);
                *(uint32_t*)&Ohi[(size_t)r0 * Nw + col]       = h0;
                *(uint32_t*)&Olo[(size_t)r0 * Nw + col]       = l0;
                *(uint32_t*)&Ohi[(size_t)(r0 + 8) * Nw + col] = h1;
                *(uint32_t*)&Olo[(size_t)(r0 + 8) * Nw + col] = l1;
            }
        }
    }
}

// Fused Q/K/V projection: one launch, 384 equal-work CTAs (V first for packing).
__global__ __launch_bounds__(256, 2)
void gemm_qkv(const __nv_bfloat16* __restrict__ Xhi, const __nv_bfloat16* __restrict__ Xlo)
{
    extern __shared__ char smem[];
    const int bid = blockIdx.x;
    const __nv_bfloat16 *Bh, *Bl;
    __nv_bfloat16 *oh, *ol;
    int m0, n0, Nw;
    if (bid < 256) {                       // V projection: 8 x 32 tiles
        m0 = (bid >> 3) * 128; n0 = (bid & 7) * 128; Nw = DMODEL;
        Bh = g_WvT_hi; Bl = g_WvT_lo; oh = g_Vhi; ol = g_Vlo;
    } else {                               // Q/K projections: 2 x (2 x 32) tiles
        const int t = bid - 256;
        const int zz = t >> 6, t2 = t & 63;
        m0 = (t2 >> 1) * 128; n0 = (t2 & 1) * 128; Nw = NQK;
        if (zz == 0) { Bh = g_WqT_hi; Bl = g_WqT_lo; oh = g_Qhi; ol = g_Qlo; }
        else         { Bh = g_WkT_hi; Bl = g_WkT_lo; oh = g_Khi; ol = g_Klo; }
    }
    gemm_body(Xhi, Xlo, Bh, Bl, nullptr, oh, ol, 1, m0, n0, Nw, smem);
}

// Output projection: fp32 out -> d_out
__global__ __launch_bounds__(256, 2)
void gemm_out(const __nv_bfloat16* __restrict__ Yhi, const __nv_bfloat16* __restrict__ Ylo,
              float* __restrict__ out)
{
    extern __shared__ char smem[];
    gemm_body(Yhi, Ylo, g_WoT_hi, g_WoT_lo, out, nullptr, nullptr, 0,
              blockIdx.y * 128, blockIdx.x * 128, DMODEL, smem);
}

// ------------------------------ attention ----------------------------------
// 128-row q tiles, 8 warps; each warp owns 16 q-rows x ALL 64 v-cols.
// Heavy-first scheduling: qt = gridDim.x-1-blockIdx.x (work per CTA ~ 2qt+2).
#define QPITCH   48
#define V_PITCH  144
#define SM_QH    0
#define SM_QL    6144
#define SM_KBUF(b) (12288 + (b) * 6144)     // KH +0, KL +3072
#define SM_VBUF(b) (24576 + (b) * 18432)    // VH +0, VL +9216
#define ATTN_SMEM 61440

__global__ __launch_bounds__(256)
void attn_kernel()
{
    extern __shared__ char sm[];
    const uint32_t sb = smem_u32(sm);

    const int qt = gridDim.x - 1 - blockIdx.x;                   // heavy first
    const int h = blockIdx.y, b = blockIdx.z;
    const int tid = threadIdx.x, lane = tid & 31, wid = tid >> 5;
    const int g = lane >> 2, tg = lane & 3;

    const size_t tok0 = (size_t)(b * L_SEQ + qt * 128);
    const int row_base = qt * 128 + wid * 16;

    auto issue_q = [&]() {
        #pragma unroll
        for (int i = 0; i < 2; i++) {
            int idx = tid + i * 256;
            int arr = idx >> 8, rem = idx & 255, row = rem >> 1, seg = rem & 1;
            uint32_t dst = sb + (arr ? SM_QL : SM_QH) + (uint32_t)row * QPITCH + seg * 16;
            const __nv_bfloat16* src = (arr ? g_Qlo : g_Qhi)
                + (tok0 + row) * NQK + h * FDIM + seg * 8;
            cp_async16(dst, src);
        }
    };
    auto issue_kv = [&](int kt, int buf) {
        const size_t ktok = (size_t)(b * L_SEQ + kt * 64);
        {
            int arr = tid >> 7, rem = tid & 127, row = rem >> 1, seg = rem & 1;
            uint32_t dst = sb + SM_KBUF(buf) + arr * 3072 + (uint32_t)row * QPITCH + seg * 16;
            const __nv_bfloat16* src = (arr ? g_Klo : g_Khi) + (ktok + row) * NQK + h * FDIM + seg * 8;
            cp_async16(dst, src);
        }
        #pragma unroll
        for (int i = 0; i < 4; i++) {
            int idx = tid + i * 256, arr = idx >> 9, rem = idx & 511, row = rem >> 3, seg = rem & 7;
            uint32_t dst = sb + SM_VBUF(buf) + arr * 9216 + (uint32_t)row * V_PITCH + seg * 16;
            const __nv_bfloat16* src = (arr ? g_Vlo : g_Vhi) + (ktok + row) * DMODEL + h * VDIM + seg * 8;
            cp_async16(dst, src);
        }
    };

    issue_q();
    issue_kv(0, 0);
    CP_COMMIT();
    CP_WAIT0();
    __syncthreads();

    uint32_t qh4[4], ql4[4];
    {
        uint32_t off = (uint32_t)(wid * 16 + (lane & 15)) * QPITCH + ((lane >> 4) << 3) * 2;
        ldmatrix_x4(qh4[0], qh4[1], qh4[2], qh4[3], sb + SM_QH + off);
        ldmatrix_x4(ql4[0], ql4[1], ql4[2], ql4[3], sb + SM_QL + off);
    }

    const int ktmax = 2 * qt + 1;
    issue_kv(1, 1);
    CP_COMMIT();

    float acc[8][4];
    #pragma unroll
    for (int j = 0; j < 8; j++)
        #pragma unroll
        for (int q = 0; q < 4; q++) acc[j][q] = 0.f;
    float dden0 = 0.f, dden1 = 0.f;

    for (int kt = 0; kt <= ktmax; kt++) {
        const int buf = kt & 1;
        if (kt > 0) {
            CP_WAIT0();
            __syncthreads();
            if (kt < ktmax) { issue_kv(kt + 1, buf ^ 1); CP_COMMIT(); }
        }

        if (kt * 64 > row_base + 15) continue;

        // ---- phase 1: S = Q K^T (16 rows x 64 cols)
        float s_acc[8][4];
        #pragma unroll
        for (int j = 0; j < 8; j++)
            #pragma unroll
            for (int e = 0; e < 4; e++) s_acc[j][e] = 0.f;

        const uint32_t kh_b = sb + SM_KBUF(buf), kl_b = kh_b + 3072;
        #pragma unroll
        for (int jp2 = 0; jp2 < 4; jp2++) {
            uint32_t koff = (uint32_t)(jp2 * 16 + (lane & 7) + ((lane & 16) ? 8 : 0)) * QPITCH
                          + ((lane & 8) ? 16 : 0);
            uint32_t bh4[4], bl4[4];
            ldmatrix_x4(bh4[0], bh4[1], bh4[2], bh4[3], kh_b + koff);
            ldmatrix_x4(bl4[0], bl4[1], bl4[2], bl4[3], kl_b + koff);
            #pragma unroll
            for (int sub = 0; sub < 2; sub++) {
                const int j = jp2 * 2 + sub;
                mma16816(s_acc[j], qh4, &bh4[sub * 2]);
                mma16816(s_acc[j], qh4, &bl4[sub * 2]);
                mma16816(s_acc[j], ql4, &bh4[sub * 2]);
            }
        }

        // ---- phi + causal mask + denominator + in-register repack
        uint32_t pah[16], pal[16];
        const bool need_mask = (kt * 64 + 63 > row_base);
        #pragma unroll
        for (int j = 0; j < 8; j++) {
            float ph[4];
            #pragma unroll
            for (int e = 0; e < 4; e++) {
                float s = s_acc[j][e] * 0.25f;
                float phi = fmaf(s, fmaf(0.5f, s, 1.f), 1.f);
                if (need_mask) {
                    int col = kt * 64 + j * 8 + tg * 2 + (e & 1);
                    int row = row_base + g + ((e >= 2) ? 8 : 0);
                    if (col > row) phi = 0.f;
                }
                ph[e] = phi;
            }
            dden0 += ph[0] + ph[1];
            dden1 += ph[2] + ph[3];
            split2(ph[0], ph[1], pah[j * 2 + 0], pal[j * 2 + 0]);
            split2(ph[2], ph[3], pah[j * 2 + 1], pal[j * 2 + 1]);
        }

        // ---- phase 2: acc += A(16x64) @ V(64x64)
        const uint32_t vh_b = sb + SM_VBUF(buf), vl_b = vh_b + 9216;
        #pragma unroll
        for (int ksi = 0; ksi < 4; ksi++) {
            const uint32_t* ah = &pah[ksi * 4];
            const uint32_t* al = &pal[ksi * 4];
            #pragma unroll
            for (int jp = 0; jp < 4; jp++) {
                uint32_t voff = (uint32_t)(ksi * 16 + (lane & 15)) * V_PITCH
                              + (jp * 16 + ((lane >> 4) << 3)) * 2;
                uint32_t vh4[4], vl4[4];
                ldmatrix_x4_t(vh4[0], vh4[1], vh4[2], vh4[3], vh_b + voff);
                ldmatrix_x4_t(vl4[0], vl4[1], vl4[2], vl4[3], vl_b + voff);
                #pragma unroll
                for (int sub = 0; sub < 2; sub++) {
                    const int j2 = jp * 2 + sub;
                    mma16816(acc[j2], ah, &vh4[sub * 2]);
                    mma16816(acc[j2], ah, &vl4[sub * 2]);
                    mma16816(acc[j2], al, &vh4[sub * 2]);
                }
            }
        }
    }

    // ---- denominator: quad shuffle reduction (rows warp-exclusive)
    dden0 += __shfl_xor_sync(0xffffffff, dden0, 1);
    dden0 += __shfl_xor_sync(0xffffffff, dden0, 2);
    dden1 += __shfl_xor_sync(0xffffffff, dden1, 1);
    dden1 += __shfl_xor_sync(0xffffffff, dden1, 2);
    const float z0 = 1.f / (dden0 + 1e-12f);
    const float z1 = 1.f / (dden1 + 1e-12f);

    // ---- epilogue
    {
        const size_t grow0 = tok0 + wid * 16 + g;
        #pragma unroll
        for (int j = 0; j < 8; j++) {
            const int col = h * VDIM + j * 8 + tg * 2;
            uint32_t h0, l0, h1, l1;
            split2(acc[j][0] * z0, acc[j][1] * z0, h0, l0);
            split2(acc[j][2] * z1, acc[j][3] * z1, h1, l1);
            *(uint32_t*)&g_Yhi[grow0 * DMODEL + col]       = h0;
            *(uint32_t*)&g_Ylo[grow0 * DMODEL + col]       = l0;
            *(uint32_t*)&g_Yhi[(grow0 + 8) * DMODEL + col] = h1;
            *(uint32_t*)&g_Ylo[(grow0 + 8) * DMODEL + col] = l1;
        }
    }
}

// ---------------------------------------------------------------------------
extern "C" void kernel_launch(void* const* d_in, const int* in_sizes, int n_in,
                              void* d_out, int out_size)
{
    const float* X  = (const float*)d_in[0];
    const float* Wq = (const float*)d_in[1];
    const float* Wk = (const float*)d_in[2];
    const float* Wv = (const float*)d_in[3];
    const float* Wo = (const float*)d_in[4];
    float* out = (float*)d_out;

    __nv_bfloat16 *Xhi, *Xlo, *Yhi, *Ylo;
    cudaGetSymbolAddress((void**)&Xhi, g_Xhi);
    cudaGetSymbolAddress((void**)&Xlo, g_Xlo);
    cudaGetSymbolAddress((void**)&Yhi, g_Yhi);
    cudaGetSymbolAddress((void**)&Ylo, g_Ylo);

    cudaFuncSetAttribute(gemm_qkv, cudaFuncAttributeMaxDynamicSharedMemorySize, GEMM_SMEM);
    cudaFuncSetAttribute(gemm_out, cudaFuncAttributeMaxDynamicSharedMemorySize, GEMM_SMEM);
    cudaFuncSetAttribute(attn_kernel, cudaFuncAttributeMaxDynamicSharedMemorySize, ATTN_SMEM);

    const int n4 = MTOT * DMODEL / 4;
    split_bf16<<<(n4 + 255) / 256, 256>>>((const float4*)X, (uint2*)Xhi, (uint2*)Xlo, n4);
    transpose_split_all<<<dim3(32, 32, 4), dim3(32, 32)>>>(Wq, Wk, Wv, Wo);

    // fused Q/K/V projections, split bf16 out (384 CTAs, one launch)
    gemm_qkv<<<384, 256, GEMM_SMEM>>>(Xhi, Xlo);
    // causal taylor-exp attention (full HMMA), split bf16 out, heavy-first
    attn_kernel<<<dim3(L_SEQ / 128, NH, B_SZ), 256, ATTN_SMEM>>>();
    // output projection, fp32 out -> d_out
    gemm_out<<<dim3(DMODEL / 128, MTOT / 128), 256, GEMM_SMEM>>>(Yhi, Ylo, out);
}

// round 10
// speedup vs baseline: 2.5427x; 1.0478x over previous
#include <cuda_runtime.h>
#include <cuda_bf16.h>
#include <cstdint>

#define B_SZ   2
#define L_SEQ  2048
#define NH     16
#define FDIM   16
#define VDIM   64
#define DMODEL 1024
#define MTOT   (B_SZ * L_SEQ)   // 4096
#define NQK    (NH * FDIM)      // 256

// ------------------------------ scratch (device globals) -------------------
__device__ __nv_bfloat16 g_Qhi[(size_t)MTOT * NQK];
__device__ __nv_bfloat16 g_Qlo[(size_t)MTOT * NQK];
__device__ __nv_bfloat16 g_Khi[(size_t)MTOT * NQK];
__device__ __nv_bfloat16 g_Klo[(size_t)MTOT * NQK];

__device__ __nv_bfloat16 g_Xhi[(size_t)MTOT * DMODEL];
__device__ __nv_bfloat16 g_Xlo[(size_t)MTOT * DMODEL];
__device__ __nv_bfloat16 g_Vhi[(size_t)MTOT * DMODEL];
__device__ __nv_bfloat16 g_Vlo[(size_t)MTOT * DMODEL];
__device__ __nv_bfloat16 g_Yhi[(size_t)MTOT * DMODEL];
__device__ __nv_bfloat16 g_Ylo[(size_t)MTOT * DMODEL];

__device__ __nv_bfloat16 g_WqT_hi[(size_t)NQK * DMODEL];
__device__ __nv_bfloat16 g_WqT_lo[(size_t)NQK * DMODEL];
__device__ __nv_bfloat16 g_WkT_hi[(size_t)NQK * DMODEL];
__device__ __nv_bfloat16 g_WkT_lo[(size_t)NQK * DMODEL];
__device__ __nv_bfloat16 g_WvT_hi[(size_t)DMODEL * DMODEL];
__device__ __nv_bfloat16 g_WvT_lo[(size_t)DMODEL * DMODEL];
__device__ __nv_bfloat16 g_WoT_hi[(size_t)DMODEL * DMODEL];
__device__ __nv_bfloat16 g_WoT_lo[(size_t)DMODEL * DMODEL];

// ------------------------------ helpers ------------------------------------
__device__ __forceinline__ uint32_t smem_u32(const void* p) {
    uint32_t a;
    asm("{ .reg .u64 t; cvta.to.shared.u64 t, %1; cvt.u32.u64 %0, t; }" : "=r"(a) : "l"(p));
    return a;
}
__device__ __forceinline__ void cp_async16(uint32_t s, const void* g) {
    asm volatile("cp.async.cg.shared.global [%0], [%1], 16;" :: "r"(s), "l"(g));
}
#define CP_COMMIT() asm volatile("cp.async.commit_group;" ::: "memory")
#define CP_WAIT0()  asm volatile("cp.async.wait_group 0;" ::: "memory")

__device__ __forceinline__ void ldmatrix_x4(uint32_t& r0, uint32_t& r1, uint32_t& r2, uint32_t& r3,
                                            uint32_t addr) {
    asm volatile("ldmatrix.sync.aligned.m8n8.x4.shared.b16 {%0,%1,%2,%3}, [%4];"
                 : "=r"(r0), "=r"(r1), "=r"(r2), "=r"(r3) : "r"(addr));
}
__device__ __forceinline__ void ldmatrix_x4_t(uint32_t& r0, uint32_t& r1, uint32_t& r2, uint32_t& r3,
                                              uint32_t addr) {
    asm volatile("ldmatrix.sync.aligned.m8n8.x4.trans.shared.b16 {%0,%1,%2,%3}, [%4];"
                 : "=r"(r0), "=r"(r1), "=r"(r2), "=r"(r3) : "r"(addr));
}
__device__ __forceinline__ void mma16816(float* d, const uint32_t* a, const uint32_t* b) {
    asm volatile(
        "mma.sync.aligned.m16n8k16.row.col.f32.bf16.bf16.f32 "
        "{%0,%1,%2,%3},{%4,%5,%6,%7},{%8,%9},{%0,%1,%2,%3};"
        : "+f"(d[0]), "+f"(d[1]), "+f"(d[2]), "+f"(d[3])
        : "r"(a[0]), "r"(a[1]), "r"(a[2]), "r"(a[3]), "r"(b[0]), "r"(b[1]));
}
// split two fp32 into packed bf16 hi + bf16 lo(residual). Uses F2FP.BF16X2
// (one instr packs two) both directions; identical RN rounding to the
// per-element __float2bfloat16 version.
__device__ __forceinline__ void split2(float y0, float y1, uint32_t& hi, uint32_t& lo) {
    uint32_t h;
    asm("cvt.rn.bf16x2.f32 %0, %1, %2;" : "=r"(h) : "f"(y1), "f"(y0));
    float f0 = __uint_as_float(h << 16);
    float f1 = __uint_as_float(h & 0xffff0000u);
    asm("cvt.rn.bf16x2.f32 %0, %1, %2;" : "=r"(lo) : "f"(y1 - f1), "f"(y0 - f0));
    hi = h;
}

// ------------------------------ prep kernels -------------------------------
__global__ void split_bf16(const float4* __restrict__ x,
                           uint2* __restrict__ hi, uint2* __restrict__ lo, int n4)
{
    int i = blockIdx.x * blockDim.x + threadIdx.x;
    if (i >= n4) return;
    float4 v = x[i];
    uint32_t h0, l0, h1, l1;
    split2(v.x, v.y, h0, l0);
    split2(v.z, v.w, h1, l1);
    hi[i] = make_uint2(h0, h1);
    lo[i] = make_uint2(l0, l1);
}

// All 4 weight transposes fused: W (K x N) row-major -> T (N x K) bf16 hi/lo.
__global__ void transpose_split_all(const float* __restrict__ Wq, const float* __restrict__ Wk,
                                    const float* __restrict__ Wv, const float* __restrict__ Wo)
{
    __shared__ float t[32][33];
    const int z = blockIdx.z;
    const float* W;
    __nv_bfloat16 *Th, *Tl;
    int N;
    if (z == 0)      { W = Wq; Th = g_WqT_hi; Tl = g_WqT_lo; N = NQK; }
    else if (z == 1) { W = Wk; Th = g_WkT_hi; Tl = g_WkT_lo; N = NQK; }
    else if (z == 2) { W = Wv; Th = g_WvT_hi; Tl = g_WvT_lo; N = DMODEL; }
    else             { W = Wo; Th = g_WoT_hi; Tl = g_WoT_lo; N = DMODEL; }
    const int n0 = blockIdx.x * 32;
    if (n0 >= N) return;
    const int k0 = blockIdx.y * 32;
    t[threadIdx.y][threadIdx.x] = W[(size_t)(k0 + threadIdx.y) * N + n0 + threadIdx.x];
    __syncthreads();
    float v = t[threadIdx.x][threadIdx.y];
    int n = n0 + threadIdx.y, k = k0 + threadIdx.x;
    __nv_bfloat16 hb = __float2bfloat16(v);
    float r = v - __bfloat162float(hb);
    Th[(size_t)n * DMODEL + k] = hb;
    Tl[(size_t)n * DMODEL + k] = __float2bfloat16(r);
}

// ------------------------------ HMMA GEMM body -----------------------------
#define KC        32
#define ROWB      80
#define ARR_BYTES (128 * ROWB)
#define BUF_BYTES (4 * ARR_BYTES)
#define GEMM_SMEM (2 * BUF_BYTES)

__device__ __forceinline__ void gemm_body(
    const __nv_bfloat16* __restrict__ Ahi, const __nv_bfloat16* __restrict__ Alo,
    const __nv_bfloat16* __restrict__ Bhi, const __nv_bfloat16* __restrict__ Blo,
    float* __restrict__ C, __nv_bfloat16* __restrict__ Ohi, __nv_bfloat16* __restrict__ Olo,
    int split_out, int m0, int n0, int Nw, char* smem)
{
    const uint32_t sb = smem_u32(smem);
    const int tid = threadIdx.x, lane = tid & 31, wid = tid >> 5;
    const int warp_m = wid & 3, warp_n = wid >> 2;
    const int nchunk = DMODEL / KC;
    const int frow0 = tid >> 2, fcol = tid & 3;

    auto issue_chunk = [&](int c) {
        const uint32_t base = sb + (c & 1) * BUF_BYTES;
        const int k0 = c * KC;
        #pragma unroll
        for (int i = 0; i < 2; i++) {
            const int row = frow0 + i * 64;
            const uint32_t soff = (uint32_t)row * ROWB + fcol * 16;
            const size_t ga = (size_t)(m0 + row) * DMODEL + k0 + fcol * 8;
            const size_t gb = (size_t)(n0 + row) * DMODEL + k0 + fcol * 8;
            cp_async16(base + soff,                 Ahi + ga);
            cp_async16(base + ARR_BYTES + soff,     Alo + ga);
            cp_async16(base + 2 * ARR_BYTES + soff, Bhi + gb);
            cp_async16(base + 3 * ARR_BYTES + soff, Blo + gb);
        }
    };

    float acc[2][8][4];
    #pragma unroll
    for (int mt = 0; mt < 2; mt++)
        #pragma unroll
        for (int j = 0; j < 8; j++)
            #pragma unroll
            for (int q = 0; q < 4; q++) acc[mt][j][q] = 0.f;

    issue_chunk(0);
    CP_COMMIT();

    const int arow_l = (lane & 15);
    const int akc_l  = (lane >> 4) << 3;
    const int brow_l = (lane & 7) + ((lane & 16) ? 8 : 0);
    const int bkc_l  = (lane & 8) ? 8 : 0;

    for (int c = 0; c < nchunk; c++) {
        CP_WAIT0();
        __syncthreads();
        if (c + 1 < nchunk) { issue_chunk(c + 1); CP_COMMIT(); }

        const uint32_t base = sb + (c & 1) * BUF_BYTES;
        #pragma unroll
        for (int ks = 0; ks < 2; ks++) {
            uint32_t ah[2][4], al[2][4];
            #pragma unroll
            for (int mt = 0; mt < 2; mt++) {
                uint32_t addr = base + (uint32_t)(warp_m * 32 + mt * 16 + arow_l) * ROWB
                              + (ks * 16 + akc_l) * 2;
                ldmatrix_x4(ah[mt][0], ah[mt][1], ah[mt][2], ah[mt][3], addr);
                ldmatrix_x4(al[mt][0], al[mt][1], al[mt][2], al[mt][3], addr + ARR_BYTES);
            }
            #pragma unroll
            for (int jp = 0; jp < 4; jp++) {
                uint32_t baddr = base + 2 * ARR_BYTES
                               + (uint32_t)(warp_n * 64 + jp * 16 + brow_l) * ROWB
                               + (ks * 16 + bkc_l) * 2;
                uint32_t bh[4], bl[4];
                ldmatrix_x4(bh[0], bh[1], bh[2], bh[3], baddr);
                ldmatrix_x4(bl[0], bl[1], bl[2], bl[3], baddr + ARR_BYTES);
                #pragma unroll
                for (int sub = 0; sub < 2; sub++) {
                    const int j = jp * 2 + sub;
                    #pragma unroll
                    for (int mt = 0; mt < 2; mt++) {
                        mma16816(acc[mt][j], ah[mt], &bh[sub * 2]);
                        mma16816(acc[mt][j], ah[mt], &bl[sub * 2]);
                        mma16816(acc[mt][j], al[mt], &bh[sub * 2]);
                    }
                }
            }
        }
    }

    #pragma unroll
    for (int mt = 0; mt < 2; mt++) {
        const int r0 = m0 + warp_m * 32 + mt * 16 + (lane >> 2);
        #pragma unroll
        for (int j = 0; j < 8; j++) {
            const int col = n0 + warp_n * 64 + j * 8 + (lane & 3) * 2;
            if (!split_out) {
                *(float2*)&C[(size_t)r0 * Nw + col]       = make_float2(acc[mt][j][0], acc[mt][j][1]);
                *(float2*)&C[(size_t)(r0 + 8) * Nw + col] = make_float2(acc[mt][j][2], acc[mt][j][3]);
            } else {
                uint32_t h0, l0, h1, l1;
                split2(acc[mt][j][0], acc[mt][j][1], h0, l0);
                split2(acc[mt][j][2], acc[mt][j][3], h1, l1);
                *(uint32_t*)&Ohi[(size_t)r0 * Nw + col]       = h0;
                *(uint32_t*)&Olo[(size_t)r0 * Nw + col]       = l0;
                *(uint32_t*)&Ohi[(size_t)(r0 + 8) * Nw + col] = h1;
                *(uint32_t*)&Olo[(size_t)(r0 + 8) * Nw + col] = l1;
            }
        }
    }
}

// Fused Q/K/V projection: one launch, 384 equal-work CTAs (V first for packing).
__global__ __launch_bounds__(256, 2)
void gemm_qkv(const __nv_bfloat16* __restrict__ Xhi, const __nv_bfloat16* __restrict__ Xlo)
{
    extern __shared__ char smem[];
    const int bid = blockIdx.x;
    const __nv_bfloat16 *Bh, *Bl;
    __nv_bfloat16 *oh, *ol;
    int m0, n0, Nw;
    if (bid < 256) {                       // V projection: 8 x 32 tiles
        m0 = (bid >> 3) * 128; n0 = (bid & 7) * 128; Nw = DMODEL;
        Bh = g_WvT_hi; Bl = g_WvT_lo; oh = g_Vhi; ol = g_Vlo;
    } else {                               // Q/K projections: 2 x (2 x 32) tiles
        const int t = bid - 256;
        const int zz = t >> 6, t2 = t & 63;
        m0 = (t2 >> 1) * 128; n0 = (t2 & 1) * 128; Nw = NQK;
        if (zz == 0) { Bh = g_WqT_hi; Bl = g_WqT_lo; oh = g_Qhi; ol = g_Qlo; }
        else         { Bh = g_WkT_hi; Bl = g_WkT_lo; oh = g_Khi; ol = g_Klo; }
    }
    gemm_body(Xhi, Xlo, Bh, Bl, nullptr, oh, ol, 1, m0, n0, Nw, smem);
}

// Output projection: fp32 out -> d_out
__global__ __launch_bounds__(256, 2)
void gemm_out(const __nv_bfloat16* __restrict__ Yhi, const __nv_bfloat16* __restrict__ Ylo,
              float* __restrict__ out)
{
    extern __shared__ char smem[];
    gemm_body(Yhi, Ylo, g_WoT_hi, g_WoT_lo, out, nullptr, nullptr, 0,
              blockIdx.y * 128, blockIdx.x * 128, DMODEL, smem);
}

// ------------------------------ attention ----------------------------------
// 128-row q tiles, 8 warps; each warp owns 16 q-rows x ALL 64 v-cols.
// Heavy-first scheduling. Per k-tile the body runs in TWO HALVES
// (cols 0-31 then 32-63): phase-1 S half -> phi/pack -> phase-2 half.
// Halving s_acc and pah/pal live ranges lets ptxas fit 85 regs so
// __launch_bounds__(256,3) gives 3 CTAs/SM (was 2 @ 102 regs).
#define QPITCH   48
#define V_PITCH  144
#define SM_QH    0
#define SM_QL    6144
#define SM_KBUF(b) (12288 + (b) * 6144)     // KH +0, KL +3072
#define SM_VBUF(b) (24576 + (b) * 18432)    // VH +0, VL +9216
#define ATTN_SMEM 61440

__global__ __launch_bounds__(256, 3)
void attn_kernel()
{
    extern __shared__ char sm[];
    const uint32_t sb = smem_u32(sm);

    const int qt = gridDim.x - 1 - blockIdx.x;                   // heavy first
    const int h = blockIdx.y, b = blockIdx.z;
    const int tid = threadIdx.x, lane = tid & 31, wid = tid >> 5;
    const int g = lane >> 2, tg = lane & 3;

    const size_t tok0 = (size_t)(b * L_SEQ + qt * 128);
    const int row_base = qt * 128 + wid * 16;

    auto issue_q = [&]() {
        #pragma unroll
        for (int i = 0; i < 2; i++) {
            int idx = tid + i * 256;
            int arr = idx >> 8, rem = idx & 255, row = rem >> 1, seg = rem & 1;
            uint32_t dst = sb + (arr ? SM_QL : SM_QH) + (uint32_t)row * QPITCH + seg * 16;
            const __nv_bfloat16* src = (arr ? g_Qlo : g_Qhi)
                + (tok0 + row) * NQK + h * FDIM + seg * 8;
            cp_async16(dst, src);
        }
    };
    auto issue_kv = [&](int kt, int buf) {
        const size_t ktok = (size_t)(b * L_SEQ + kt * 64);
        {
            int arr = tid >> 7, rem = tid & 127, row = rem >> 1, seg = rem & 1;
            uint32_t dst = sb + SM_KBUF(buf) + arr * 3072 + (uint32_t)row * QPITCH + seg * 16;
            const __nv_bfloat16* src = (arr ? g_Klo : g_Khi) + (ktok + row) * NQK + h * FDIM + seg * 8;
            cp_async16(dst, src);
        }
        #pragma unroll
        for (int i = 0; i < 4; i++) {
            int idx = tid + i * 256, arr = idx >> 9, rem = idx & 511, row = rem >> 3, seg = rem & 7;
            uint32_t dst = sb + SM_VBUF(buf) + arr * 9216 + (uint32_t)row * V_PITCH + seg * 16;
            const __nv_bfloat16* src = (arr ? g_Vlo : g_Vhi) + (ktok + row) * DMODEL + h * VDIM + seg * 8;
            cp_async16(dst, src);
        }
    };

    issue_q();
    issue_kv(0, 0);
    CP_COMMIT();
    CP_WAIT0();
    __syncthreads();

    uint32_t qh4[4], ql4[4];
    {
        uint32_t off = (uint32_t)(wid * 16 + (lane & 15)) * QPITCH + ((lane >> 4) << 3) * 2;
        ldmatrix_x4(qh4[0], qh4[1], qh4[2], qh4[3], sb + SM_QH + off);
        ldmatrix_x4(ql4[0], ql4[1], ql4[2], ql4[3], sb + SM_QL + off);
    }

    const int ktmax = 2 * qt + 1;
    issue_kv(1, 1);
    CP_COMMIT();

    float acc[8][4];
    #pragma unroll
    for (int j = 0; j < 8; j++)
        #pragma unroll
        for (int q = 0; q < 4; q++) acc[j][q] = 0.f;
    float dden0 = 0.f, dden1 = 0.f;

    for (int kt = 0; kt <= ktmax; kt++) {
        const int buf = kt & 1;
        if (kt > 0) {
            CP_WAIT0();
            __syncthreads();
            if (kt < ktmax) { issue_kv(kt + 1, buf ^ 1); CP_COMMIT(); }
        }

        if (kt * 64 > row_base + 15) continue;

        const uint32_t kh_b = sb + SM_KBUF(buf), kl_b = kh_b + 3072;
        const uint32_t vh_b = sb + SM_VBUF(buf), vl_b = vh_b + 9216;
        const bool need_mask = (kt * 64 + 63 > row_base);

        #pragma unroll
        for (int half = 0; half < 2; half++) {
            // ---- phase 1 (half): S cols [half*32, half*32+32)
            float s_acc[4][4];
            #pragma unroll
            for (int jl = 0; jl < 4; jl++)
                #pragma unroll
                for (int e = 0; e < 4; e++) s_acc[jl][e] = 0.f;

            #pragma unroll
            for (int jj = 0; jj < 2; jj++) {
                const int jp2 = half * 2 + jj;
                uint32_t koff = (uint32_t)(jp2 * 16 + (lane & 7) + ((lane & 16) ? 8 : 0)) * QPITCH
                              + ((lane & 8) ? 16 : 0);
                uint32_t bh4[4], bl4[4];
                ldmatrix_x4(bh4[0], bh4[1], bh4[2], bh4[3], kh_b + koff);
                ldmatrix_x4(bl4[0], bl4[1], bl4[2], bl4[3], kl_b + koff);
                #pragma unroll
                for (int sub = 0; sub < 2; sub++) {
                    const int jl = jj * 2 + sub;
                    mma16816(s_acc[jl], qh4, &bh4[sub * 2]);
                    mma16816(s_acc[jl], qh4, &bl4[sub * 2]);
                    mma16816(s_acc[jl], ql4, &bh4[sub * 2]);
                }
            }

            // ---- phi + mask + denominator + in-register repack (half)
            uint32_t pah[8], pal[8];
            #pragma unroll
            for (int jl = 0; jl < 4; jl++) {
                const int j = half * 4 + jl;
                float ph[4];
                #pragma unroll
                for (int e = 0; e < 4; e++) {
                    float s = s_acc[jl][e] * 0.25f;
                    float phi = fmaf(s, fmaf(0.5f, s, 1.f), 1.f);
                    if (need_mask) {
                        int col = kt * 64 + j * 8 + tg * 2 + (e & 1);
                        int row = row_base + g + ((e >= 2) ? 8 : 0);
                        if (col > row) phi = 0.f;
                    }
                    ph[e] = phi;
                }
                dden0 += ph[0] + ph[1];
                dden1 += ph[2] + ph[3];
                split2(ph[0], ph[1], pah[jl * 2 + 0], pal[jl * 2 + 0]);
                split2(ph[2], ph[3], pah[jl * 2 + 1], pal[jl * 2 + 1]);
            }

            // ---- phase 2 (half): acc += A(16 x 32-half) @ V(32-half x 64)
            #pragma unroll
            for (int ks2 = 0; ks2 < 2; ks2++) {
                const int ksi = half * 2 + ks2;
                const uint32_t* ah = &pah[ks2 * 4];
                const uint32_t* al = &pal[ks2 * 4];
                #pragma unroll
                for (int jp = 0; jp < 4; jp++) {
                    uint32_t voff = (uint32_t)(ksi * 16 + (lane & 15)) * V_PITCH
                                  + (jp * 16 + ((lane >> 4) << 3)) * 2;
                    uint32_t vh4[4], vl4[4];
                    ldmatrix_x4_t(vh4[0], vh4[1], vh4[2], vh4[3], vh_b + voff);
                    ldmatrix_x4_t(vl4[0], vl4[1], vl4[2], vl4[3], vl_b + voff);
                    #pragma unroll
                    for (int sub = 0; sub < 2; sub++) {
                        const int j2 = jp * 2 + sub;
                        mma16816(acc[j2], ah, &vh4[sub * 2]);
                        mma16816(acc[j2], ah, &vl4[sub * 2]);
                        mma16816(acc[j2], al, &vh4[sub * 2]);
                    }
                }
            }
        }
    }

    // ---- denominator: quad shuffle reduction (rows warp-exclusive)
    dden0 += __shfl_xor_sync(0xffffffff, dden0, 1);
    dden0 += __shfl_xor_sync(0xffffffff, dden0, 2);
    dden1 += __shfl_xor_sync(0xffffffff, dden1, 1);
    dden1 += __shfl_xor_sync(0xffffffff, dden1, 2);
    const float z0 = 1.f / (dden0 + 1e-12f);
    const float z1 = 1.f / (dden1 + 1e-12f);

    // ---- epilogue
    {
        const size_t grow0 = tok0 + wid * 16 + g;
        #pragma unroll
        for (int j = 0; j < 8; j++) {
            const int col = h * VDIM + j * 8 + tg * 2;
            uint32_t h0, l0, h1, l1;
            split2(acc[j][0] * z0, acc[j][1] * z0, h0, l0);
            split2(acc[j][2] * z1, acc[j][3] * z1, h1, l1);
            *(uint32_t*)&g_Yhi[grow0 * DMODEL + col]       = h0;
            *(uint32_t*)&g_Ylo[grow0 * DMODEL + col]       = l0;
            *(uint32_t*)&g_Yhi[(grow0 + 8) * DMODEL + col] = h1;
            *(uint32_t*)&g_Ylo[(grow0 + 8) * DMODEL + col] = l1;
        }
    }
}

// ---------------------------------------------------------------------------
extern "C" void kernel_launch(void* const* d_in, const int* in_sizes, int n_in,
                              void* d_out, int out_size)
{
    const float* X  = (const float*)d_in[0];
    const float* Wq = (const float*)d_in[1];
    const float* Wk = (const float*)d_in[2];
    const float* Wv = (const float*)d_in[3];
    const float* Wo = (const float*)d_in[4];
    float* out = (float*)d_out;

    __nv_bfloat16 *Xhi, *Xlo, *Yhi, *Ylo;
    cudaGetSymbolAddress((void**)&Xhi, g_Xhi);
    cudaGetSymbolAddress((void**)&Xlo, g_Xlo);
    cudaGetSymbolAddress((void**)&Yhi, g_Yhi);
    cudaGetSymbolAddress((void**)&Ylo, g_Ylo);

    cudaFuncSetAttribute(gemm_qkv, cudaFuncAttributeMaxDynamicSharedMemorySize, GEMM_SMEM);
    cudaFuncSetAttribute(gemm_out, cudaFuncAttributeMaxDynamicSharedMemorySize, GEMM_SMEM);
    cudaFuncSetAttribute(attn_kernel, cudaFuncAttributeMaxDynamicSharedMemorySize, ATTN_SMEM);

    const int n4 = MTOT * DMODEL / 4;
    split_bf16<<<(n4 + 255) / 256, 256>>>((const float4*)X, (uint2*)Xhi, (uint2*)Xlo, n4);
    transpose_split_all<<<dim3(32, 32, 4), dim3(32, 32)>>>(Wq, Wk, Wv, Wo);

    // fused Q/K/V projections, split bf16 out (384 CTAs, one launch)
    gemm_qkv<<<384, 256, GEMM_SMEM>>>(Xhi, Xlo);
    // causal taylor-exp attention (full HMMA), split bf16 out, heavy-first
    attn_kernel<<<dim3(L_SEQ / 128, NH, B_SZ), 256, ATTN_SMEM>>>();
    // output projection, fp32 out -> d_out
    gemm_out<<<dim3(DMODEL / 128, MTOT / 128), 256, GEMM_SMEM>>>(Yhi, Ylo, out);
}

// round 11
// speedup vs baseline: 2.9086x; 1.1439x over previous
#include <cuda_runtime.h>
#include <cuda_bf16.h>
#include <cuda_fp16.h>
#include <cstdint>

#define B_SZ   2
#define L_SEQ  2048
#define NH     16
#define FDIM   16
#define VDIM   64
#define DMODEL 1024
#define MTOT   (B_SZ * L_SEQ)   // 4096
#define NQK    (NH * FDIM)      // 256

// ------------------------------ scratch (device globals) -------------------
__device__ __half g_Qh16[(size_t)MTOT * NQK];
__device__ __half g_Ql16[(size_t)MTOT * NQK];
__device__ __half g_K16[(size_t)MTOT * NQK];
__device__ __half g_V16[(size_t)MTOT * DMODEL];

__device__ __nv_bfloat16 g_Xhi[(size_t)MTOT * DMODEL];
__device__ __nv_bfloat16 g_Xlo[(size_t)MTOT * DMODEL];
__device__ __nv_bfloat16 g_Yhi[(size_t)MTOT * DMODEL];
__device__ __nv_bfloat16 g_Ylo[(size_t)MTOT * DMODEL];

__device__ __nv_bfloat16 g_WqT_hi[(size_t)NQK * DMODEL];
__device__ __nv_bfloat16 g_WqT_lo[(size_t)NQK * DMODEL];
__device__ __nv_bfloat16 g_WkT_hi[(size_t)NQK * DMODEL];
__device__ __nv_bfloat16 g_WkT_lo[(size_t)NQK * DMODEL];
__device__ __nv_bfloat16 g_WvT_hi[(size_t)DMODEL * DMODEL];
__device__ __nv_bfloat16 g_WvT_lo[(size_t)DMODEL * DMODEL];
__device__ __nv_bfloat16 g_WoT_hi[(size_t)DMODEL * DMODEL];
__device__ __nv_bfloat16 g_WoT_lo[(size_t)DMODEL * DMODEL];

// ------------------------------ helpers ------------------------------------
__device__ __forceinline__ uint32_t smem_u32(const void* p) {
    uint32_t a;
    asm("{ .reg .u64 t; cvta.to.shared.u64 t, %1; cvt.u32.u64 %0, t; }" : "=r"(a) : "l"(p));
    return a;
}
__device__ __forceinline__ void cp_async16(uint32_t s, const void* g) {
    asm volatile("cp.async.cg.shared.global [%0], [%1], 16;" :: "r"(s), "l"(g));
}
#define CP_COMMIT() asm volatile("cp.async.commit_group;" ::: "memory")
#define CP_WAIT0()  asm volatile("cp.async.wait_group 0;" ::: "memory")

__device__ __forceinline__ void ldmatrix_x4(uint32_t& r0, uint32_t& r1, uint32_t& r2, uint32_t& r3,
                                            uint32_t addr) {
    asm volatile("ldmatrix.sync.aligned.m8n8.x4.shared.b16 {%0,%1,%2,%3}, [%4];"
                 : "=r"(r0), "=r"(r1), "=r"(r2), "=r"(r3) : "r"(addr));
}
__device__ __forceinline__ void ldmatrix_x4_t(uint32_t& r0, uint32_t& r1, uint32_t& r2, uint32_t& r3,
                                              uint32_t addr) {
    asm volatile("ldmatrix.sync.aligned.m8n8.x4.trans.shared.b16 {%0,%1,%2,%3}, [%4];"
                 : "=r"(r0), "=r"(r1), "=r"(r2), "=r"(r3) : "r"(addr));
}
__device__ __forceinline__ void mma16816(float* d, const uint32_t* a, const uint32_t* b) {
    asm volatile(
        "mma.sync.aligned.m16n8k16.row.col.f32.bf16.bf16.f32 "
        "{%0,%1,%2,%3},{%4,%5,%6,%7},{%8,%9},{%0,%1,%2,%3};"
        : "+f"(d[0]), "+f"(d[1]), "+f"(d[2]), "+f"(d[3])
        : "r"(a[0]), "r"(a[1]), "r"(a[2]), "r"(a[3]), "r"(b[0]), "r"(b[1]));
}
__device__ __forceinline__ void mma16816h(float* d, const uint32_t* a, const uint32_t* b) {
    asm volatile(
        "mma.sync.aligned.m16n8k16.row.col.f32.f16.f16.f32 "
        "{%0,%1,%2,%3},{%4,%5,%6,%7},{%8,%9},{%0,%1,%2,%3};"
        : "+f"(d[0]), "+f"(d[1]), "+f"(d[2]), "+f"(d[3])
        : "r"(a[0]), "r"(a[1]), "r"(a[2]), "r"(a[3]), "r"(b[0]), "r"(b[1]));
}
// bf16 hi/lo split (hi = RN(y), lo = RN(y - hi)), packed pairwise
__device__ __forceinline__ void split2(float y0, float y1, uint32_t& hi, uint32_t& lo) {
    uint32_t h;
    asm("cvt.rn.bf16x2.f32 %0, %1, %2;" : "=r"(h) : "f"(y1), "f"(y0));
    float f0 = __uint_as_float(h << 16);
    float f1 = __uint_as_float(h & 0xffff0000u);
    asm("cvt.rn.bf16x2.f32 %0, %1, %2;" : "=r"(lo) : "f"(y1 - f1), "f"(y0 - f0));
    hi = h;
}
// fp16 hi/lo split, packed pairwise (low half = y0)
__device__ __forceinline__ void split2h(float y0, float y1, uint32_t& hi, uint32_t& lo) {
    __half2 h = __floats2half2_rn(y0, y1);
    float2 f = __half22float2(h);
    __half2 l = __floats2half2_rn(y0 - f.x, y1 - f.y);
    hi = *(uint32_t*)&h;
    lo = *(uint32_t*)&l;
}

// ------------------------------ prep kernels -------------------------------
__global__ void split_bf16(const float4* __restrict__ x,
                           uint2* __restrict__ hi, uint2* __restrict__ lo, int n4)
{
    int i = blockIdx.x * blockDim.x + threadIdx.x;
    if (i >= n4) return;
    float4 v = x[i];
    uint32_t h0, l0, h1, l1;
    split2(v.x, v.y, h0, l0);
    split2(v.z, v.w, h1, l1);
    hi[i] = make_uint2(h0, h1);
    lo[i] = make_uint2(l0, l1);
}

__global__ void transpose_split_all(const float* __restrict__ Wq, const float* __restrict__ Wk,
                                    const float* __restrict__ Wv, const float* __restrict__ Wo)
{
    __shared__ float t[32][33];
    const int z = blockIdx.z;
    const float* W;
    __nv_bfloat16 *Th, *Tl;
    int N;
    if (z == 0)      { W = Wq; Th = g_WqT_hi; Tl = g_WqT_lo; N = NQK; }
    else if (z == 1) { W = Wk; Th = g_WkT_hi; Tl = g_WkT_lo; N = NQK; }
    else if (z == 2) { W = Wv; Th = g_WvT_hi; Tl = g_WvT_lo; N = DMODEL; }
    else             { W = Wo; Th = g_WoT_hi; Tl = g_WoT_lo; N = DMODEL; }
    const int n0 = blockIdx.x * 32;
    if (n0 >= N) return;
    const int k0 = blockIdx.y * 32;
    t[threadIdx.y][threadIdx.x] = W[(size_t)(k0 + threadIdx.y) * N + n0 + threadIdx.x];
    __syncthreads();
    float v = t[threadIdx.x][threadIdx.y];
    int n = n0 + threadIdx.y, k = k0 + threadIdx.x;
    __nv_bfloat16 hb = __float2bfloat16(v);
    float r = v - __bfloat162float(hb);
    Th[(size_t)n * DMODEL + k] = hb;
    Tl[(size_t)n * DMODEL + k] = __float2bfloat16(r);
}

// ------------------------------ HMMA GEMM body -----------------------------
// modes: 0 = fp32 C, 1 = bf16 hi/lo split, 2 = fp16 hi/lo split, 3 = fp16 single
#define KC        32
#define ROWB      80
#define ARR_BYTES (128 * ROWB)
#define BUF_BYTES (4 * ARR_BYTES)
#define GEMM_SMEM (2 * BUF_BYTES)

__device__ __forceinline__ void gemm_body(
    const __nv_bfloat16* __restrict__ Ahi, const __nv_bfloat16* __restrict__ Alo,
    const __nv_bfloat16* __restrict__ Bhi, const __nv_bfloat16* __restrict__ Blo,
    float* __restrict__ C, void* __restrict__ Oh, void* __restrict__ Ol,
    int mode, int m0, int n0, int Nw, char* smem)
{
    const uint32_t sb = smem_u32(smem);
    const int tid = threadIdx.x, lane = tid & 31, wid = tid >> 5;
    const int warp_m = wid & 3, warp_n = wid >> 2;
    const int nchunk = DMODEL / KC;
    const int frow0 = tid >> 2, fcol = tid & 3;

    auto issue_chunk = [&](int c) {
        const uint32_t base = sb + (c & 1) * BUF_BYTES;
        const int k0 = c * KC;
        #pragma unroll
        for (int i = 0; i < 2; i++) {
            const int row = frow0 + i * 64;
            const uint32_t soff = (uint32_t)row * ROWB + fcol * 16;
            const size_t ga = (size_t)(m0 + row) * DMODEL + k0 + fcol * 8;
            const size_t gb = (size_t)(n0 + row) * DMODEL + k0 + fcol * 8;
            cp_async16(base + soff,                 Ahi + ga);
            cp_async16(base + ARR_BYTES + soff,     Alo + ga);
            cp_async16(base + 2 * ARR_BYTES + soff, Bhi + gb);
            cp_async16(base + 3 * ARR_BYTES + soff, Blo + gb);
        }
    };

    float acc[2][8][4];
    #pragma unroll
    for (int mt = 0; mt < 2; mt++)
        #pragma unroll
        for (int j = 0; j < 8; j++)
            #pragma unroll
            for (int q = 0; q < 4; q++) acc[mt][j][q] = 0.f;

    issue_chunk(0);
    CP_COMMIT();

    const int arow_l = (lane & 15);
    const int akc_l  = (lane >> 4) << 3;
    const int brow_l = (lane & 7) + ((lane & 16) ? 8 : 0);
    const int bkc_l  = (lane & 8) ? 8 : 0;

    for (int c = 0; c < nchunk; c++) {
        CP_WAIT0();
        __syncthreads();
        if (c + 1 < nchunk) { issue_chunk(c + 1); CP_COMMIT(); }

        const uint32_t base = sb + (c & 1) * BUF_BYTES;
        #pragma unroll
        for (int ks = 0; ks < 2; ks++) {
            uint32_t ah[2][4], al[2][4];
            #pragma unroll
            for (int mt = 0; mt < 2; mt++) {
                uint32_t addr = base + (uint32_t)(warp_m * 32 + mt * 16 + arow_l) * ROWB
                              + (ks * 16 + akc_l) * 2;
                ldmatrix_x4(ah[mt][0], ah[mt][1], ah[mt][2], ah[mt][3], addr);
                ldmatrix_x4(al[mt][0], al[mt][1], al[mt][2], al[mt][3], addr + ARR_BYTES);
            }
            #pragma unroll
            for (int jp = 0; jp < 4; jp++) {
                uint32_t baddr = base + 2 * ARR_BYTES
                               + (uint32_t)(warp_n * 64 + jp * 16 + brow_l) * ROWB
                               + (ks * 16 + bkc_l) * 2;
                uint32_t bh[4], bl[4];
                ldmatrix_x4(bh[0], bh[1], bh[2], bh[3], baddr);
                ldmatrix_x4(bl[0], bl[1], bl[2], bl[3], baddr + ARR_BYTES);
                #pragma unroll
                for (int sub = 0; sub < 2; sub++) {
                    const int j = jp * 2 + sub;
                    #pragma unroll
                    for (int mt = 0; mt < 2; mt++) {
                        mma16816(acc[mt][j], ah[mt], &bh[sub * 2]);
                        mma16816(acc[mt][j], ah[mt], &bl[sub * 2]);
                        mma16816(acc[mt][j], al[mt], &bh[sub * 2]);
                    }
                }
            }
        }
    }

    #pragma unroll
    for (int mt = 0; mt < 2; mt++) {
        const int r0 = m0 + warp_m * 32 + mt * 16 + (lane >> 2);
        #pragma unroll
        for (int j = 0; j < 8; j++) {
            const int col = n0 + warp_n * 64 + j * 8 + (lane & 3) * 2;
            const size_t i0 = (size_t)r0 * Nw + col;
            const size_t i1 = (size_t)(r0 + 8) * Nw + col;
            if (mode == 0) {
                *(float2*)&C[i0] = make_float2(acc[mt][j][0], acc[mt][j][1]);
                *(float2*)&C[i1] = make_float2(acc[mt][j][2], acc[mt][j][3]);
            } else if (mode == 1) {
                uint32_t h0, l0, h1, l1;
                split2(acc[mt][j][0], acc[mt][j][1], h0, l0);
                split2(acc[mt][j][2], acc[mt][j][3], h1, l1);
                ((uint32_t*)((__nv_bfloat16*)Oh + i0))[0] = h0;
                ((uint32_t*)((__nv_bfloat16*)Ol + i0))[0] = l0;
                ((uint32_t*)((__nv_bfloat16*)Oh + i1))[0] = h1;
                ((uint32_t*)((__nv_bfloat16*)Ol + i1))[0] = l1;
            } else if (mode == 2) {
                uint32_t h0, l0, h1, l1;
                split2h(acc[mt][j][0], acc[mt][j][1], h0, l0);
                split2h(acc[mt][j][2], acc[mt][j][3], h1, l1);
                ((uint32_t*)((__half*)Oh + i0))[0] = h0;
                ((uint32_t*)((__half*)Ol + i0))[0] = l0;
                ((uint32_t*)((__half*)Oh + i1))[0] = h1;
                ((uint32_t*)((__half*)Ol + i1))[0] = l1;
            } else {
                __half2 p0 = __floats2half2_rn(acc[mt][j][0], acc[mt][j][1]);
                __half2 p1 = __floats2half2_rn(acc[mt][j][2], acc[mt][j][3]);
                ((uint32_t*)((__half*)Oh + i0))[0] = *(uint32_t*)&p0;
                ((uint32_t*)((__half*)Oh + i1))[0] = *(uint32_t*)&p1;
            }
        }
    }
}

// Fused Q/K/V projection: 384 equal-work CTAs (V first).
__global__ __launch_bounds__(256, 2)
void gemm_qkv(const __nv_bfloat16* __restrict__ Xhi, const __nv_bfloat16* __restrict__ Xlo)
{
    extern __shared__ char smem[];
    const int bid = blockIdx.x;
    const __nv_bfloat16 *Bh, *Bl;
    void *oh = nullptr, *ol = nullptr;
    int m0, n0, Nw, mode;
    if (bid < 256) {                       // V: fp16 single
        m0 = (bid >> 3) * 128; n0 = (bid & 7) * 128; Nw = DMODEL; mode = 3;
        Bh = g_WvT_hi; Bl = g_WvT_lo; oh = g_V16;
    } else if (bid < 320) {                // Q: fp16 split
        const int t = bid - 256;
        m0 = (t >> 1) * 128; n0 = (t & 1) * 128; Nw = NQK; mode = 2;
        Bh = g_WqT_hi; Bl = g_WqT_lo; oh = g_Qh16; ol = g_Ql16;
    } else {                               // K: fp16 single
        const int t = bid - 320;
        m0 = (t >> 1) * 128; n0 = (t & 1) * 128; Nw = NQK; mode = 3;
        Bh = g_WkT_hi; Bl = g_WkT_lo; oh = g_K16;
    }
    gemm_body(Xhi, Xlo, Bh, Bl, nullptr, oh, ol, mode, m0, n0, Nw, smem);
}

__global__ __launch_bounds__(256, 2)
void gemm_out(const __nv_bfloat16* __restrict__ Yhi, const __nv_bfloat16* __restrict__ Ylo,
              float* __restrict__ out)
{
    extern __shared__ char smem[];
    gemm_body(Yhi, Ylo, g_WoT_hi, g_WoT_lo, out, nullptr, nullptr, 0,
              blockIdx.y * 128, blockIdx.x * 128, DMODEL, smem);
}

// ------------------------------ attention ----------------------------------
// 128-row q tiles, 8 warps x 16 rows. fp16 path:
//   phase 1: S = (Qh+Ql) . K16  (2 MMAs; Q fp16 split, K fp16 single)
//   phase 2: acc += (Ah+Al) . V16 (2 MMAs; phi fp16 split, V fp16 single)
// k-tiles of 128 keys (double-buffered), heavy-first scheduling.
#define QPITCH   48                          // 16 fp16 = 32B + 16B pad
#define V_PITCH  144                         // 64 fp16 = 128B + 16B pad
#define SM_QH    0
#define SM_QL    6144
#define SM_KBUF(b) (12288 + (b) * 24576)     // 128 rows x 48B = 6144
#define SM_VBUF(b) (12288 + (b) * 24576 + 6144) // 128 rows x 144B = 18432
#define ATTN_SMEM 61440

__global__ __launch_bounds__(256, 3)
void attn_kernel()
{
    extern __shared__ char sm[];
    const uint32_t sb = smem_u32(sm);

    const int qt = gridDim.x - 1 - blockIdx.x;                   // heavy first
    const int h = blockIdx.y, b = blockIdx.z;
    const int tid = threadIdx.x, lane = tid & 31, wid = tid >> 5;
    const int g = lane >> 2, tg = lane & 3;

    const size_t tok0 = (size_t)(b * L_SEQ + qt * 128);
    const int row_base = qt * 128 + wid * 16;

    auto issue_q = [&]() {
        #pragma unroll
        for (int i = 0; i < 2; i++) {        // 512 x 16B
            int idx = tid + i * 256;
            int arr = idx >> 8, rem = idx & 255, row = rem >> 1, seg = rem & 1;
            uint32_t dst = sb + (arr ? SM_QL : SM_QH) + (uint32_t)row * QPITCH + seg * 16;
            const __half* src = (arr ? g_Ql16 : g_Qh16)
                + (tok0 + row) * NQK + h * FDIM + seg * 8;
            cp_async16(dst, src);
        }
    };
    auto issue_kv = [&](int kt, int buf) {
        const size_t ktok = (size_t)(b * L_SEQ + kt * 128);
        {   // K: 256 x 16B, 1 per thread
            int row = tid >> 1, seg = tid & 1;
            uint32_t dst = sb + SM_KBUF(buf) + (uint32_t)row * QPITCH + seg * 16;
            cp_async16(dst, g_K16 + (ktok + row) * NQK + h * FDIM + seg * 8);
        }
        #pragma unroll
        for (int i = 0; i < 4; i++) {        // V: 1024 x 16B
            int idx = tid + i * 256, row = idx >> 3, seg = idx & 7;
            uint32_t dst = sb + SM_VBUF(buf) + (uint32_t)row * V_PITCH + seg * 16;
            cp_async16(dst, g_V16 + (ktok + row) * DMODEL + h * VDIM + seg * 8);
        }
    };

    issue_q();
    issue_kv(0, 0);
    CP_COMMIT();
    CP_WAIT0();
    __syncthreads();

    uint32_t qh4[4], ql4[4];
    {
        uint32_t off = (uint32_t)(wid * 16 + (lane & 15)) * QPITCH + ((lane >> 4) << 3) * 2;
        ldmatrix_x4(qh4[0], qh4[1], qh4[2], qh4[3], sb + SM_QH + off);
        ldmatrix_x4(ql4[0], ql4[1], ql4[2], ql4[3], sb + SM_QL + off);
    }

    const int ktmax = qt;                    // tiles of 128 keys
    if (ktmax >= 1) { issue_kv(1, 1); CP_COMMIT(); }

    float acc[8][4];
    #pragma unroll
    for (int j = 0; j < 8; j++)
        #pragma unroll
        for (int q = 0; q < 4; q++) acc[j][q] = 0.f;
    float dden0 = 0.f, dden1 = 0.f;

    for (int kt = 0; kt <= ktmax; kt++) {
        const int buf = kt & 1;
        if (kt > 0) {
            CP_WAIT0();
            __syncthreads();
            if (kt < ktmax) { issue_kv(kt + 1, buf ^ 1); CP_COMMIT(); }
        }

        if (kt * 128 > row_base + 15) continue;

        const uint32_t kh_b = sb + SM_KBUF(buf);
        const uint32_t vh_b = sb + SM_VBUF(buf);
        const bool need_mask = (kt * 128 + 127 > row_base);

        #pragma unroll
        for (int q4 = 0; q4 < 4; q4++) {     // 32-col quarters of the 128-key tile
            // ---- phase 1: S cols [q4*32, q4*32+32)
            float s_acc[4][4];
            #pragma unroll
            for (int jl = 0; jl < 4; jl++)
                #pragma unroll
                for (int e = 0; e < 4; e++) s_acc[jl][e] = 0.f;

            #pragma unroll
            for (int jj = 0; jj < 2; jj++) {
                uint32_t koff = (uint32_t)(q4 * 32 + jj * 16 + (lane & 7)
                                           + ((lane & 16) ? 8 : 0)) * QPITCH
                              + ((lane & 8) ? 16 : 0);
                uint32_t kh4[4];
                ldmatrix_x4(kh4[0], kh4[1], kh4[2], kh4[3], kh_b + koff);
                #pragma unroll
                for (int sub = 0; sub < 2; sub++) {
                    const int jl = jj * 2 + sub;
                    mma16816h(s_acc[jl], qh4, &kh4[sub * 2]);
                    mma16816h(s_acc[jl], ql4, &kh4[sub * 2]);
                }
            }

            // ---- phi + mask + denominator + fp16 hi/lo repack to A frags
            uint32_t pah[8], pal[8];
            #pragma unroll
            for (int jl = 0; jl < 4; jl++) {
                const int j = q4 * 4 + jl;
                float ph[4];
                #pragma unroll
                for (int e = 0; e < 4; e++) {
                    float s = s_acc[jl][e] * 0.25f;
                    float phi = fmaf(s, fmaf(0.5f, s, 1.f), 1.f);
                    if (need_mask) {
                        int col = kt * 128 + j * 8 + tg * 2 + (e & 1);
                        int row = row_base + g + ((e >= 2) ? 8 : 0);
                        if (col > row) phi = 0.f;
                    }
                    ph[e] = phi;
                }
                dden0 += ph[0] + ph[1];
                dden1 += ph[2] + ph[3];
                split2h(ph[0], ph[1], pah[jl * 2 + 0], pal[jl * 2 + 0]);
                split2h(ph[2], ph[3], pah[jl * 2 + 1], pal[jl * 2 + 1]);
            }

            // ---- phase 2: acc += A(16 x 32) @ V(32 x 64)
            #pragma unroll
            for (int ks2 = 0; ks2 < 2; ks2++) {
                const int ksi = q4 * 2 + ks2;
                const uint32_t* ah = &pah[ks2 * 4];
                const uint32_t* al = &pal[ks2 * 4];
                #pragma unroll
                for (int jp = 0; jp < 4; jp++) {
                    uint32_t voff = (uint32_t)(ksi * 16 + (lane & 15)) * V_PITCH
                                  + (jp * 16 + ((lane >> 4) << 3)) * 2;
                    uint32_t vh4[4];
                    ldmatrix_x4_t(vh4[0], vh4[1], vh4[2], vh4[3], vh_b + voff);
                    #pragma unroll
                    for (int sub = 0; sub < 2; sub++) {
                        const int j2 = jp * 2 + sub;
                        mma16816h(acc[j2], ah, &vh4[sub * 2]);
                        mma16816h(acc[j2], al, &vh4[sub * 2]);
                    }
                }
            }
        }
    }

    // ---- denominator: quad shuffle reduction (rows warp-exclusive)
    dden0 += __shfl_xor_sync(0xffffffff, dden0, 1);
    dden0 += __shfl_xor_sync(0xffffffff, dden0, 2);
    dden1 += __shfl_xor_sync(0xffffffff, dden1, 1);
    dden1 += __shfl_xor_sync(0xffffffff, dden1, 2);
    const float z0 = 1.f / (dden0 + 1e-12f);
    const float z1 = 1.f / (dden1 + 1e-12f);

    // ---- epilogue: Y written as bf16 hi/lo split (out-proj stays 3-pass bf16)
    {
        const size_t grow0 = tok0 + wid * 16 + g;
        #pragma unroll
        for (int j = 0; j < 8; j++) {
            const int col = h * VDIM + j * 8 + tg * 2;
            uint32_t h0, l0, h1, l1;
            split2(acc[j][0] * z0, acc[j][1] * z0, h0, l0);
            split2(acc[j][2] * z1, acc[j][3] * z1, h1, l1);
            *(uint32_t*)&g_Yhi[grow0 * DMODEL + col]       = h0;
            *(uint32_t*)&g_Ylo[grow0 * DMODEL + col]       = l0;
            *(uint32_t*)&g_Yhi[(grow0 + 8) * DMODEL + col] = h1;
            *(uint32_t*)&g_Ylo[(grow0 + 8) * DMODEL + col] = l1;
        }
    }
}

// ---------------------------------------------------------------------------
extern "C" void kernel_launch(void* const* d_in, const int* in_sizes, int n_in,
                              void* d_out, int out_size)
{
    const float* X  = (const float*)d_in[0];
    const float* Wq = (const float*)d_in[1];
    const float* Wk = (const float*)d_in[2];
    const float* Wv = (const float*)d_in[3];
    const float* Wo = (const float*)d_in[4];
    float* out = (float*)d_out;

    __nv_bfloat16 *Xhi, *Xlo, *Yhi, *Ylo;
    cudaGetSymbolAddress((void**)&Xhi, g_Xhi);
    cudaGetSymbolAddress((void**)&Xlo, g_Xlo);
    cudaGetSymbolAddress((void**)&Yhi, g_Yhi);
    cudaGetSymbolAddress((void**)&Ylo, g_Ylo);

    cudaFuncSetAttribute(gemm_qkv, cudaFuncAttributeMaxDynamicSharedMemorySize, GEMM_SMEM);
    cudaFuncSetAttribute(gemm_out, cudaFuncAttributeMaxDynamicSharedMemorySize, GEMM_SMEM);
    cudaFuncSetAttribute(attn_kernel, cudaFuncAttributeMaxDynamicSharedMemorySize, ATTN_SMEM);

    const int n4 = MTOT * DMODEL / 4;
    split_bf16<<<(n4 + 255) / 256, 256>>>((const float4*)X, (uint2*)Xhi, (uint2*)Xlo, n4);
    transpose_split_all<<<dim3(32, 32, 4), dim3(32, 32)>>>(Wq, Wk, Wv, Wo);

    // fused Q/K/V projections (Q: fp16 split, K/V: fp16 single)
    gemm_qkv<<<384, 256, GEMM_SMEM>>>(Xhi, Xlo);
    // causal taylor-exp attention (fp16 2-pass HMMA), bf16-split Y out
    attn_kernel<<<dim3(L_SEQ / 128, NH, B_SZ), 256, ATTN_SMEM>>>();
    // output projection (3-pass bf16), fp32 out -> d_out
    gemm_out<<<dim3(DMODEL / 128, MTOT / 128), 256, GEMM_SMEM>>>(Yhi, Ylo, out);
}

// round 12
// speedup vs baseline: 3.5648x; 1.2256x over previous
#include <cuda_runtime.h>
#include <cuda_bf16.h>
#include <cuda_fp16.h>
#include <cstdint>

#define B_SZ   2
#define L_SEQ  2048
#define NH     16
#define FDIM   16
#define VDIM   64
#define DMODEL 1024
#define MTOT   (B_SZ * L_SEQ)   // 4096
#define NQK    (NH * FDIM)      // 256

// ------------------------------ scratch (device globals) -------------------
__device__ __half g_Qh16[(size_t)MTOT * NQK];
__device__ __half g_Ql16[(size_t)MTOT * NQK];
__device__ __half g_K16[(size_t)MTOT * NQK];
__device__ __half g_V16[(size_t)MTOT * DMODEL];

__device__ __half g_Xh16[(size_t)MTOT * DMODEL];
__device__ __half g_Xl16[(size_t)MTOT * DMODEL];
__device__ __half g_Yh16[(size_t)MTOT * DMODEL];
__device__ __half g_Yl16[(size_t)MTOT * DMODEL];

__device__ __half g_WqT16[(size_t)NQK * DMODEL];
__device__ __half g_WkT16[(size_t)NQK * DMODEL];
__device__ __half g_WvT16[(size_t)DMODEL * DMODEL];
__device__ __half g_WoT16[(size_t)DMODEL * DMODEL];

// ------------------------------ helpers ------------------------------------
__device__ __forceinline__ uint32_t smem_u32(const void* p) {
    uint32_t a;
    asm("{ .reg .u64 t; cvta.to.shared.u64 t, %1; cvt.u32.u64 %0, t; }" : "=r"(a) : "l"(p));
    return a;
}
__device__ __forceinline__ void cp_async16(uint32_t s, const void* g) {
    asm volatile("cp.async.cg.shared.global [%0], [%1], 16;" :: "r"(s), "l"(g));
}
#define CP_COMMIT() asm volatile("cp.async.commit_group;" ::: "memory")
#define CP_WAIT0()  asm volatile("cp.async.wait_group 0;" ::: "memory")

__device__ __forceinline__ void ldmatrix_x4(uint32_t& r0, uint32_t& r1, uint32_t& r2, uint32_t& r3,
                                            uint32_t addr) {
    asm volatile("ldmatrix.sync.aligned.m8n8.x4.shared.b16 {%0,%1,%2,%3}, [%4];"
                 : "=r"(r0), "=r"(r1), "=r"(r2), "=r"(r3) : "r"(addr));
}
__device__ __forceinline__ void ldmatrix_x4_t(uint32_t& r0, uint32_t& r1, uint32_t& r2, uint32_t& r3,
                                              uint32_t addr) {
    asm volatile("ldmatrix.sync.aligned.m8n8.x4.trans.shared.b16 {%0,%1,%2,%3}, [%4];"
                 : "=r"(r0), "=r"(r1), "=r"(r2), "=r"(r3) : "r"(addr));
}
__device__ __forceinline__ void mma16816h(float* d, const uint32_t* a, const uint32_t* b) {
    asm volatile(
        "mma.sync.aligned.m16n8k16.row.col.f32.f16.f16.f32 "
        "{%0,%1,%2,%3},{%4,%5,%6,%7},{%8,%9},{%0,%1,%2,%3};"
        : "+f"(d[0]), "+f"(d[1]), "+f"(d[2]), "+f"(d[3])
        : "r"(a[0]), "r"(a[1]), "r"(a[2]), "r"(a[3]), "r"(b[0]), "r"(b[1]));
}
// fp16 hi/lo split, packed pairwise (low half = y0)
__device__ __forceinline__ void split2h(float y0, float y1, uint32_t& hi, uint32_t& lo) {
    __half2 h = __floats2half2_rn(y0, y1);
    float2 f = __half22float2(h);
    __half2 l = __floats2half2_rn(y0 - f.x, y1 - f.y);
    hi = *(uint32_t*)&h;
    lo = *(uint32_t*)&l;
}

// ------------------------------ prep kernels -------------------------------
__global__ void split_fp16(const float4* __restrict__ x,
                           uint2* __restrict__ hi, uint2* __restrict__ lo, int n4)
{
    int i = blockIdx.x * blockDim.x + threadIdx.x;
    if (i >= n4) return;
    float4 v = x[i];
    uint32_t h0, l0, h1, l1;
    split2h(v.x, v.y, h0, l0);
    split2h(v.z, v.w, h1, l1);
    hi[i] = make_uint2(h0, h1);
    lo[i] = make_uint2(l0, l1);
}

// All 4 weight transposes fused: W (K x N) row-major -> T (N x K) single fp16.
__global__ void transpose_all(const float* __restrict__ Wq, const float* __restrict__ Wk,
                              const float* __restrict__ Wv, const float* __restrict__ Wo)
{
    __shared__ float t[32][33];
    const int z = blockIdx.z;
    const float* W;
    __half* Th;
    int N;
    if (z == 0)      { W = Wq; Th = g_WqT16; N = NQK; }
    else if (z == 1) { W = Wk; Th = g_WkT16; N = NQK; }
    else if (z == 2) { W = Wv; Th = g_WvT16; N = DMODEL; }
    else             { W = Wo; Th = g_WoT16; N = DMODEL; }
    const int n0 = blockIdx.x * 32;
    if (n0 >= N) return;
    const int k0 = blockIdx.y * 32;
    t[threadIdx.y][threadIdx.x] = W[(size_t)(k0 + threadIdx.y) * N + n0 + threadIdx.x];
    __syncthreads();
    float v = t[threadIdx.x][threadIdx.y];
    int n = n0 + threadIdx.y, k = k0 + threadIdx.x;
    Th[(size_t)n * DMODEL + k] = __float2half_rn(v);
}

// ------------------------------ HMMA GEMM body -----------------------------
// C(M x Nw) = (Ahi+Alo)(M x K) @ B16(Nw x K)^T, fp32 acc, 2-pass fp16 split.
// modes: 0 = fp32 C, 2 = fp16 hi/lo split out, 3 = fp16 single out
#define KC        32
#define ROWB      80
#define ARR_BYTES (128 * ROWB)          // 10240
#define BUF_BYTES (3 * ARR_BYTES)       // 30720: Ah, Al, B
#define GEMM_SMEM (2 * BUF_BYTES)       // 61440

__device__ __forceinline__ void gemm_body(
    const __half* __restrict__ Ahi, const __half* __restrict__ Alo,
    const __half* __restrict__ B16,
    float* __restrict__ C, void* __restrict__ Oh, void* __restrict__ Ol,
    int mode, int m0, int n0, int Nw, char* smem)
{
    const uint32_t sb = smem_u32(smem);
    const int tid = threadIdx.x, lane = tid & 31, wid = tid >> 5;
    const int warp_m = wid & 3, warp_n = wid >> 2;
    const int nchunk = DMODEL / KC;
    const int frow0 = tid >> 2, fcol = tid & 3;

    auto issue_chunk = [&](int c) {
        const uint32_t base = sb + (c & 1) * BUF_BYTES;
        const int k0 = c * KC;
        #pragma unroll
        for (int i = 0; i < 2; i++) {
            const int row = frow0 + i * 64;
            const uint32_t soff = (uint32_t)row * ROWB + fcol * 16;
            const size_t ga = (size_t)(m0 + row) * DMODEL + k0 + fcol * 8;
            const size_t gb = (size_t)(n0 + row) * DMODEL + k0 + fcol * 8;
            cp_async16(base + soff,                 Ahi + ga);
            cp_async16(base + ARR_BYTES + soff,     Alo + ga);
            cp_async16(base + 2 * ARR_BYTES + soff, B16 + gb);
        }
    };

    float acc[2][8][4];
    #pragma unroll
    for (int mt = 0; mt < 2; mt++)
        #pragma unroll
        for (int j = 0; j < 8; j++)
            #pragma unroll
            for (int q = 0; q < 4; q++) acc[mt][j][q] = 0.f;

    issue_chunk(0);
    CP_COMMIT();

    const int arow_l = (lane & 15);
    const int akc_l  = (lane >> 4) << 3;
    const int brow_l = (lane & 7) + ((lane & 16) ? 8 : 0);
    const int bkc_l  = (lane & 8) ? 8 : 0;

    for (int c = 0; c < nchunk; c++) {
        CP_WAIT0();
        __syncthreads();
        if (c + 1 < nchunk) { issue_chunk(c + 1); CP_COMMIT(); }

        const uint32_t base = sb + (c & 1) * BUF_BYTES;
        #pragma unroll
        for (int ks = 0; ks < 2; ks++) {
            uint32_t ah[2][4], al[2][4];
            #pragma unroll
            for (int mt = 0; mt < 2; mt++) {
                uint32_t addr = base + (uint32_t)(warp_m * 32 + mt * 16 + arow_l) * ROWB
                              + (ks * 16 + akc_l) * 2;
                ldmatrix_x4(ah[mt][0], ah[mt][1], ah[mt][2], ah[mt][3], addr);
                ldmatrix_x4(al[mt][0], al[mt][1], al[mt][2], al[mt][3], addr + ARR_BYTES);
            }
            #pragma unroll
            for (int jp = 0; jp < 4; jp++) {
                uint32_t baddr = base + 2 * ARR_BYTES
                               + (uint32_t)(warp_n * 64 + jp * 16 + brow_l) * ROWB
                               + (ks * 16 + bkc_l) * 2;
                uint32_t bh[4];
                ldmatrix_x4(bh[0], bh[1], bh[2], bh[3], baddr);
                #pragma unroll
                for (int sub = 0; sub < 2; sub++) {
                    const int j = jp * 2 + sub;
                    #pragma unroll
                    for (int mt = 0; mt < 2; mt++) {
                        mma16816h(acc[mt][j], ah[mt], &bh[sub * 2]);
                        mma16816h(acc[mt][j], al[mt], &bh[sub * 2]);
                    }
                }
            }
        }
    }

    #pragma unroll
    for (int mt = 0; mt < 2; mt++) {
        const int r0 = m0 + warp_m * 32 + mt * 16 + (lane >> 2);
        #pragma unroll
        for (int j = 0; j < 8; j++) {
            const int col = n0 + warp_n * 64 + j * 8 + (lane & 3) * 2;
            const size_t i0 = (size_t)r0 * Nw + col;
            const size_t i1 = (size_t)(r0 + 8) * Nw + col;
            if (mode == 0) {
                *(float2*)&C[i0] = make_float2(acc[mt][j][0], acc[mt][j][1]);
                *(float2*)&C[i1] = make_float2(acc[mt][j][2], acc[mt][j][3]);
            } else if (mode == 2) {
                uint32_t h0, l0, h1, l1;
                split2h(acc[mt][j][0], acc[mt][j][1], h0, l0);
                split2h(acc[mt][j][2], acc[mt][j][3], h1, l1);
                ((uint32_t*)((__half*)Oh + i0))[0] = h0;
                ((uint32_t*)((__half*)Ol + i0))[0] = l0;
                ((uint32_t*)((__half*)Oh + i1))[0] = h1;
                ((uint32_t*)((__half*)Ol + i1))[0] = l1;
            } else {
                __half2 p0 = __floats2half2_rn(acc[mt][j][0], acc[mt][j][1]);
                __half2 p1 = __floats2half2_rn(acc[mt][j][2], acc[mt][j][3]);
                ((uint32_t*)((__half*)Oh + i0))[0] = *(uint32_t*)&p0;
                ((uint32_t*)((__half*)Oh + i1))[0] = *(uint32_t*)&p1;
            }
        }
    }
}

// Fused Q/K/V projection: 384 equal-work CTAs (V first).
__global__ __launch_bounds__(256, 2)
void gemm_qkv(const __half* __restrict__ Xhi, const __half* __restrict__ Xlo)
{
    extern __shared__ char smem[];
    const int bid = blockIdx.x;
    const __half* B16;
    void *oh = nullptr, *ol = nullptr;
    int m0, n0, Nw, mode;
    if (bid < 256) {                       // V: fp16 single
        m0 = (bid >> 3) * 128; n0 = (bid & 7) * 128; Nw = DMODEL; mode = 3;
        B16 = g_WvT16; oh = g_V16;
    } else if (bid < 320) {                // Q: fp16 split
        const int t = bid - 256;
        m0 = (t >> 1) * 128; n0 = (t & 1) * 128; Nw = NQK; mode = 2;
        B16 = g_WqT16; oh = g_Qh16; ol = g_Ql16;
    } else {                               // K: fp16 single
        const int t = bid - 320;
        m0 = (t >> 1) * 128; n0 = (t & 1) * 128; Nw = NQK; mode = 3;
        B16 = g_WkT16; oh = g_K16;
    }
    gemm_body(Xhi, Xlo, B16, nullptr, oh, ol, mode, m0, n0, Nw, smem);
}

__global__ __launch_bounds__(256, 2)
void gemm_out(const __half* __restrict__ Yhi, const __half* __restrict__ Ylo,
              float* __restrict__ out)
{
    extern __shared__ char smem[];
    gemm_body(Yhi, Ylo, g_WoT16, out, nullptr, nullptr, 0,
              blockIdx.y * 128, blockIdx.x * 128, DMODEL, smem);
}

// ------------------------------ attention ----------------------------------
// 128-row q tiles, 8 warps x 16 rows. fp16 path:
//   phase 1: S = (Qh+Ql) . K16  (2 MMAs)
//   phase 2: acc += (Ah+Al) . V16 (2 MMAs)
// k-tiles of 128 keys (double-buffered), heavy-first scheduling.
#define QPITCH   48
#define V_PITCH  144
#define SM_QH    0
#define SM_QL    6144
#define SM_KBUF(b) (12288 + (b) * 24576)
#define SM_VBUF(b) (12288 + (b) * 24576 + 6144)
#define ATTN_SMEM 61440

__global__ __launch_bounds__(256, 3)
void attn_kernel()
{
    extern __shared__ char sm[];
    const uint32_t sb = smem_u32(sm);

    const int qt = gridDim.x - 1 - blockIdx.x;                   // heavy first
    const int h = blockIdx.y, b = blockIdx.z;
    const int tid = threadIdx.x, lane = tid & 31, wid = tid >> 5;
    const int g = lane >> 2, tg = lane & 3;

    const size_t tok0 = (size_t)(b * L_SEQ + qt * 128);
    const int row_base = qt * 128 + wid * 16;

    auto issue_q = [&]() {
        #pragma unroll
        for (int i = 0; i < 2; i++) {
            int idx = tid + i * 256;
            int arr = idx >> 8, rem = idx & 255, row = rem >> 1, seg = rem & 1;
            uint32_t dst = sb + (arr ? SM_QL : SM_QH) + (uint32_t)row * QPITCH + seg * 16;
            const __half* src = (arr ? g_Ql16 : g_Qh16)
                + (tok0 + row) * NQK + h * FDIM + seg * 8;
            cp_async16(dst, src);
        }
    };
    auto issue_kv = [&](int kt, int buf) {
        const size_t ktok = (size_t)(b * L_SEQ + kt * 128);
        {
            int row = tid >> 1, seg = tid & 1;
            uint32_t dst = sb + SM_KBUF(buf) + (uint32_t)row * QPITCH + seg * 16;
            cp_async16(dst, g_K16 + (ktok + row) * NQK + h * FDIM + seg * 8);
        }
        #pragma unroll
        for (int i = 0; i < 4; i++) {
            int idx = tid + i * 256, row = idx >> 3, seg = idx & 7;
            uint32_t dst = sb + SM_VBUF(buf) + (uint32_t)row * V_PITCH + seg * 16;
            cp_async16(dst, g_V16 + (ktok + row) * DMODEL + h * VDIM + seg * 8);
        }
    };

    issue_q();
    issue_kv(0, 0);
    CP_COMMIT();
    CP_WAIT0();
    __syncthreads();

    uint32_t qh4[4], ql4[4];
    {
        uint32_t off = (uint32_t)(wid * 16 + (lane & 15)) * QPITCH + ((lane >> 4) << 3) * 2;
        ldmatrix_x4(qh4[0], qh4[1], qh4[2], qh4[3], sb + SM_QH + off);
        ldmatrix_x4(ql4[0], ql4[1], ql4[2], ql4[3], sb + SM_QL + off);
    }

    const int ktmax = qt;
    if (ktmax >= 1) { issue_kv(1, 1); CP_COMMIT(); }

    float acc[8][4];
    #pragma unroll
    for (int j = 0; j < 8; j++)
        #pragma unroll
        for (int q = 0; q < 4; q++) acc[j][q] = 0.f;
    float dden0 = 0.f, dden1 = 0.f;

    for (int kt = 0; kt <= ktmax; kt++) {
        const int buf = kt & 1;
        if (kt > 0) {
            CP_WAIT0();
            __syncthreads();
            if (kt < ktmax) { issue_kv(kt + 1, buf ^ 1); CP_COMMIT(); }
        }

        if (kt * 128 > row_base + 15) continue;

        const uint32_t kh_b = sb + SM_KBUF(buf);
        const uint32_t vh_b = sb + SM_VBUF(buf);
        const bool need_mask = (kt * 128 + 127 > row_base);

        #pragma unroll
        for (int q4 = 0; q4 < 4; q4++) {
            // ---- phase 1: S cols [q4*32, q4*32+32)
            float s_acc[4][4];
            #pragma unroll
            for (int jl = 0; jl < 4; jl++)
                #pragma unroll
                for (int e = 0; e < 4; e++) s_acc[jl][e] = 0.f;

            #pragma unroll
            for (int jj = 0; jj < 2; jj++) {
                uint32_t koff = (uint32_t)(q4 * 32 + jj * 16 + (lane & 7)
                                           + ((lane & 16) ? 8 : 0)) * QPITCH
                              + ((lane & 8) ? 16 : 0);
                uint32_t kh4[4];
                ldmatrix_x4(kh4[0], kh4[1], kh4[2], kh4[3], kh_b + koff);
                #pragma unroll
                for (int sub = 0; sub < 2; sub++) {
                    const int jl = jj * 2 + sub;
                    mma16816h(s_acc[jl], qh4, &kh4[sub * 2]);
                    mma16816h(s_acc[jl], ql4, &kh4[sub * 2]);
                }
            }

            // ---- phi + mask + denominator + fp16 hi/lo repack
            uint32_t pah[8], pal[8];
            #pragma unroll
            for (int jl = 0; jl < 4; jl++) {
                const int j = q4 * 4 + jl;
                float ph[4];
                #pragma unroll
                for (int e = 0; e < 4; e++) {
                    float s = s_acc[jl][e] * 0.25f;
                    float phi = fmaf(s, fmaf(0.5f, s, 1.f), 1.f);
                    if (need_mask) {
                        int col = kt * 128 + j * 8 + tg * 2 + (e & 1);
                        int row = row_base + g + ((e >= 2) ? 8 : 0);
                        if (col > row) phi = 0.f;
                    }
                    ph[e] = phi;
                }
                dden0 += ph[0] + ph[1];
                dden1 += ph[2] + ph[3];
                split2h(ph[0], ph[1], pah[jl * 2 + 0], pal[jl * 2 + 0]);
                split2h(ph[2], ph[3], pah[jl * 2 + 1], pal[jl * 2 + 1]);
            }

            // ---- phase 2: acc += A(16 x 32) @ V(32 x 64)
            #pragma unroll
            for (int ks2 = 0; ks2 < 2; ks2++) {
                const int ksi = q4 * 2 + ks2;
                const uint32_t* ah = &pah[ks2 * 4];
                const uint32_t* al = &pal[ks2 * 4];
                #pragma unroll
                for (int jp = 0; jp < 4; jp++) {
                    uint32_t voff = (uint32_t)(ksi * 16 + (lane & 15)) * V_PITCH
                                  + (jp * 16 + ((lane >> 4) << 3)) * 2;
                    uint32_t vh4[4];
                    ldmatrix_x4_t(vh4[0], vh4[1], vh4[2], vh4[3], vh_b + voff);
                    #pragma unroll
                    for (int sub = 0; sub < 2; sub++) {
                        const int j2 = jp * 2 + sub;
                        mma16816h(acc[j2], ah, &vh4[sub * 2]);
                        mma16816h(acc[j2], al, &vh4[sub * 2]);
                    }
                }
            }
        }
    }

    // ---- denominator: quad shuffle reduction
    dden0 += __shfl_xor_sync(0xffffffff, dden0, 1);
    dden0 += __shfl_xor_sync(0xffffffff, dden0, 2);
    dden1 += __shfl_xor_sync(0xffffffff, dden1, 1);
    dden1 += __shfl_xor_sync(0xffffffff, dden1, 2);
    const float z0 = 1.f / (dden0 + 1e-12f);
    const float z1 = 1.f / (dden1 + 1e-12f);

    // ---- epilogue: Y written as fp16 hi/lo split (out-proj is 2-pass fp16)
    {
        const size_t grow0 = tok0 + wid * 16 + g;
        #pragma unroll
        for (int j = 0; j < 8; j++) {
            const int col = h * VDIM + j * 8 + tg * 2;
            uint32_t h0, l0, h1, l1;
            split2h(acc[j][0] * z0, acc[j][1] * z0, h0, l0);
            split2h(acc[j][2] * z1, acc[j][3] * z1, h1, l1);
            *(uint32_t*)&g_Yh16[grow0 * DMODEL + col]       = h0;
            *(uint32_t*)&g_Yl16[grow0 * DMODEL + col]       = l0;
            *(uint32_t*)&g_Yh16[(grow0 + 8) * DMODEL + col] = h1;
            *(uint32_t*)&g_Yl16[(grow0 + 8) * DMODEL + col] = l1;
        }
    }
}

// ---------------------------------------------------------------------------
extern "C" void kernel_launch(void* const* d_in, const int* in_sizes, int n_in,
                              void* d_out, int out_size)
{
    const float* X  = (const float*)d_in[0];
    const float* Wq = (const float*)d_in[1];
    const float* Wk = (const float*)d_in[2];
    const float* Wv = (const float*)d_in[3];
    const float* Wo = (const float*)d_in[4];
    float* out = (float*)d_out;

    __half *Xhi, *Xlo, *Yhi, *Ylo;
    cudaGetSymbolAddress((void**)&Xhi, g_Xh16);
    cudaGetSymbolAddress((void**)&Xlo, g_Xl16);
    cudaGetSymbolAddress((void**)&Yhi, g_Yh16);
    cudaGetSymbolAddress((void**)&Ylo, g_Yl16);

    cudaFuncSetAttribute(gemm_qkv, cudaFuncAttributeMaxDynamicSharedMemorySize, GEMM_SMEM);
    cudaFuncSetAttribute(gemm_out, cudaFuncAttributeMaxDynamicSharedMemorySize, GEMM_SMEM);
    cudaFuncSetAttribute(attn_kernel, cudaFuncAttributeMaxDynamicSharedMemorySize, ATTN_SMEM);

    const int n4 = MTOT * DMODEL / 4;
    split_fp16<<<(n4 + 255) / 256, 256>>>((const float4*)X, (uint2*)Xhi, (uint2*)Xlo, n4);
    transpose_all<<<dim3(32, 32, 4), dim3(32, 32)>>>(Wq, Wk, Wv, Wo);

    // fused Q/K/V projections, 2-pass fp16 (Q split out, K/V single out)
    gemm_qkv<<<384, 256, GEMM_SMEM>>>(Xhi, Xlo);
    // causal taylor-exp attention (fp16 2-pass HMMA), fp16-split Y out
    attn_kernel<<<dim3(L_SEQ / 128, NH, B_SZ), 256, ATTN_SMEM>>>();
    // output projection, 2-pass fp16, fp32 out -> d_out
    gemm_out<<<dim3(DMODEL / 128, MTOT / 128), 256, GEMM_SMEM>>>(Yhi, Ylo, out);
}

// round 13
// speedup vs baseline: 4.0051x; 1.1235x over previous
#include <cuda_runtime.h>
#include <cuda_bf16.h>
#include <cuda_fp16.h>
#include <cstdint>

#define B_SZ   2
#define L_SEQ  2048
#define NH     16
#define FDIM   16
#define VDIM   64
#define DMODEL 1024
#define MTOT   (B_SZ * L_SEQ)   // 4096
#define NQK    (NH * FDIM)      // 256

// ------------------------------ scratch (device globals) -------------------
__device__ __half g_Qh16[(size_t)MTOT * NQK];
__device__ __half g_Ql16[(size_t)MTOT * NQK];
__device__ __half g_K16[(size_t)MTOT * NQK];
__device__ __half g_V16[(size_t)MTOT * DMODEL];

__device__ __half g_Xh16[(size_t)MTOT * DMODEL];
__device__ __half g_Xl16[(size_t)MTOT * DMODEL];
__device__ __half g_Yh16[(size_t)MTOT * DMODEL];
__device__ __half g_Yl16[(size_t)MTOT * DMODEL];

__device__ __half g_WqT16[(size_t)NQK * DMODEL];
__device__ __half g_WkT16[(size_t)NQK * DMODEL];
__device__ __half g_WvT16[(size_t)DMODEL * DMODEL];
__device__ __half g_WoT16[(size_t)DMODEL * DMODEL];

// ------------------------------ helpers ------------------------------------
__device__ __forceinline__ uint32_t smem_u32(const void* p) {
    uint32_t a;
    asm("{ .reg .u64 t; cvta.to.shared.u64 t, %1; cvt.u32.u64 %0, t; }" : "=r"(a) : "l"(p));
    return a;
}
__device__ __forceinline__ void cp_async16(uint32_t s, const void* g) {
    asm volatile("cp.async.cg.shared.global [%0], [%1], 16;" :: "r"(s), "l"(g));
}
#define CP_COMMIT() asm volatile("cp.async.commit_group;" ::: "memory")
#define CP_WAIT0()  asm volatile("cp.async.wait_group 0;" ::: "memory")

__device__ __forceinline__ void ldmatrix_x4(uint32_t& r0, uint32_t& r1, uint32_t& r2, uint32_t& r3,
                                            uint32_t addr) {
    asm volatile("ldmatrix.sync.aligned.m8n8.x4.shared.b16 {%0,%1,%2,%3}, [%4];"
                 : "=r"(r0), "=r"(r1), "=r"(r2), "=r"(r3) : "r"(addr));
}
__device__ __forceinline__ void ldmatrix_x4_t(uint32_t& r0, uint32_t& r1, uint32_t& r2, uint32_t& r3,
                                              uint32_t addr) {
    asm volatile("ldmatrix.sync.aligned.m8n8.x4.trans.shared.b16 {%0,%1,%2,%3}, [%4];"
                 : "=r"(r0), "=r"(r1), "=r"(r2), "=r"(r3) : "r"(addr));
}
__device__ __forceinline__ void mma16816h(float* d, const uint32_t* a, const uint32_t* b) {
    asm volatile(
        "mma.sync.aligned.m16n8k16.row.col.f32.f16.f16.f32 "
        "{%0,%1,%2,%3},{%4,%5,%6,%7},{%8,%9},{%0,%1,%2,%3};"
        : "+f"(d[0]), "+f"(d[1]), "+f"(d[2]), "+f"(d[3])
        : "r"(a[0]), "r"(a[1]), "r"(a[2]), "r"(a[3]), "r"(b[0]), "r"(b[1]));
}
// fp16 hi/lo split, packed pairwise (low half = y0)
__device__ __forceinline__ void split2h(float y0, float y1, uint32_t& hi, uint32_t& lo) {
    __half2 h = __floats2half2_rn(y0, y1);
    float2 f = __half22float2(h);
    __half2 l = __floats2half2_rn(y0 - f.x, y1 - f.y);
    hi = *(uint32_t*)&h;
    lo = *(uint32_t*)&l;
}
__device__ __forceinline__ uint32_t pack2h(float y0, float y1) {
    __half2 h = __floats2half2_rn(y0, y1);
    return *(uint32_t*)&h;
}

// ------------------------------ prep kernels -------------------------------
__global__ void split_fp16(const float4* __restrict__ x,
                           uint2* __restrict__ hi, uint2* __restrict__ lo, int n4)
{
    int i = blockIdx.x * blockDim.x + threadIdx.x;
    if (i >= n4) return;
    float4 v = x[i];
    uint32_t h0, l0, h1, l1;
    split2h(v.x, v.y, h0, l0);
    split2h(v.z, v.w, h1, l1);
    hi[i] = make_uint2(h0, h1);
    lo[i] = make_uint2(l0, l1);
}

// All 4 weight transposes fused: W (K x N) row-major -> T (N x K) single fp16.
__global__ void transpose_all(const float* __restrict__ Wq, const float* __restrict__ Wk,
                              const float* __restrict__ Wv, const float* __restrict__ Wo)
{
    __shared__ float t[32][33];
    const int z = blockIdx.z;
    const float* W;
    __half* Th;
    int N;
    if (z == 0)      { W = Wq; Th = g_WqT16; N = NQK; }
    else if (z == 1) { W = Wk; Th = g_WkT16; N = NQK; }
    else if (z == 2) { W = Wv; Th = g_WvT16; N = DMODEL; }
    else             { W = Wo; Th = g_WoT16; N = DMODEL; }
    const int n0 = blockIdx.x * 32;
    if (n0 >= N) return;
    const int k0 = blockIdx.y * 32;
    t[threadIdx.y][threadIdx.x] = W[(size_t)(k0 + threadIdx.y) * N + n0 + threadIdx.x];
    __syncthreads();
    float v = t[threadIdx.x][threadIdx.y];
    int n = n0 + threadIdx.y, k = k0 + threadIdx.x;
    Th[(size_t)n * DMODEL + k] = __float2half_rn(v);
}

// ------------------------------ HMMA GEMM body -----------------------------
// C(M x Nw) = (Ahi+Alo)(M x K) @ B16(Nw x K)^T, fp32 acc, 2-pass fp16 split.
// modes: 0 = fp32 C, 2 = fp16 hi/lo split out, 3 = fp16 single out
#define KC        32
#define ROWB      80
#define ARR_BYTES (128 * ROWB)          // 10240
#define BUF_BYTES (3 * ARR_BYTES)       // 30720: Ah, Al, B
#define GEMM_SMEM (2 * BUF_BYTES)       // 61440

__device__ __forceinline__ void gemm_body(
    const __half* __restrict__ Ahi, const __half* __restrict__ Alo,
    const __half* __restrict__ B16,
    float* __restrict__ C, void* __restrict__ Oh, void* __restrict__ Ol,
    int mode, int m0, int n0, int Nw, char* smem)
{
    const uint32_t sb = smem_u32(smem);
    const int tid = threadIdx.x, lane = tid & 31, wid = tid >> 5;
    const int warp_m = wid & 3, warp_n = wid >> 2;
    const int nchunk = DMODEL / KC;
    const int frow0 = tid >> 2, fcol = tid & 3;

    auto issue_chunk = [&](int c) {
        const uint32_t base = sb + (c & 1) * BUF_BYTES;
        const int k0 = c * KC;
        #pragma unroll
        for (int i = 0; i < 2; i++) {
            const int row = frow0 + i * 64;
            const uint32_t soff = (uint32_t)row * ROWB + fcol * 16;
            const size_t ga = (size_t)(m0 + row) * DMODEL + k0 + fcol * 8;
            const size_t gb = (size_t)(n0 + row) * DMODEL + k0 + fcol * 8;
            cp_async16(base + soff,                 Ahi + ga);
            cp_async16(base + ARR_BYTES + soff,     Alo + ga);
            cp_async16(base + 2 * ARR_BYTES + soff, B16 + gb);
        }
    };

    float acc[2][8][4];
    #pragma unroll
    for (int mt = 0; mt < 2; mt++)
        #pragma unroll
        for (int j = 0; j < 8; j++)
            #pragma unroll
            for (int q = 0; q < 4; q++) acc[mt][j][q] = 0.f;

    issue_chunk(0);
    CP_COMMIT();

    const int arow_l = (lane & 15);
    const int akc_l  = (lane >> 4) << 3;
    const int brow_l = (lane & 7) + ((lane & 16) ? 8 : 0);
    const int bkc_l  = (lane & 8) ? 8 : 0;

    for (int c = 0; c < nchunk; c++) {
        CP_WAIT0();
        __syncthreads();
        if (c + 1 < nchunk) { issue_chunk(c + 1); CP_COMMIT(); }

        const uint32_t base = sb + (c & 1) * BUF_BYTES;
        #pragma unroll
        for (int ks = 0; ks < 2; ks++) {
            uint32_t ah[2][4], al[2][4];
            #pragma unroll
            for (int mt = 0; mt < 2; mt++) {
                uint32_t addr = base + (uint32_t)(warp_m * 32 + mt * 16 + arow_l) * ROWB
                              + (ks * 16 + akc_l) * 2;
                ldmatrix_x4(ah[mt][0], ah[mt][1], ah[mt][2], ah[mt][3], addr);
                ldmatrix_x4(al[mt][0], al[mt][1], al[mt][2], al[mt][3], addr + ARR_BYTES);
            }
            #pragma unroll
            for (int jp = 0; jp < 4; jp++) {
                uint32_t baddr = base + 2 * ARR_BYTES
                               + (uint32_t)(warp_n * 64 + jp * 16 + brow_l) * ROWB
                               + (ks * 16 + bkc_l) * 2;
                uint32_t bh[4];
                ldmatrix_x4(bh[0], bh[1], bh[2], bh[3], baddr);
                #pragma unroll
                for (int sub = 0; sub < 2; sub++) {
                    const int j = jp * 2 + sub;
                    #pragma unroll
                    for (int mt = 0; mt < 2; mt++) {
                        mma16816h(acc[mt][j], ah[mt], &bh[sub * 2]);
                        mma16816h(acc[mt][j], al[mt], &bh[sub * 2]);
                    }
                }
            }
        }
    }

    #pragma unroll
    for (int mt = 0; mt < 2; mt++) {
        const int r0 = m0 + warp_m * 32 + mt * 16 + (lane >> 2);
        #pragma unroll
        for (int j = 0; j < 8; j++) {
            const int col = n0 + warp_n * 64 + j * 8 + (lane & 3) * 2;
            const size_t i0 = (size_t)r0 * Nw + col;
            const size_t i1 = (size_t)(r0 + 8) * Nw + col;
            if (mode == 0) {
                *(float2*)&C[i0] = make_float2(acc[mt][j][0], acc[mt][j][1]);
                *(float2*)&C[i1] = make_float2(acc[mt][j][2], acc[mt][j][3]);
            } else if (mode == 2) {
                uint32_t h0, l0, h1, l1;
                split2h(acc[mt][j][0], acc[mt][j][1], h0, l0);
                split2h(acc[mt][j][2], acc[mt][j][3], h1, l1);
                ((uint32_t*)((__half*)Oh + i0))[0] = h0;
                ((uint32_t*)((__half*)Ol + i0))[0] = l0;
                ((uint32_t*)((__half*)Oh + i1))[0] = h1;
                ((uint32_t*)((__half*)Ol + i1))[0] = l1;
            } else {
                ((uint32_t*)((__half*)Oh + i0))[0] = pack2h(acc[mt][j][0], acc[mt][j][1]);
                ((uint32_t*)((__half*)Oh + i1))[0] = pack2h(acc[mt][j][2], acc[mt][j][3]);
            }
        }
    }
}

// Fused Q/K/V projection: 384 equal-work CTAs (V first).
__global__ __launch_bounds__(256, 2)
void gemm_qkv(const __half* __restrict__ Xhi, const __half* __restrict__ Xlo)
{
    extern __shared__ char smem[];
    const int bid = blockIdx.x;
    const __half* B16;
    void *oh = nullptr, *ol = nullptr;
    int m0, n0, Nw, mode;
    if (bid < 256) {                       // V: fp16 single
        m0 = (bid >> 3) * 128; n0 = (bid & 7) * 128; Nw = DMODEL; mode = 3;
        B16 = g_WvT16; oh = g_V16;
    } else if (bid < 320) {                // Q: fp16 split
        const int t = bid - 256;
        m0 = (t >> 1) * 128; n0 = (t & 1) * 128; Nw = NQK; mode = 2;
        B16 = g_WqT16; oh = g_Qh16; ol = g_Ql16;
    } else {                               // K: fp16 single
        const int t = bid - 320;
        m0 = (t >> 1) * 128; n0 = (t & 1) * 128; Nw = NQK; mode = 3;
        B16 = g_WkT16; oh = g_K16;
    }
    gemm_body(Xhi, Xlo, B16, nullptr, oh, ol, mode, m0, n0, Nw, smem);
}

__global__ __launch_bounds__(256, 2)
void gemm_out(const __half* __restrict__ Yhi, const __half* __restrict__ Ylo,
              float* __restrict__ out)
{
    extern __shared__ char smem[];
    gemm_body(Yhi, Ylo, g_WoT16, out, nullptr, nullptr, 0,
              blockIdx.y * 128, blockIdx.x * 128, DMODEL, smem);
}

// ------------------------------ attention ----------------------------------
// 128-row q tiles, 8 warps x 16 rows. fp16 path:
//   phase 1: S = (Qh+Ql) . K16   (2 MMA passes; Q fp16 split)
//   phase 2: acc += A16 . V16    (1 MMA pass; phi single fp16 — R13)
// Denominator keeps exact fp32 phi sums. k-tiles of 128 keys, double-buffered.
#define QPITCH   48
#define V_PITCH  144
#define SM_QH    0
#define SM_QL    6144
#define SM_KBUF(b) (12288 + (b) * 24576)
#define SM_VBUF(b) (12288 + (b) * 24576 + 6144)
#define ATTN_SMEM 61440

__global__ __launch_bounds__(256, 3)
void attn_kernel()
{
    extern __shared__ char sm[];
    const uint32_t sb = smem_u32(sm);

    const int qt = gridDim.x - 1 - blockIdx.x;                   // heavy first
    const int h = blockIdx.y, b = blockIdx.z;
    const int tid = threadIdx.x, lane = tid & 31, wid = tid >> 5;
    const int g = lane >> 2, tg = lane & 3;

    const size_t tok0 = (size_t)(b * L_SEQ + qt * 128);
    const int row_base = qt * 128 + wid * 16;

    auto issue_q = [&]() {
        #pragma unroll
        for (int i = 0; i < 2; i++) {
            int idx = tid + i * 256;
            int arr = idx >> 8, rem = idx & 255, row = rem >> 1, seg = rem & 1;
            uint32_t dst = sb + (arr ? SM_QL : SM_QH) + (uint32_t)row * QPITCH + seg * 16;
            const __half* src = (arr ? g_Ql16 : g_Qh16)
                + (tok0 + row) * NQK + h * FDIM + seg * 8;
            cp_async16(dst, src);
        }
    };
    auto issue_kv = [&](int kt, int buf) {
        const size_t ktok = (size_t)(b * L_SEQ + kt * 128);
        {
            int row = tid >> 1, seg = tid & 1;
            uint32_t dst = sb + SM_KBUF(buf) + (uint32_t)row * QPITCH + seg * 16;
            cp_async16(dst, g_K16 + (ktok + row) * NQK + h * FDIM + seg * 8);
        }
        #pragma unroll
        for (int i = 0; i < 4; i++) {
            int idx = tid + i * 256, row = idx >> 3, seg = idx & 7;
            uint32_t dst = sb + SM_VBUF(buf) + (uint32_t)row * V_PITCH + seg * 16;
            cp_async16(dst, g_V16 + (ktok + row) * DMODEL + h * VDIM + seg * 8);
        }
    };

    issue_q();
    issue_kv(0, 0);
    CP_COMMIT();
    CP_WAIT0();
    __syncthreads();

    uint32_t qh4[4], ql4[4];
    {
        uint32_t off = (uint32_t)(wid * 16 + (lane & 15)) * QPITCH + ((lane >> 4) << 3) * 2;
        ldmatrix_x4(qh4[0], qh4[1], qh4[2], qh4[3], sb + SM_QH + off);
        ldmatrix_x4(ql4[0], ql4[1], ql4[2], ql4[3], sb + SM_QL + off);
    }

    const int ktmax = qt;
    if (ktmax >= 1) { issue_kv(1, 1); CP_COMMIT(); }

    float acc[8][4];
    #pragma unroll
    for (int j = 0; j < 8; j++)
        #pragma unroll
        for (int q = 0; q < 4; q++) acc[j][q] = 0.f;
    float dden0 = 0.f, dden1 = 0.f;

    for (int kt = 0; kt <= ktmax; kt++) {
        const int buf = kt & 1;
        if (kt > 0) {
            CP_WAIT0();
            __syncthreads();
            if (kt < ktmax) { issue_kv(kt + 1, buf ^ 1); CP_COMMIT(); }
        }

        if (kt * 128 > row_base + 15) continue;

        const uint32_t kh_b = sb + SM_KBUF(buf);
        const uint32_t vh_b = sb + SM_VBUF(buf);
        const bool need_mask = (kt * 128 + 127 > row_base);

        #pragma unroll
        for (int q4 = 0; q4 < 4; q4++) {
            // ---- phase 1: S cols [q4*32, q4*32+32)
            float s_acc[4][4];
            #pragma unroll
            for (int jl = 0; jl < 4; jl++)
                #pragma unroll
                for (int e = 0; e < 4; e++) s_acc[jl][e] = 0.f;

            #pragma unroll
            for (int jj = 0; jj < 2; jj++) {
                uint32_t koff = (uint32_t)(q4 * 32 + jj * 16 + (lane & 7)
                                           + ((lane & 16) ? 8 : 0)) * QPITCH
                              + ((lane & 8) ? 16 : 0);
                uint32_t kh4[4];
                ldmatrix_x4(kh4[0], kh4[1], kh4[2], kh4[3], kh_b + koff);
                #pragma unroll
                for (int sub = 0; sub < 2; sub++) {
                    const int jl = jj * 2 + sub;
                    mma16816h(s_acc[jl], qh4, &kh4[sub * 2]);
                    mma16816h(s_acc[jl], ql4, &kh4[sub * 2]);
                }
            }

            // ---- phi + mask + denominator; pack phi single fp16 (A frags)
            uint32_t pah[8];
            #pragma unroll
            for (int jl = 0; jl < 4; jl++) {
                const int j = q4 * 4 + jl;
                float ph[4];
                #pragma unroll
                for (int e = 0; e < 4; e++) {
                    float s = s_acc[jl][e] * 0.25f;
                    float phi = fmaf(s, fmaf(0.5f, s, 1.f), 1.f);
                    if (need_mask) {
                        int col = kt * 128 + j * 8 + tg * 2 + (e & 1);
                        int row = row_base + g + ((e >= 2) ? 8 : 0);
                        if (col > row) phi = 0.f;
                    }
                    ph[e] = phi;
                }
                dden0 += ph[0] + ph[1];
                dden1 += ph[2] + ph[3];
                pah[jl * 2 + 0] = pack2h(ph[0], ph[1]);
                pah[jl * 2 + 1] = pack2h(ph[2], ph[3]);
            }

            // ---- phase 2 (single pass): acc += A(16 x 32) @ V(32 x 64)
            #pragma unroll
            for (int ks2 = 0; ks2 < 2; ks2++) {
                const int ksi = q4 * 2 + ks2;
                const uint32_t* ah = &pah[ks2 * 4];
                #pragma unroll
                for (int jp = 0; jp < 4; jp++) {
                    uint32_t voff = (uint32_t)(ksi * 16 + (lane & 15)) * V_PITCH
                                  + (jp * 16 + ((lane >> 4) << 3)) * 2;
                    uint32_t vh4[4];
                    ldmatrix_x4_t(vh4[0], vh4[1], vh4[2], vh4[3], vh_b + voff);
                    mma16816h(acc[jp * 2 + 0], ah, &vh4[0]);
                    mma16816h(acc[jp * 2 + 1], ah, &vh4[2]);
                }
            }
        }
    }

    // ---- denominator: quad shuffle reduction
    dden0 += __shfl_xor_sync(0xffffffff, dden0, 1);
    dden0 += __shfl_xor_sync(0xffffffff, dden0, 2);
    dden1 += __shfl_xor_sync(0xffffffff, dden1, 1);
    dden1 += __shfl_xor_sync(0xffffffff, dden1, 2);
    const float z0 = 1.f / (dden0 + 1e-12f);
    const float z1 = 1.f / (dden1 + 1e-12f);

    // ---- epilogue: Y written as fp16 hi/lo split (out-proj is 2-pass fp16)
    {
        const size_t grow0 = tok0 + wid * 16 + g;
        #pragma unroll
        for (int j = 0; j < 8; j++) {
            const int col = h * VDIM + j * 8 + tg * 2;
            uint32_t h0, l0, h1, l1;
            split2h(acc[j][0] * z0, acc[j][1] * z0, h0, l0);
            split2h(acc[j][2] * z1, acc[j][3] * z1, h1, l1);
            *(uint32_t*)&g_Yh16[grow0 * DMODEL + col]       = h0;
            *(uint32_t*)&g_Yl16[grow0 * DMODEL + col]       = l0;
            *(uint32_t*)&g_Yh16[(grow0 + 8) * DMODEL + col] = h1;
            *(uint32_t*)&g_Yl16[(grow0 + 8) * DMODEL + col] = l1;
        }
    }
}

// ---------------------------------------------------------------------------
extern "C" void kernel_launch(void* const* d_in, const int* in_sizes, int n_in,
                              void* d_out, int out_size)
{
    const float* X  = (const float*)d_in[0];
    const float* Wq = (const float*)d_in[1];
    const float* Wk = (const float*)d_in[2];
    const float* Wv = (const float*)d_in[3];
    const float* Wo = (const float*)d_in[4];
    float* out = (float*)d_out;

    __half *Xhi, *Xlo, *Yhi, *Ylo;
    cudaGetSymbolAddress((void**)&Xhi, g_Xh16);
    cudaGetSymbolAddress((void**)&Xlo, g_Xl16);
    cudaGetSymbolAddress((void**)&Yhi, g_Yh16);
    cudaGetSymbolAddress((void**)&Ylo, g_Yl16);

    cudaFuncSetAttribute(gemm_qkv, cudaFuncAttributeMaxDynamicSharedMemorySize, GEMM_SMEM);
    cudaFuncSetAttribute(gemm_out, cudaFuncAttributeMaxDynamicSharedMemorySize, GEMM_SMEM);
    cudaFuncSetAttribute(attn_kernel, cudaFuncAttributeMaxDynamicSharedMemorySize, ATTN_SMEM);

    const int n4 = MTOT * DMODEL / 4;
    split_fp16<<<(n4 + 255) / 256, 256>>>((const float4*)X, (uint2*)Xhi, (uint2*)Xlo, n4);
    transpose_all<<<dim3(32, 32, 4), dim3(32, 32)>>>(Wq, Wk, Wv, Wo);

    // fused Q/K/V projections, 2-pass fp16 (Q split out, K/V single out)
    gemm_qkv<<<384, 256, GEMM_SMEM>>>(Xhi, Xlo);
    // causal taylor-exp attention (phase1 2-pass, phase2 1-pass fp16)
    attn_kernel<<<dim3(L_SEQ / 128, NH, B_SZ), 256, ATTN_SMEM>>>();
    // output projection, 2-pass fp16, fp32 out -> d_out
    gemm_out<<<dim3(DMODEL / 128, MTOT / 128), 256, GEMM_SMEM>>>(Yhi, Ylo, out);
}

// round 14
// speedup vs baseline: 4.0788x; 1.0184x over previous
#include <cuda_runtime.h>
#include <cuda_bf16.h>
#include <cuda_fp16.h>
#include <cstdint>

#define B_SZ   2
#define L_SEQ  2048
#define NH     16
#define FDIM   16
#define VDIM   64
#define DMODEL 1024
#define MTOT   (B_SZ * L_SEQ)   // 4096
#define NQK    (NH * FDIM)      // 256

// ------------------------------ scratch (device globals) -------------------
__device__ __half g_Qh16[(size_t)MTOT * NQK];
__device__ __half g_Ql16[(size_t)MTOT * NQK];
__device__ __half g_K16[(size_t)MTOT * NQK];
__device__ __half g_V16[(size_t)MTOT * DMODEL];

__device__ __half g_Xh16[(size_t)MTOT * DMODEL];
__device__ __half g_Xl16[(size_t)MTOT * DMODEL];
__device__ __half g_Yh16[(size_t)MTOT * DMODEL];
__device__ __half g_Yl16[(size_t)MTOT * DMODEL];

__device__ __half g_WqT16[(size_t)NQK * DMODEL];
__device__ __half g_WkT16[(size_t)NQK * DMODEL];
__device__ __half g_WvT16[(size_t)DMODEL * DMODEL];
__device__ __half g_WoT16[(size_t)DMODEL * DMODEL];

// ------------------------------ helpers ------------------------------------
__device__ __forceinline__ uint32_t smem_u32(const void* p) {
    uint32_t a;
    asm("{ .reg .u64 t; cvta.to.shared.u64 t, %1; cvt.u32.u64 %0, t; }" : "=r"(a) : "l"(p));
    return a;
}
__device__ __forceinline__ void cp_async16(uint32_t s, const void* g) {
    asm volatile("cp.async.cg.shared.global [%0], [%1], 16;" :: "r"(s), "l"(g));
}
#define CP_COMMIT() asm volatile("cp.async.commit_group;" ::: "memory")
#define CP_WAIT0()  asm volatile("cp.async.wait_group 0;" ::: "memory")

__device__ __forceinline__ void ldmatrix_x4(uint32_t& r0, uint32_t& r1, uint32_t& r2, uint32_t& r3,
                                            uint32_t addr) {
    asm volatile("ldmatrix.sync.aligned.m8n8.x4.shared.b16 {%0,%1,%2,%3}, [%4];"
                 : "=r"(r0), "=r"(r1), "=r"(r2), "=r"(r3) : "r"(addr));
}
__device__ __forceinline__ void ldmatrix_x4_t(uint32_t& r0, uint32_t& r1, uint32_t& r2, uint32_t& r3,
                                              uint32_t addr) {
    asm volatile("ldmatrix.sync.aligned.m8n8.x4.trans.shared.b16 {%0,%1,%2,%3}, [%4];"
                 : "=r"(r0), "=r"(r1), "=r"(r2), "=r"(r3) : "r"(addr));
}
__device__ __forceinline__ void mma16816h(float* d, const uint32_t* a, const uint32_t* b) {
    asm volatile(
        "mma.sync.aligned.m16n8k16.row.col.f32.f16.f16.f32 "
        "{%0,%1,%2,%3},{%4,%5,%6,%7},{%8,%9},{%0,%1,%2,%3};"
        : "+f"(d[0]), "+f"(d[1]), "+f"(d[2]), "+f"(d[3])
        : "r"(a[0]), "r"(a[1]), "r"(a[2]), "r"(a[3]), "r"(b[0]), "r"(b[1]));
}
// fp16 hi/lo split, packed pairwise (low half = y0)
__device__ __forceinline__ void split2h(float y0, float y1, uint32_t& hi, uint32_t& lo) {
    __half2 h = __floats2half2_rn(y0, y1);
    float2 f = __half22float2(h);
    __half2 l = __floats2half2_rn(y0 - f.x, y1 - f.y);
    hi = *(uint32_t*)&h;
    lo = *(uint32_t*)&l;
}
__device__ __forceinline__ uint32_t pack2h(float y0, float y1) {
    __half2 h = __floats2half2_rn(y0, y1);
    return *(uint32_t*)&h;
}

// ------------------------------ prep kernels -------------------------------
__global__ void split_fp16(const float4* __restrict__ x,
                           uint2* __restrict__ hi, uint2* __restrict__ lo, int n4)
{
    int i = blockIdx.x * blockDim.x + threadIdx.x;
    if (i >= n4) return;
    float4 v = x[i];
    uint32_t h0, l0, h1, l1;
    split2h(v.x, v.y, h0, l0);
    split2h(v.z, v.w, h1, l1);
    hi[i] = make_uint2(h0, h1);
    lo[i] = make_uint2(l0, l1);
}

// All 4 weight transposes fused: W (K x N) row-major -> T (N x K) single fp16.
__global__ void transpose_all(const float* __restrict__ Wq, const float* __restrict__ Wk,
                              const float* __restrict__ Wv, const float* __restrict__ Wo)
{
    __shared__ float t[32][33];
    const int z = blockIdx.z;
    const float* W;
    __half* Th;
    int N;
    if (z == 0)      { W = Wq; Th = g_WqT16; N = NQK; }
    else if (z == 1) { W = Wk; Th = g_WkT16; N = NQK; }
    else if (z == 2) { W = Wv; Th = g_WvT16; N = DMODEL; }
    else             { W = Wo; Th = g_WoT16; N = DMODEL; }
    const int n0 = blockIdx.x * 32;
    if (n0 >= N) return;
    const int k0 = blockIdx.y * 32;
    t[threadIdx.y][threadIdx.x] = W[(size_t)(k0 + threadIdx.y) * N + n0 + threadIdx.x];
    __syncthreads();
    float v = t[threadIdx.x][threadIdx.y];
    int n = n0 + threadIdx.y, k = k0 + threadIdx.x;
    Th[(size_t)n * DMODEL + k] = __float2half_rn(v);
}

// ------------------------------ HMMA GEMM body -----------------------------
// C(M x Nw) = A @ B16(Nw x K)^T, fp32 acc.
// two_pass=1: A = Ahi + Alo (fp16 split, exact);  two_pass=0: A = Ahi only.
// modes: 0 = fp32 C, 2 = fp16 hi/lo split out, 3 = fp16 single out
#define KC        32
#define ROWB      80
#define ARR_BYTES (128 * ROWB)          // 10240
#define BUF_BYTES (3 * ARR_BYTES)       // 30720: Ah, Al, B
#define GEMM_SMEM (2 * BUF_BYTES)       // 61440

__device__ __forceinline__ void gemm_body(
    const __half* __restrict__ Ahi, const __half* __restrict__ Alo,
    const __half* __restrict__ B16,
    float* __restrict__ C, void* __restrict__ Oh, void* __restrict__ Ol,
    int mode, int two_pass, int m0, int n0, int Nw, char* smem)
{
    const uint32_t sb = smem_u32(smem);
    const int tid = threadIdx.x, lane = tid & 31, wid = tid >> 5;
    const int warp_m = wid & 3, warp_n = wid >> 2;
    const int nchunk = DMODEL / KC;
    const int frow0 = tid >> 2, fcol = tid & 3;

    auto issue_chunk = [&](int c) {
        const uint32_t base = sb + (c & 1) * BUF_BYTES;
        const int k0 = c * KC;
        #pragma unroll
        for (int i = 0; i < 2; i++) {
            const int row = frow0 + i * 64;
            const uint32_t soff = (uint32_t)row * ROWB + fcol * 16;
            const size_t ga = (size_t)(m0 + row) * DMODEL + k0 + fcol * 8;
            const size_t gb = (size_t)(n0 + row) * DMODEL + k0 + fcol * 8;
            cp_async16(base + soff, Ahi + ga);
            if (two_pass) cp_async16(base + ARR_BYTES + soff, Alo + ga);
            cp_async16(base + 2 * ARR_BYTES + soff, B16 + gb);
        }
    };

    float acc[2][8][4];
    #pragma unroll
    for (int mt = 0; mt < 2; mt++)
        #pragma unroll
        for (int j = 0; j < 8; j++)
            #pragma unroll
            for (int q = 0; q < 4; q++) acc[mt][j][q] = 0.f;

    issue_chunk(0);
    CP_COMMIT();

    const int arow_l = (lane & 15);
    const int akc_l  = (lane >> 4) << 3;
    const int brow_l = (lane & 7) + ((lane & 16) ? 8 : 0);
    const int bkc_l  = (lane & 8) ? 8 : 0;

    for (int c = 0; c < nchunk; c++) {
        CP_WAIT0();
        __syncthreads();
        if (c + 1 < nchunk) { issue_chunk(c + 1); CP_COMMIT(); }

        const uint32_t base = sb + (c & 1) * BUF_BYTES;
        #pragma unroll
        for (int ks = 0; ks < 2; ks++) {
            uint32_t ah[2][4], al[2][4];
            #pragma unroll
            for (int mt = 0; mt < 2; mt++) {
                uint32_t addr = base + (uint32_t)(warp_m * 32 + mt * 16 + arow_l) * ROWB
                              + (ks * 16 + akc_l) * 2;
                ldmatrix_x4(ah[mt][0], ah[mt][1], ah[mt][2], ah[mt][3], addr);
                if (two_pass)
                    ldmatrix_x4(al[mt][0], al[mt][1], al[mt][2], al[mt][3], addr + ARR_BYTES);
            }
            #pragma unroll
            for (int jp = 0; jp < 4; jp++) {
                uint32_t baddr = base + 2 * ARR_BYTES
                               + (uint32_t)(warp_n * 64 + jp * 16 + brow_l) * ROWB
                               + (ks * 16 + bkc_l) * 2;
                uint32_t bh[4];
                ldmatrix_x4(bh[0], bh[1], bh[2], bh[3], baddr);
                #pragma unroll
                for (int sub = 0; sub < 2; sub++) {
                    const int j = jp * 2 + sub;
                    #pragma unroll
                    for (int mt = 0; mt < 2; mt++) {
                        mma16816h(acc[mt][j], ah[mt], &bh[sub * 2]);
                        if (two_pass) mma16816h(acc[mt][j], al[mt], &bh[sub * 2]);
                    }
                }
            }
        }
    }

    #pragma unroll
    for (int mt = 0; mt < 2; mt++) {
        const int r0 = m0 + warp_m * 32 + mt * 16 + (lane >> 2);
        #pragma unroll
        for (int j = 0; j < 8; j++) {
            const int col = n0 + warp_n * 64 + j * 8 + (lane & 3) * 2;
            const size_t i0 = (size_t)r0 * Nw + col;
            const size_t i1 = (size_t)(r0 + 8) * Nw + col;
            if (mode == 0) {
                *(float2*)&C[i0] = make_float2(acc[mt][j][0], acc[mt][j][1]);
                *(float2*)&C[i1] = make_float2(acc[mt][j][2], acc[mt][j][3]);
            } else if (mode == 2) {
                uint32_t h0, l0, h1, l1;
                split2h(acc[mt][j][0], acc[mt][j][1], h0, l0);
                split2h(acc[mt][j][2], acc[mt][j][3], h1, l1);
                ((uint32_t*)((__half*)Oh + i0))[0] = h0;
                ((uint32_t*)((__half*)Ol + i0))[0] = l0;
                ((uint32_t*)((__half*)Oh + i1))[0] = h1;
                ((uint32_t*)((__half*)Ol + i1))[0] = l1;
            } else {
                ((uint32_t*)((__half*)Oh + i0))[0] = pack2h(acc[mt][j][0], acc[mt][j][1]);
                ((uint32_t*)((__half*)Oh + i1))[0] = pack2h(acc[mt][j][2], acc[mt][j][3]);
            }
        }
    }
}

// Fused Q/K/V projection: 384 CTAs (V first).
// V & K outputs are fp16-rounded anyway -> computed 1-pass (X hi only).
// Q is 2-pass (hi/lo exact) since its split representation feeds phase-1.
__global__ __launch_bounds__(256, 2)
void gemm_qkv(const __half* __restrict__ Xhi, const __half* __restrict__ Xlo)
{
    extern __shared__ char smem[];
    const int bid = blockIdx.x;
    const __half* B16;
    void *oh = nullptr, *ol = nullptr;
    int m0, n0, Nw, mode, two_pass;
    if (bid < 256) {                       // V: fp16 single, 1-pass
        m0 = (bid >> 3) * 128; n0 = (bid & 7) * 128; Nw = DMODEL; mode = 3; two_pass = 0;
        B16 = g_WvT16; oh = g_V16;
    } else if (bid < 320) {                // Q: fp16 split, 2-pass
        const int t = bid - 256;
        m0 = (t >> 1) * 128; n0 = (t & 1) * 128; Nw = NQK; mode = 2; two_pass = 1;
        B16 = g_WqT16; oh = g_Qh16; ol = g_Ql16;
    } else {                               // K: fp16 single, 1-pass
        const int t = bid - 320;
        m0 = (t >> 1) * 128; n0 = (t & 1) * 128; Nw = NQK; mode = 3; two_pass = 0;
        B16 = g_WkT16; oh = g_K16;
    }
    gemm_body(Xhi, Xlo, B16, nullptr, oh, ol, mode, two_pass, m0, n0, Nw, smem);
}

__global__ __launch_bounds__(256, 2)
void gemm_out(const __half* __restrict__ Yhi, const __half* __restrict__ Ylo,
              float* __restrict__ out)
{
    extern __shared__ char smem[];
    gemm_body(Yhi, Ylo, g_WoT16, out, nullptr, nullptr, 0, 1,
              blockIdx.y * 128, blockIdx.x * 128, DMODEL, smem);
}

// ------------------------------ attention ----------------------------------
// 128-row q tiles, 8 warps x 16 rows. fp16 path:
//   phase 1: S = (Qh+Ql) . K16   (2 MMA passes; Q fp16 split)
//   phase 2: acc += A16 . V16    (1 MMA pass; phi single fp16)
// Denominator keeps exact fp32 phi sums. k-tiles of 128 keys, double-buffered.
#define QPITCH   48
#define V_PITCH  144
#define SM_QH    0
#define SM_QL    6144
#define SM_KBUF(b) (12288 + (b) * 24576)
#define SM_VBUF(b) (12288 + (b) * 24576 + 6144)
#define ATTN_SMEM 61440

__global__ __launch_bounds__(256, 3)
void attn_kernel()
{
    extern __shared__ char sm[];
    const uint32_t sb = smem_u32(sm);

    const int qt = gridDim.x - 1 - blockIdx.x;                   // heavy first
    const int h = blockIdx.y, b = blockIdx.z;
    const int tid = threadIdx.x, lane = tid & 31, wid = tid >> 5;
    const int g = lane >> 2, tg = lane & 3;

    const size_t tok0 = (size_t)(b * L_SEQ + qt * 128);
    const int row_base = qt * 128 + wid * 16;

    auto issue_q = [&]() {
        #pragma unroll
        for (int i = 0; i < 2; i++) {
            int idx = tid + i * 256;
            int arr = idx >> 8, rem = idx & 255, row = rem >> 1, seg = rem & 1;
            uint32_t dst = sb + (arr ? SM_QL : SM_QH) + (uint32_t)row * QPITCH + seg * 16;
            const __half* src = (arr ? g_Ql16 : g_Qh16)
                + (tok0 + row) * NQK + h * FDIM + seg * 8;
            cp_async16(dst, src);
        }
    };
    auto issue_kv = [&](int kt, int buf) {
        const size_t ktok = (size_t)(b * L_SEQ + kt * 128);
        {
            int row = tid >> 1, seg = tid & 1;
            uint32_t dst = sb + SM_KBUF(buf) + (uint32_t)row * QPITCH + seg * 16;
            cp_async16(dst, g_K16 + (ktok + row) * NQK + h * FDIM + seg * 8);
        }
        #pragma unroll
        for (int i = 0; i < 4; i++) {
            int idx = tid + i * 256, row = idx >> 3, seg = idx & 7;
            uint32_t dst = sb + SM_VBUF(buf) + (uint32_t)row * V_PITCH + seg * 16;
            cp_async16(dst, g_V16 + (ktok + row) * DMODEL + h * VDIM + seg * 8);
        }
    };

    issue_q();
    issue_kv(0, 0);
    CP_COMMIT();
    CP_WAIT0();
    __syncthreads();

    uint32_t qh4[4], ql4[4];
    {
        uint32_t off = (uint32_t)(wid * 16 + (lane & 15)) * QPITCH + ((lane >> 4) << 3) * 2;
        ldmatrix_x4(qh4[0], qh4[1], qh4[2], qh4[3], sb + SM_QH + off);
        ldmatrix_x4(ql4[0], ql4[1], ql4[2], ql4[3], sb + SM_QL + off);
    }

    const int ktmax = qt;
    if (ktmax >= 1) { issue_kv(1, 1); CP_COMMIT(); }

    float acc[8][4];
    #pragma unroll
    for (int j = 0; j < 8; j++)
        #pragma unroll
        for (int q = 0; q < 4; q++) acc[j][q] = 0.f;
    float dden0 = 0.f, dden1 = 0.f;

    for (int kt = 0; kt <= ktmax; kt++) {
        const int buf = kt & 1;
        if (kt > 0) {
            CP_WAIT0();
            __syncthreads();
            if (kt < ktmax) { issue_kv(kt + 1, buf ^ 1); CP_COMMIT(); }
        }

        if (kt * 128 > row_base + 15) continue;

        const uint32_t kh_b = sb + SM_KBUF(buf);
        const uint32_t vh_b = sb + SM_VBUF(buf);
        const bool need_mask = (kt * 128 + 127 > row_base);

        #pragma unroll
        for (int q4 = 0; q4 < 4; q4++) {
            // ---- phase 1: S cols [q4*32, q4*32+32)
            float s_acc[4][4];
            #pragma unroll
            for (int jl = 0; jl < 4; jl++)
                #pragma unroll
                for (int e = 0; e < 4; e++) s_acc[jl][e] = 0.f;

            #pragma unroll
            for (int jj = 0; jj < 2; jj++) {
                uint32_t koff = (uint32_t)(q4 * 32 + jj * 16 + (lane & 7)
                                           + ((lane & 16) ? 8 : 0)) * QPITCH
                              + ((lane & 8) ? 16 : 0);
                uint32_t kh4[4];
                ldmatrix_x4(kh4[0], kh4[1], kh4[2], kh4[3], kh_b + koff);
                #pragma unroll
                for (int sub = 0; sub < 2; sub++) {
                    const int jl = jj * 2 + sub;
                    mma16816h(s_acc[jl], qh4, &kh4[sub * 2]);
                    mma16816h(s_acc[jl], ql4, &kh4[sub * 2]);
                }
            }

            // ---- phi + mask + denominator; pack phi single fp16 (A frags)
            uint32_t pah[8];
            #pragma unroll
            for (int jl = 0; jl < 4; jl++) {
                const int j = q4 * 4 + jl;
                float ph[4];
                #pragma unroll
                for (int e = 0; e < 4; e++) {
                    float s = s_acc[jl][e] * 0.25f;
                    float phi = fmaf(s, fmaf(0.5f, s, 1.f), 1.f);
                    if (need_mask) {
                        int col = kt * 128 + j * 8 + tg * 2 + (e & 1);
                        int row = row_base + g + ((e >= 2) ? 8 : 0);
                        if (col > row) phi = 0.f;
                    }
                    ph[e] = phi;
                }
                dden0 += ph[0] + ph[1];
                dden1 += ph[2] + ph[3];
                pah[jl * 2 + 0] = pack2h(ph[0], ph[1]);
                pah[jl * 2 + 1] = pack2h(ph[2], ph[3]);
            }

            // ---- phase 2 (single pass): acc += A(16 x 32) @ V(32 x 64)
            #pragma unroll
            for (int ks2 = 0; ks2 < 2; ks2++) {
                const int ksi = q4 * 2 + ks2;
                const uint32_t* ah = &pah[ks2 * 4];
                #pragma unroll
                for (int jp = 0; jp < 4; jp++) {
                    uint32_t voff = (uint32_t)(ksi * 16 + (lane & 15)) * V_PITCH
                                  + (jp * 16 + ((lane >> 4) << 3)) * 2;
                    uint32_t vh4[4];
                    ldmatrix_x4_t(vh4[0], vh4[1], vh4[2], vh4[3], vh_b + voff);
                    mma16816h(acc[jp * 2 + 0], ah, &vh4[0]);
                    mma16816h(acc[jp * 2 + 1], ah, &vh4[2]);
                }
            }
        }
    }

    // ---- denominator: quad shuffle reduction
    dden0 += __shfl_xor_sync(0xffffffff, dden0, 1);
    dden0 += __shfl_xor_sync(0xffffffff, dden0, 2);
    dden1 += __shfl_xor_sync(0xffffffff, dden1, 1);
    dden1 += __shfl_xor_sync(0xffffffff, dden1, 2);
    const float z0 = 1.f / (dden0 + 1e-12f);
    const float z1 = 1.f / (dden1 + 1e-12f);

    // ---- epilogue: Y written as fp16 hi/lo split (out-proj is 2-pass fp16)
    {
        const size_t grow0 = tok0 + wid * 16 + g;
        #pragma unroll
        for (int j = 0; j < 8; j++) {
            const int col = h * VDIM + j * 8 + tg * 2;
            uint32_t h0, l0, h1, l1;
            split2h(acc[j][0] * z0, acc[j][1] * z0, h0, l0);
            split2h(acc[j][2] * z1, acc[j][3] * z1, h1, l1);
            *(uint32_t*)&g_Yh16[grow0 * DMODEL + col]       = h0;
            *(uint32_t*)&g_Yl16[grow0 * DMODEL + col]       = l0;
            *(uint32_t*)&g_Yh16[(grow0 + 8) * DMODEL + col] = h1;
            *(uint32_t*)&g_Yl16[(grow0 + 8) * DMODEL + col] = l1;
        }
    }
}

// ---------------------------------------------------------------------------
extern "C" void kernel_launch(void* const* d_in, const int* in_sizes, int n_in,
                              void* d_out, int out_size)
{
    const float* X  = (const float*)d_in[0];
    const float* Wq = (const float*)d_in[1];
    const float* Wk = (const float*)d_in[2];
    const float* Wv = (const float*)d_in[3];
    const float* Wo = (const float*)d_in[4];
    float* out = (float*)d_out;

    __half *Xhi, *Xlo, *Yhi, *Ylo;
    cudaGetSymbolAddress((void**)&Xhi, g_Xh16);
    cudaGetSymbolAddress((void**)&Xlo, g_Xl16);
    cudaGetSymbolAddress((void**)&Yhi, g_Yh16);
    cudaGetSymbolAddress((void**)&Ylo, g_Yl16);

    cudaFuncSetAttribute(gemm_qkv, cudaFuncAttributeMaxDynamicSharedMemorySize, GEMM_SMEM);
    cudaFuncSetAttribute(gemm_out, cudaFuncAttributeMaxDynamicSharedMemorySize, GEMM_SMEM);
    cudaFuncSetAttribute(attn_kernel, cudaFuncAttributeMaxDynamicSharedMemorySize, ATTN_SMEM);

    const int n4 = MTOT * DMODEL / 4;
    split_fp16<<<(n4 + 255) / 256, 256>>>((const float4*)X, (uint2*)Xhi, (uint2*)Xlo, n4);
    transpose_all<<<dim3(32, 32, 4), dim3(32, 32)>>>(Wq, Wk, Wv, Wo);

    // fused Q/K/V projections (V,K: 1-pass; Q: 2-pass split out)
    gemm_qkv<<<384, 256, GEMM_SMEM>>>(Xhi, Xlo);
    // causal taylor-exp attention (phase1 2-pass, phase2 1-pass fp16)
    attn_kernel<<<dim3(L_SEQ / 128, NH, B_SZ), 256, ATTN_SMEM>>>();
    // output projection, 2-pass fp16, fp32 out -> d_out
    gemm_out<<<dim3(DMODEL / 128, MTOT / 128), 256, GEMM_SMEM>>>(Yhi, Ylo, out);
}

// round 15
// speedup vs baseline: 4.3179x; 1.0586x over previous
#include <cuda_runtime.h>
#include <cuda_bf16.h>
#include <cuda_fp16.h>
#include <cstdint>

#define B_SZ   2
#define L_SEQ  2048
#define NH     16
#define FDIM   16
#define VDIM   64
#define DMODEL 1024
#define MTOT   (B_SZ * L_SEQ)   // 4096
#define NQK    (NH * FDIM)      // 256

// ------------------------------ scratch (device globals) -------------------
__device__ __half g_Qh16[(size_t)MTOT * NQK];
__device__ __half g_Ql16[(size_t)MTOT * NQK];
__device__ __half g_K16[(size_t)MTOT * NQK];
__device__ __half g_V16[(size_t)MTOT * DMODEL];

__device__ __half g_Xh16[(size_t)MTOT * DMODEL];
__device__ __half g_Xl16[(size_t)MTOT * DMODEL];
__device__ __half g_Yh16[(size_t)MTOT * DMODEL];
__device__ __half g_Yl16[(size_t)MTOT * DMODEL];

__device__ __half g_WqT16[(size_t)NQK * DMODEL];
__device__ __half g_WkT16[(size_t)NQK * DMODEL];
__device__ __half g_WvT16[(size_t)DMODEL * DMODEL];
__device__ __half g_WoT16[(size_t)DMODEL * DMODEL];

// ------------------------------ helpers ------------------------------------
__device__ __forceinline__ uint32_t smem_u32(const void* p) {
    uint32_t a;
    asm("{ .reg .u64 t; cvta.to.shared.u64 t, %1; cvt.u32.u64 %0, t; }" : "=r"(a) : "l"(p));
    return a;
}
__device__ __forceinline__ void cp_async16(uint32_t s, const void* g) {
    asm volatile("cp.async.cg.shared.global [%0], [%1], 16;" :: "r"(s), "l"(g));
}
#define CP_COMMIT() asm volatile("cp.async.commit_group;" ::: "memory")
#define CP_WAIT0()  asm volatile("cp.async.wait_group 0;" ::: "memory")

__device__ __forceinline__ void ldmatrix_x4(uint32_t& r0, uint32_t& r1, uint32_t& r2, uint32_t& r3,
                                            uint32_t addr) {
    asm volatile("ldmatrix.sync.aligned.m8n8.x4.shared.b16 {%0,%1,%2,%3}, [%4];"
                 : "=r"(r0), "=r"(r1), "=r"(r2), "=r"(r3) : "r"(addr));
}
__device__ __forceinline__ void ldmatrix_x4_t(uint32_t& r0, uint32_t& r1, uint32_t& r2, uint32_t& r3,
                                              uint32_t addr) {
    asm volatile("ldmatrix.sync.aligned.m8n8.x4.trans.shared.b16 {%0,%1,%2,%3}, [%4];"
                 : "=r"(r0), "=r"(r1), "=r"(r2), "=r"(r3) : "r"(addr));
}
__device__ __forceinline__ void mma16816h(float* d, const uint32_t* a, const uint32_t* b) {
    asm volatile(
        "mma.sync.aligned.m16n8k16.row.col.f32.f16.f16.f32 "
        "{%0,%1,%2,%3},{%4,%5,%6,%7},{%8,%9},{%0,%1,%2,%3};"
        : "+f"(d[0]), "+f"(d[1]), "+f"(d[2]), "+f"(d[3])
        : "r"(a[0]), "r"(a[1]), "r"(a[2]), "r"(a[3]), "r"(b[0]), "r"(b[1]));
}
// fp16 hi/lo split, packed pairwise (low half = y0)
__device__ __forceinline__ void split2h(float y0, float y1, uint32_t& hi, uint32_t& lo) {
    __half2 h = __floats2half2_rn(y0, y1);
    float2 f = __half22float2(h);
    __half2 l = __floats2half2_rn(y0 - f.x, y1 - f.y);
    hi = *(uint32_t*)&h;
    lo = *(uint32_t*)&l;
}
__device__ __forceinline__ uint32_t pack2h(float y0, float y1) {
    __half2 h = __floats2half2_rn(y0, y1);
    return *(uint32_t*)&h;
}

// ------------------------------ prep kernels -------------------------------
__global__ void split_fp16(const float4* __restrict__ x,
                           uint2* __restrict__ hi, uint2* __restrict__ lo, int n4)
{
    int i = blockIdx.x * blockDim.x + threadIdx.x;
    if (i >= n4) return;
    float4 v = x[i];
    uint32_t h0, l0, h1, l1;
    split2h(v.x, v.y, h0, l0);
    split2h(v.z, v.w, h1, l1);
    hi[i] = make_uint2(h0, h1);
    lo[i] = make_uint2(l0, l1);
}

// All 4 weight transposes fused: W (K x N) row-major -> T (N x K) single fp16.
__global__ void transpose_all(const float* __restrict__ Wq, const float* __restrict__ Wk,
                              const float* __restrict__ Wv, const float* __restrict__ Wo)
{
    __shared__ float t[32][33];
    const int z = blockIdx.z;
    const float* W;
    __half* Th;
    int N;
    if (z == 0)      { W = Wq; Th = g_WqT16; N = NQK; }
    else if (z == 1) { W = Wk; Th = g_WkT16; N = NQK; }
    else if (z == 2) { W = Wv; Th = g_WvT16; N = DMODEL; }
    else             { W = Wo; Th = g_WoT16; N = DMODEL; }
    const int n0 = blockIdx.x * 32;
    if (n0 >= N) return;
    const int k0 = blockIdx.y * 32;
    t[threadIdx.y][threadIdx.x] = W[(size_t)(k0 + threadIdx.y) * N + n0 + threadIdx.x];
    __syncthreads();
    float v = t[threadIdx.x][threadIdx.y];
    int n = n0 + threadIdx.y, k = k0 + threadIdx.x;
    Th[(size_t)n * DMODEL + k] = __float2half_rn(v);
}

// ------------------------------ HMMA GEMM body -----------------------------
// C(M x Nw) = A @ B16(Nw x K)^T, fp32 acc.
// KC=64 (R15): halves the serial chunk count -> amortizes wait+sync latency.
// two_pass=1: A = Ahi + Alo (fp16 split, exact);  two_pass=0: A = Ahi only.
// modes: 0 = fp32 C, 2 = fp16 hi/lo split out, 3 = fp16 single out
#define KC        64
#define ROWB      144                   // 64 fp16 = 128B data + 16B pad
#define ARR_BYTES (128 * ROWB)          // 18432
#define BUF_BYTES (3 * ARR_BYTES)       // 55296: Ah, Al, B
#define GEMM_SMEM (2 * BUF_BYTES)       // 110592 (2 CTAs/SM = 221KB <= 228KB)

__device__ __forceinline__ void gemm_body(
    const __half* __restrict__ Ahi, const __half* __restrict__ Alo,
    const __half* __restrict__ B16,
    float* __restrict__ C, void* __restrict__ Oh, void* __restrict__ Ol,
    int mode, int two_pass, int m0, int n0, int Nw, char* smem)
{
    const uint32_t sb = smem_u32(smem);
    const int tid = threadIdx.x, lane = tid & 31, wid = tid >> 5;
    const int warp_m = wid & 3, warp_n = wid >> 2;
    const int nchunk = DMODEL / KC;      // 16

    auto issue_chunk = [&](int c) {
        const uint32_t base = sb + (c & 1) * BUF_BYTES;
        const int k0 = c * KC;
        // per array: 128 rows x 8 segs of 16B = 1024 cp.async; 4 per thread
        #pragma unroll
        for (int i = 0; i < 4; i++) {
            const int idx = tid + i * 256;
            const int row = idx >> 3, seg = idx & 7;
            const uint32_t soff = (uint32_t)row * ROWB + seg * 16;
            const size_t ga = (size_t)(m0 + row) * DMODEL + k0 + seg * 8;
            const size_t gb = (size_t)(n0 + row) * DMODEL + k0 + seg * 8;
            cp_async16(base + soff, Ahi + ga);
            if (two_pass) cp_async16(base + ARR_BYTES + soff, Alo + ga);
            cp_async16(base + 2 * ARR_BYTES + soff, B16 + gb);
        }
    };

    float acc[2][8][4];
    #pragma unroll
    for (int mt = 0; mt < 2; mt++)
        #pragma unroll
        for (int j = 0; j < 8; j++)
            #pragma unroll
            for (int q = 0; q < 4; q++) acc[mt][j][q] = 0.f;

    issue_chunk(0);
    CP_COMMIT();

    const int arow_l = (lane & 15);
    const int akc_l  = (lane >> 4) << 3;
    const int brow_l = (lane & 7) + ((lane & 16) ? 8 : 0);
    const int bkc_l  = (lane & 8) ? 8 : 0;

    for (int c = 0; c < nchunk; c++) {
        CP_WAIT0();
        __syncthreads();
        if (c + 1 < nchunk) { issue_chunk(c + 1); CP_COMMIT(); }

        const uint32_t base = sb + (c & 1) * BUF_BYTES;
        #pragma unroll
        for (int ks = 0; ks < 4; ks++) {
            uint32_t ah[2][4], al[2][4];
            #pragma unroll
            for (int mt = 0; mt < 2; mt++) {
                uint32_t addr = base + (uint32_t)(warp_m * 32 + mt * 16 + arow_l) * ROWB
                              + (ks * 16 + akc_l) * 2;
                ldmatrix_x4(ah[mt][0], ah[mt][1], ah[mt][2], ah[mt][3], addr);
                if (two_pass)
                    ldmatrix_x4(al[mt][0], al[mt][1], al[mt][2], al[mt][3], addr + ARR_BYTES);
            }
            #pragma unroll
            for (int jp = 0; jp < 4; jp++) {
                uint32_t baddr = base + 2 * ARR_BYTES
                               + (uint32_t)(warp_n * 64 + jp * 16 + brow_l) * ROWB
                               + (ks * 16 + bkc_l) * 2;
                uint32_t bh[4];
                ldmatrix_x4(bh[0], bh[1], bh[2], bh[3], baddr);
                #pragma unroll
                for (int sub = 0; sub < 2; sub++) {
                    const int j = jp * 2 + sub;
                    #pragma unroll
                    for (int mt = 0; mt < 2; mt++) {
                        mma16816h(acc[mt][j], ah[mt], &bh[sub * 2]);
                        if (two_pass) mma16816h(acc[mt][j], al[mt], &bh[sub * 2]);
                    }
                }
            }
        }
    }

    #pragma unroll
    for (int mt = 0; mt < 2; mt++) {
        const int r0 = m0 + warp_m * 32 + mt * 16 + (lane >> 2);
        #pragma unroll
        for (int j = 0; j < 8; j++) {
            const int col = n0 + warp_n * 64 + j * 8 + (lane & 3) * 2;
            const size_t i0 = (size_t)r0 * Nw + col;
            const size_t i1 = (size_t)(r0 + 8) * Nw + col;
            if (mode == 0) {
                *(float2*)&C[i0] = make_float2(acc[mt][j][0], acc[mt][j][1]);
                *(float2*)&C[i1] = make_float2(acc[mt][j][2], acc[mt][j][3]);
            } else if (mode == 2) {
                uint32_t h0, l0, h1, l1;
                split2h(acc[mt][j][0], acc[mt][j][1], h0, l0);
                split2h(acc[mt][j][2], acc[mt][j][3], h1, l1);
                ((uint32_t*)((__half*)Oh + i0))[0] = h0;
                ((uint32_t*)((__half*)Ol + i0))[0] = l0;
                ((uint32_t*)((__half*)Oh + i1))[0] = h1;
                ((uint32_t*)((__half*)Ol + i1))[0] = l1;
            } else {
                ((uint32_t*)((__half*)Oh + i0))[0] = pack2h(acc[mt][j][0], acc[mt][j][1]);
                ((uint32_t*)((__half*)Oh + i1))[0] = pack2h(acc[mt][j][2], acc[mt][j][3]);
            }
        }
    }
}

// Fused Q/K/V projection: 384 CTAs (V first).
// V & K outputs are fp16-rounded anyway -> computed 1-pass (X hi only).
// Q is 2-pass (hi/lo exact) since its split representation feeds phase-1.
__global__ __launch_bounds__(256, 2)
void gemm_qkv(const __half* __restrict__ Xhi, const __half* __restrict__ Xlo)
{
    extern __shared__ char smem[];
    const int bid = blockIdx.x;
    const __half* B16;
    void *oh = nullptr, *ol = nullptr;
    int m0, n0, Nw, mode, two_pass;
    if (bid < 256) {                       // V: fp16 single, 1-pass
        m0 = (bid >> 3) * 128; n0 = (bid & 7) * 128; Nw = DMODEL; mode = 3; two_pass = 0;
        B16 = g_WvT16; oh = g_V16;
    } else if (bid < 320) {                // Q: fp16 split, 2-pass
        const int t = bid - 256;
        m0 = (t >> 1) * 128; n0 = (t & 1) * 128; Nw = NQK; mode = 2; two_pass = 1;
        B16 = g_WqT16; oh = g_Qh16; ol = g_Ql16;
    } else {                               // K: fp16 single, 1-pass
        const int t = bid - 320;
        m0 = (t >> 1) * 128; n0 = (t & 1) * 128; Nw = NQK; mode = 3; two_pass = 0;
        B16 = g_WkT16; oh = g_K16;
    }
    gemm_body(Xhi, Xlo, B16, nullptr, oh, ol, mode, two_pass, m0, n0, Nw, smem);
}

__global__ __launch_bounds__(256, 2)
void gemm_out(const __half* __restrict__ Yhi, const __half* __restrict__ Ylo,
              float* __restrict__ out)
{
    extern __shared__ char smem[];
    gemm_body(Yhi, Ylo, g_WoT16, out, nullptr, nullptr, 0, 1,
              blockIdx.y * 128, blockIdx.x * 128, DMODEL, smem);
}

// ------------------------------ attention (unchanged from R14) -------------
#define QPITCH   48
#define V_PITCH  144
#define SM_QH    0
#define SM_QL    6144
#define SM_KBUF(b) (12288 + (b) * 24576)
#define SM_VBUF(b) (12288 + (b) * 24576 + 6144)
#define ATTN_SMEM 61440

__global__ __launch_bounds__(256, 3)
void attn_kernel()
{
    extern __shared__ char sm[];
    const uint32_t sb = smem_u32(sm);

    const int qt = gridDim.x - 1 - blockIdx.x;                   // heavy first
    const int h = blockIdx.y, b = blockIdx.z;
    const int tid = threadIdx.x, lane = tid & 31, wid = tid >> 5;
    const int g = lane >> 2, tg = lane & 3;

    const size_t tok0 = (size_t)(b * L_SEQ + qt * 128);
    const int row_base = qt * 128 + wid * 16;

    auto issue_q = [&]() {
        #pragma unroll
        for (int i = 0; i < 2; i++) {
            int idx = tid + i * 256;
            int arr = idx >> 8, rem = idx & 255, row = rem >> 1, seg = rem & 1;
            uint32_t dst = sb + (arr ? SM_QL : SM_QH) + (uint32_t)row * QPITCH + seg * 16;
            const __half* src = (arr ? g_Ql16 : g_Qh16)
                + (tok0 + row) * NQK + h * FDIM + seg * 8;
            cp_async16(dst, src);
        }
    };
    auto issue_kv = [&](int kt, int buf) {
        const size_t ktok = (size_t)(b * L_SEQ + kt * 128);
        {
            int row = tid >> 1, seg = tid & 1;
            uint32_t dst = sb + SM_KBUF(buf) + (uint32_t)row * QPITCH + seg * 16;
            cp_async16(dst, g_K16 + (ktok + row) * NQK + h * FDIM + seg * 8);
        }
        #pragma unroll
        for (int i = 0; i < 4; i++) {
            int idx = tid + i * 256, row = idx >> 3, seg = idx & 7;
            uint32_t dst = sb + SM_VBUF(buf) + (uint32_t)row * V_PITCH + seg * 16;
            cp_async16(dst, g_V16 + (ktok + row) * DMODEL + h * VDIM + seg * 8);
        }
    };

    issue_q();
    issue_kv(0, 0);
    CP_COMMIT();
    CP_WAIT0();
    __syncthreads();

    uint32_t qh4[4], ql4[4];
    {
        uint32_t off = (uint32_t)(wid * 16 + (lane & 15)) * QPITCH + ((lane >> 4) << 3) * 2;
        ldmatrix_x4(qh4[0], qh4[1], qh4[2], qh4[3], sb + SM_QH + off);
        ldmatrix_x4(ql4[0], ql4[1], ql4[2], ql4[3], sb + SM_QL + off);
    }

    const int ktmax = qt;
    if (ktmax >= 1) { issue_kv(1, 1); CP_COMMIT(); }

    float acc[8][4];
    #pragma unroll
    for (int j = 0; j < 8; j++)
        #pragma unroll
        for (int q = 0; q < 4; q++) acc[j][q] = 0.f;
    float dden0 = 0.f, dden1 = 0.f;

    for (int kt = 0; kt <= ktmax; kt++) {
        const int buf = kt & 1;
        if (kt > 0) {
            CP_WAIT0();
            __syncthreads();
            if (kt < ktmax) { issue_kv(kt + 1, buf ^ 1); CP_COMMIT(); }
        }

        if (kt * 128 > row_base + 15) continue;

        const uint32_t kh_b = sb + SM_KBUF(buf);
        const uint32_t vh_b = sb + SM_VBUF(buf);
        const bool need_mask = (kt * 128 + 127 > row_base);

        #pragma unroll
        for (int q4 = 0; q4 < 4; q4++) {
            // ---- phase 1: S cols [q4*32, q4*32+32)
            float s_acc[4][4];
            #pragma unroll
            for (int jl = 0; jl < 4; jl++)
                #pragma unroll
                for (int e = 0; e < 4; e++) s_acc[jl][e] = 0.f;

            #pragma unroll
            for (int jj = 0; jj < 2; jj++) {
                uint32_t koff = (uint32_t)(q4 * 32 + jj * 16 + (lane & 7)
                                           + ((lane & 16) ? 8 : 0)) * QPITCH
                              + ((lane & 8) ? 16 : 0);
                uint32_t kh4[4];
                ldmatrix_x4(kh4[0], kh4[1], kh4[2], kh4[3], kh_b + koff);
                #pragma unroll
                for (int sub = 0; sub < 2; sub++) {
                    const int jl = jj * 2 + sub;
                    mma16816h(s_acc[jl], qh4, &kh4[sub * 2]);
                    mma16816h(s_acc[jl], ql4, &kh4[sub * 2]);
                }
            }

            // ---- phi + mask + denominator; pack phi single fp16 (A frags)
            uint32_t pah[8];
            #pragma unroll
            for (int jl = 0; jl < 4; jl++) {
                const int j = q4 * 4 + jl;
                float ph[4];
                #pragma unroll
                for (int e = 0; e < 4; e++) {
                    float s = s_acc[jl][e] * 0.25f;
                    float phi = fmaf(s, fmaf(0.5f, s, 1.f), 1.f);
                    if (need_mask) {
                        int col = kt * 128 + j * 8 + tg * 2 + (e & 1);
                        int row = row_base + g + ((e >= 2) ? 8 : 0);
                        if (col > row) phi = 0.f;
                    }
                    ph[e] = phi;
                }
                dden0 += ph[0] + ph[1];
                dden1 += ph[2] + ph[3];
                pah[jl * 2 + 0] = pack2h(ph[0], ph[1]);
                pah[jl * 2 + 1] = pack2h(ph[2], ph[3]);
            }

            // ---- phase 2 (single pass): acc += A(16 x 32) @ V(32 x 64)
            #pragma unroll
            for (int ks2 = 0; ks2 < 2; ks2++) {
                const int ksi = q4 * 2 + ks2;
                const uint32_t* ah = &pah[ks2 * 4];
                #pragma unroll
                for (int jp = 0; jp < 4; jp++) {
                    uint32_t voff = (uint32_t)(ksi * 16 + (lane & 15)) * V_PITCH
                                  + (jp * 16 + ((lane >> 4) << 3)) * 2;
                    uint32_t vh4[4];
                    ldmatrix_x4_t(vh4[0], vh4[1], vh4[2], vh4[3], vh_b + voff);
                    mma16816h(acc[jp * 2 + 0], ah, &vh4[0]);
                    mma16816h(acc[jp * 2 + 1], ah, &vh4[2]);
                }
            }
        }
    }

    // ---- denominator: quad shuffle reduction
    dden0 += __shfl_xor_sync(0xffffffff, dden0, 1);
    dden0 += __shfl_xor_sync(0xffffffff, dden0, 2);
    dden1 += __shfl_xor_sync(0xffffffff, dden1, 1);
    dden1 += __shfl_xor_sync(0xffffffff, dden1, 2);
    const float z0 = 1.f / (dden0 + 1e-12f);
    const float z1 = 1.f / (dden1 + 1e-12f);

    // ---- epilogue: Y written as fp16 hi/lo split (out-proj is 2-pass fp16)
    {
        const size_t grow0 = tok0 + wid * 16 + g;
        #pragma unroll
        for (int j = 0; j < 8; j++) {
            const int col = h * VDIM + j * 8 + tg * 2;
            uint32_t h0, l0, h1, l1;
            split2h(acc[j][0] * z0, acc[j][1] * z0, h0, l0);
            split2h(acc[j][2] * z1, acc[j][3] * z1, h1, l1);
            *(uint32_t*)&g_Yh16[grow0 * DMODEL + col]       = h0;
            *(uint32_t*)&g_Yl16[grow0 * DMODEL + col]       = l0;
            *(uint32_t*)&g_Yh16[(grow0 + 8) * DMODEL + col] = h1;
            *(uint32_t*)&g_Yl16[(grow0 + 8) * DMODEL + col] = l1;
        }
    }
}

// ---------------------------------------------------------------------------
extern "C" void kernel_launch(void* const* d_in, const int* in_sizes, int n_in,
                              void* d_out, int out_size)
{
    const float* X  = (const float*)d_in[0];
    const float* Wq = (const float*)d_in[1];
    const float* Wk = (const float*)d_in[2];
    const float* Wv = (const float*)d_in[3];
    const float* Wo = (const float*)d_in[4];
    float* out = (float*)d_out;

    __half *Xhi, *Xlo, *Yhi, *Ylo;
    cudaGetSymbolAddress((void**)&Xhi, g_Xh16);
    cudaGetSymbolAddress((void**)&Xlo, g_Xl16);
    cudaGetSymbolAddress((void**)&Yhi, g_Yh16);
    cudaGetSymbolAddress((void**)&Ylo, g_Yl16);

    cudaFuncSetAttribute(gemm_qkv, cudaFuncAttributeMaxDynamicSharedMemorySize, GEMM_SMEM);
    cudaFuncSetAttribute(gemm_out, cudaFuncAttributeMaxDynamicSharedMemorySize, GEMM_SMEM);
    cudaFuncSetAttribute(attn_kernel, cudaFuncAttributeMaxDynamicSharedMemorySize, ATTN_SMEM);

    const int n4 = MTOT * DMODEL / 4;
    split_fp16<<<(n4 + 255) / 256, 256>>>((const float4*)X, (uint2*)Xhi, (uint2*)Xlo, n4);
    transpose_all<<<dim3(32, 32, 4), dim3(32, 32)>>>(Wq, Wk, Wv, Wo);

    // fused Q/K/V projections (V,K: 1-pass; Q: 2-pass split out), KC=64
    gemm_qkv<<<384, 256, GEMM_SMEM>>>(Xhi, Xlo);
    // causal taylor-exp attention (phase1 2-pass, phase2 1-pass fp16)
    attn_kernel<<<dim3(L_SEQ / 128, NH, B_SZ), 256, ATTN_SMEM>>>();
    // output projection, 2-pass fp16, fp32 out -> d_out, KC=64
    gemm_out<<<dim3(DMODEL / 128, MTOT / 128), 256, GEMM_SMEM>>>(Yhi, Ylo, out);
}

// round 16
// speedup vs baseline: 4.5344x; 1.0501x over previous
#include <cuda_runtime.h>
#include <cuda_bf16.h>
#include <cuda_fp16.h>
#include <cstdint>

#define B_SZ   2
#define L_SEQ  2048
#define NH     16
#define FDIM   16
#define VDIM   64
#define DMODEL 1024
#define MTOT   (B_SZ * L_SEQ)   // 4096
#define NQK    (NH * FDIM)      // 256

// ------------------------------ scratch (device globals) -------------------
__device__ __half g_Q16[(size_t)MTOT * NQK];
__device__ __half g_K16[(size_t)MTOT * NQK];
__device__ __half g_V16[(size_t)MTOT * DMODEL];

__device__ __half g_Xh16[(size_t)MTOT * DMODEL];
__device__ __half g_Xl16[(size_t)MTOT * DMODEL];
__device__ __half g_Yh16[(size_t)MTOT * DMODEL];
__device__ __half g_Yl16[(size_t)MTOT * DMODEL];

__device__ __half g_WqT16[(size_t)NQK * DMODEL];
__device__ __half g_WkT16[(size_t)NQK * DMODEL];
__device__ __half g_WvT16[(size_t)DMODEL * DMODEL];
__device__ __half g_WoT16[(size_t)DMODEL * DMODEL];

// ------------------------------ helpers ------------------------------------
__device__ __forceinline__ uint32_t smem_u32(const void* p) {
    uint32_t a;
    asm("{ .reg .u64 t; cvta.to.shared.u64 t, %1; cvt.u32.u64 %0, t; }" : "=r"(a) : "l"(p));
    return a;
}
__device__ __forceinline__ void cp_async16(uint32_t s, const void* g) {
    asm volatile("cp.async.cg.shared.global [%0], [%1], 16;" :: "r"(s), "l"(g));
}
#define CP_COMMIT() asm volatile("cp.async.commit_group;" ::: "memory")
#define CP_WAIT0()  asm volatile("cp.async.wait_group 0;" ::: "memory")

__device__ __forceinline__ void ldmatrix_x4(uint32_t& r0, uint32_t& r1, uint32_t& r2, uint32_t& r3,
                                            uint32_t addr) {
    asm volatile("ldmatrix.sync.aligned.m8n8.x4.shared.b16 {%0,%1,%2,%3}, [%4];"
                 : "=r"(r0), "=r"(r1), "=r"(r2), "=r"(r3) : "r"(addr));
}
__device__ __forceinline__ void ldmatrix_x4_t(uint32_t& r0, uint32_t& r1, uint32_t& r2, uint32_t& r3,
                                              uint32_t addr) {
    asm volatile("ldmatrix.sync.aligned.m8n8.x4.trans.shared.b16 {%0,%1,%2,%3}, [%4];"
                 : "=r"(r0), "=r"(r1), "=r"(r2), "=r"(r3) : "r"(addr));
}
__device__ __forceinline__ void mma16816h(float* d, const uint32_t* a, const uint32_t* b) {
    asm volatile(
        "mma.sync.aligned.m16n8k16.row.col.f32.f16.f16.f32 "
        "{%0,%1,%2,%3},{%4,%5,%6,%7},{%8,%9},{%0,%1,%2,%3};"
        : "+f"(d[0]), "+f"(d[1]), "+f"(d[2]), "+f"(d[3])
        : "r"(a[0]), "r"(a[1]), "r"(a[2]), "r"(a[3]), "r"(b[0]), "r"(b[1]));
}
// fp16 hi/lo split, packed pairwise (low half = y0)
__device__ __forceinline__ void split2h(float y0, float y1, uint32_t& hi, uint32_t& lo) {
    __half2 h = __floats2half2_rn(y0, y1);
    float2 f = __half22float2(h);
    __half2 l = __floats2half2_rn(y0 - f.x, y1 - f.y);
    hi = *(uint32_t*)&h;
    lo = *(uint32_t*)&l;
}
__device__ __forceinline__ uint32_t pack2h(float y0, float y1) {
    __half2 h = __floats2half2_rn(y0, y1);
    return *(uint32_t*)&h;
}

// ------------------------------ prep kernels -------------------------------
__global__ void split_fp16(const float4* __restrict__ x,
                           uint2* __restrict__ hi, uint2* __restrict__ lo, int n4)
{
    int i = blockIdx.x * blockDim.x + threadIdx.x;
    if (i >= n4) return;
    float4 v = x[i];
    uint32_t h0, l0, h1, l1;
    split2h(v.x, v.y, h0, l0);
    split2h(v.z, v.w, h1, l1);
    hi[i] = make_uint2(h0, h1);
    lo[i] = make_uint2(l0, l1);
}

// All 4 weight transposes fused: W (K x N) row-major -> T (N x K) single fp16.
__global__ void transpose_all(const float* __restrict__ Wq, const float* __restrict__ Wk,
                              const float* __restrict__ Wv, const float* __restrict__ Wo)
{
    __shared__ float t[32][33];
    const int z = blockIdx.z;
    const float* W;
    __half* Th;
    int N;
    if (z == 0)      { W = Wq; Th = g_WqT16; N = NQK; }
    else if (z == 1) { W = Wk; Th = g_WkT16; N = NQK; }
    else if (z == 2) { W = Wv; Th = g_WvT16; N = DMODEL; }
    else             { W = Wo; Th = g_WoT16; N = DMODEL; }
    const int n0 = blockIdx.x * 32;
    if (n0 >= N) return;
    const int k0 = blockIdx.y * 32;
    t[threadIdx.y][threadIdx.x] = W[(size_t)(k0 + threadIdx.y) * N + n0 + threadIdx.x];
    __syncthreads();
    float v = t[threadIdx.x][threadIdx.y];
    int n = n0 + threadIdx.y, k = k0 + threadIdx.x;
    Th[(size_t)n * DMODEL + k] = __float2half_rn(v);
}

// ------------------------------ HMMA GEMM body -----------------------------
// C(M x Nw) = A @ B16(Nw x K)^T, fp32 acc. KC=64 double-buffered cp.async.
// two_pass=1: A = Ahi + Alo (fp16 split, exact);  two_pass=0: A = Ahi only.
// modes: 0 = fp32 C, 3 = fp16 single out
#define KC        64
#define ROWB      144                   // 64 fp16 = 128B data + 16B pad
#define ARR_BYTES (128 * ROWB)          // 18432
#define BUF_BYTES (3 * ARR_BYTES)       // 55296: Ah, Al, B
#define GEMM_SMEM (2 * BUF_BYTES)       // 110592 (2 CTAs/SM)

__device__ __forceinline__ void gemm_body(
    const __half* __restrict__ Ahi, const __half* __restrict__ Alo,
    const __half* __restrict__ B16,
    float* __restrict__ C, void* __restrict__ Oh,
    int mode, int two_pass, int m0, int n0, int Nw, char* smem)
{
    const uint32_t sb = smem_u32(smem);
    const int tid = threadIdx.x, lane = tid & 31, wid = tid >> 5;
    const int warp_m = wid & 3, warp_n = wid >> 2;
    const int nchunk = DMODEL / KC;      // 16

    auto issue_chunk = [&](int c) {
        const uint32_t base = sb + (c & 1) * BUF_BYTES;
        const int k0 = c * KC;
        #pragma unroll
        for (int i = 0; i < 4; i++) {
            const int idx = tid + i * 256;
            const int row = idx >> 3, seg = idx & 7;
            const uint32_t soff = (uint32_t)row * ROWB + seg * 16;
            const size_t ga = (size_t)(m0 + row) * DMODEL + k0 + seg * 8;
            const size_t gb = (size_t)(n0 + row) * DMODEL + k0 + seg * 8;
            cp_async16(base + soff, Ahi + ga);
            if (two_pass) cp_async16(base + ARR_BYTES + soff, Alo + ga);
            cp_async16(base + 2 * ARR_BYTES + soff, B16 + gb);
        }
    };

    float acc[2][8][4];
    #pragma unroll
    for (int mt = 0; mt < 2; mt++)
        #pragma unroll
        for (int j = 0; j < 8; j++)
            #pragma unroll
            for (int q = 0; q < 4; q++) acc[mt][j][q] = 0.f;

    issue_chunk(0);
    CP_COMMIT();

    const int arow_l = (lane & 15);
    const int akc_l  = (lane >> 4) << 3;
    const int brow_l = (lane & 7) + ((lane & 16) ? 8 : 0);
    const int bkc_l  = (lane & 8) ? 8 : 0;

    for (int c = 0; c < nchunk; c++) {
        CP_WAIT0();
        __syncthreads();
        if (c + 1 < nchunk) { issue_chunk(c + 1); CP_COMMIT(); }

        const uint32_t base = sb + (c & 1) * BUF_BYTES;
        #pragma unroll
        for (int ks = 0; ks < 4; ks++) {
            uint32_t ah[2][4], al[2][4];
            #pragma unroll
            for (int mt = 0; mt < 2; mt++) {
                uint32_t addr = base + (uint32_t)(warp_m * 32 + mt * 16 + arow_l) * ROWB
                              + (ks * 16 + akc_l) * 2;
                ldmatrix_x4(ah[mt][0], ah[mt][1], ah[mt][2], ah[mt][3], addr);
                if (two_pass)
                    ldmatrix_x4(al[mt][0], al[mt][1], al[mt][2], al[mt][3], addr + ARR_BYTES);
            }
            #pragma unroll
            for (int jp = 0; jp < 4; jp++) {
                uint32_t baddr = base + 2 * ARR_BYTES
                               + (uint32_t)(warp_n * 64 + jp * 16 + brow_l) * ROWB
                               + (ks * 16 + bkc_l) * 2;
                uint32_t bh[4];
                ldmatrix_x4(bh[0], bh[1], bh[2], bh[3], baddr);
                #pragma unroll
                for (int sub = 0; sub < 2; sub++) {
                    const int j = jp * 2 + sub;
                    #pragma unroll
                    for (int mt = 0; mt < 2; mt++) {
                        mma16816h(acc[mt][j], ah[mt], &bh[sub * 2]);
                        if (two_pass) mma16816h(acc[mt][j], al[mt], &bh[sub * 2]);
                    }
                }
            }
        }
    }

    #pragma unroll
    for (int mt = 0; mt < 2; mt++) {
        const int r0 = m0 + warp_m * 32 + mt * 16 + (lane >> 2);
        #pragma unroll
        for (int j = 0; j < 8; j++) {
            const int col = n0 + warp_n * 64 + j * 8 + (lane & 3) * 2;
            const size_t i0 = (size_t)r0 * Nw + col;
            const size_t i1 = (size_t)(r0 + 8) * Nw + col;
            if (mode == 0) {
                *(float2*)&C[i0] = make_float2(acc[mt][j][0], acc[mt][j][1]);
                *(float2*)&C[i1] = make_float2(acc[mt][j][2], acc[mt][j][3]);
            } else {
                ((uint32_t*)((__half*)Oh + i0))[0] = pack2h(acc[mt][j][0], acc[mt][j][1]);
                ((uint32_t*)((__half*)Oh + i1))[0] = pack2h(acc[mt][j][2], acc[mt][j][3]);
            }
        }
    }
}

// Fused Q/K/V projection: 384 CTAs (V first).
// V & K: 1-pass (outputs fp16-rounded anyway). Q: 2-pass exact input, fp16 out.
__global__ __launch_bounds__(256, 2)
void gemm_qkv(const __half* __restrict__ Xhi, const __half* __restrict__ Xlo)
{
    extern __shared__ char smem[];
    const int bid = blockIdx.x;
    const __half* B16;
    void *oh = nullptr;
    int m0, n0, Nw, two_pass;
    if (bid < 256) {                       // V: 1-pass
        m0 = (bid >> 3) * 128; n0 = (bid & 7) * 128; Nw = DMODEL; two_pass = 0;
        B16 = g_WvT16; oh = g_V16;
    } else if (bid < 320) {                // Q: 2-pass input, single fp16 out
        const int t = bid - 256;
        m0 = (t >> 1) * 128; n0 = (t & 1) * 128; Nw = NQK; two_pass = 1;
        B16 = g_WqT16; oh = g_Q16;
    } else {                               // K: 1-pass
        const int t = bid - 320;
        m0 = (t >> 1) * 128; n0 = (t & 1) * 128; Nw = NQK; two_pass = 0;
        B16 = g_WkT16; oh = g_K16;
    }
    gemm_body(Xhi, Xlo, B16, nullptr, oh, 3, two_pass, m0, n0, Nw, smem);
}

__global__ __launch_bounds__(256, 2)
void gemm_out(const __half* __restrict__ Yhi, const __half* __restrict__ Ylo,
              float* __restrict__ out)
{
    extern __shared__ char smem[];
    gemm_body(Yhi, Ylo, g_WoT16, out, nullptr, 0, 1,
              blockIdx.y * 128, blockIdx.x * 128, DMODEL, smem);
}

// ------------------------------ attention ----------------------------------
// 128-row q tiles, 8 warps x 16 rows. fp16 path (R16):
//   phase 1: S = Q16 . K16      (1 MMA pass; Q single fp16)
//   phase 2: acc += A16 . V16   (1 MMA pass; phi single fp16)
// Exact per-quarter causal break inside the diagonal tile.
// Denominator keeps exact fp32 phi sums. k-tiles of 128 keys, double-buffered.
#define QPITCH   48
#define V_PITCH  144
#define SM_Q     0
#define SM_KBUF(b) (6144 + (b) * 24576)
#define SM_VBUF(b) (6144 + (b) * 24576 + 6144)
#define ATTN_SMEM 55296

__global__ __launch_bounds__(256, 3)
void attn_kernel()
{
    extern __shared__ char sm[];
    const uint32_t sb = smem_u32(sm);

    const int qt = gridDim.x - 1 - blockIdx.x;                   // heavy first
    const int h = blockIdx.y, b = blockIdx.z;
    const int tid = threadIdx.x, lane = tid & 31, wid = tid >> 5;
    const int g = lane >> 2, tg = lane & 3;

    const size_t tok0 = (size_t)(b * L_SEQ + qt * 128);
    const int row_base = qt * 128 + wid * 16;
    const int row_max  = row_base + 15;

    auto issue_q = [&]() {
        // 256 x 16B, 1 per thread
        int row = tid >> 1, seg = tid & 1;
        uint32_t dst = sb + SM_Q + (uint32_t)row * QPITCH + seg * 16;
        cp_async16(dst, g_Q16 + (tok0 + row) * NQK + h * FDIM + seg * 8);
    };
    auto issue_kv = [&](int kt, int buf) {
        const size_t ktok = (size_t)(b * L_SEQ + kt * 128);
        {
            int row = tid >> 1, seg = tid & 1;
            uint32_t dst = sb + SM_KBUF(buf) + (uint32_t)row * QPITCH + seg * 16;
            cp_async16(dst, g_K16 + (ktok + row) * NQK + h * FDIM + seg * 8);
        }
        #pragma unroll
        for (int i = 0; i < 4; i++) {
            int idx = tid + i * 256, row = idx >> 3, seg = idx & 7;
            uint32_t dst = sb + SM_VBUF(buf) + (uint32_t)row * V_PITCH + seg * 16;
            cp_async16(dst, g_V16 + (ktok + row) * DMODEL + h * VDIM + seg * 8);
        }
    };

    issue_q();
    issue_kv(0, 0);
    CP_COMMIT();
    CP_WAIT0();
    __syncthreads();

    uint32_t q4r[4];
    {
        uint32_t off = (uint32_t)(wid * 16 + (lane & 15)) * QPITCH + ((lane >> 4) << 3) * 2;
        ldmatrix_x4(q4r[0], q4r[1], q4r[2], q4r[3], sb + SM_Q + off);
    }

    const int ktmax = qt;
    if (ktmax >= 1) { issue_kv(1, 1); CP_COMMIT(); }

    float acc[8][4];
    #pragma unroll
    for (int j = 0; j < 8; j++)
        #pragma unroll
        for (int q = 0; q < 4; q++) acc[j][q] = 0.f;
    float dden0 = 0.f, dden1 = 0.f;

    for (int kt = 0; kt <= ktmax; kt++) {
        const int buf = kt & 1;
        if (kt > 0) {
            CP_WAIT0();
            __syncthreads();
            if (kt < ktmax) { issue_kv(kt + 1, buf ^ 1); CP_COMMIT(); }
        }

        if (kt * 128 > row_max) continue;

        const uint32_t kh_b = sb + SM_KBUF(buf);
        const uint32_t vh_b = sb + SM_VBUF(buf);
        const bool need_mask = (kt * 128 + 127 > row_base);

        #pragma unroll
        for (int q4 = 0; q4 < 4; q4++) {
            if (kt * 128 + q4 * 32 > row_max) break;   // fully-masked quarter

            // ---- phase 1: S cols [q4*32, q4*32+32)  (single Q pass)
            float s_acc[4][4];
            #pragma unroll
            for (int jl = 0; jl < 4; jl++)
                #pragma unroll
                for (int e = 0; e < 4; e++) s_acc[jl][e] = 0.f;

            #pragma unroll
            for (int jj = 0; jj < 2; jj++) {
                uint32_t koff = (uint32_t)(q4 * 32 + jj * 16 + (lane & 7)
                                           + ((lane & 16) ? 8 : 0)) * QPITCH
                              + ((lane & 8) ? 16 : 0);
                uint32_t kh4[4];
                ldmatrix_x4(kh4[0], kh4[1], kh4[2], kh4[3], kh_b + koff);
                #pragma unroll
                for (int sub = 0; sub < 2; sub++)
                    mma16816h(s_acc[jj * 2 + sub], q4r, &kh4[sub * 2]);
            }

            // ---- phi + mask + denominator; pack phi single fp16 (A frags)
            uint32_t pah[8];
            #pragma unroll
            for (int jl = 0; jl < 4; jl++) {
                const int j = q4 * 4 + jl;
                float ph[4];
                #pragma unroll
                for (int e = 0; e < 4; e++) {
                    float s = s_acc[jl][e] * 0.25f;
                    float phi = fmaf(s, fmaf(0.5f, s, 1.f), 1.f);
                    if (need_mask) {
                        int col = kt * 128 + j * 8 + tg * 2 + (e & 1);
                        int row = row_base + g + ((e >= 2) ? 8 : 0);
                        if (col > row) phi = 0.f;
                    }
                    ph[e] = phi;
                }
                dden0 += ph[0] + ph[1];
                dden1 += ph[2] + ph[3];
                pah[jl * 2 + 0] = pack2h(ph[0], ph[1]);
                pah[jl * 2 + 1] = pack2h(ph[2], ph[3]);
            }

            // ---- phase 2 (single pass): acc += A(16 x 32) @ V(32 x 64)
            #pragma unroll
            for (int ks2 = 0; ks2 < 2; ks2++) {
                const int ksi = q4 * 2 + ks2;
                const uint32_t* ah = &pah[ks2 * 4];
                #pragma unroll
                for (int jp = 0; jp < 4; jp++) {
                    uint32_t voff = (uint32_t)(ksi * 16 + (lane & 15)) * V_PITCH
                                  + (jp * 16 + ((lane >> 4) << 3)) * 2;
                    uint32_t vh4[4];
                    ldmatrix_x4_t(vh4[0], vh4[1], vh4[2], vh4[3], vh_b + voff);
                    mma16816h(acc[jp * 2 + 0], ah, &vh4[0]);
                    mma16816h(acc[jp * 2 + 1], ah, &vh4[2]);
                }
            }
        }
    }

    // ---- denominator: quad shuffle reduction
    dden0 += __shfl_xor_sync(0xffffffff, dden0, 1);
    dden0 += __shfl_xor_sync(0xffffffff, dden0, 2);
    dden1 += __shfl_xor_sync(0xffffffff, dden1, 1);
    dden1 += __shfl_xor_sync(0xffffffff, dden1, 2);
    const float z0 = 1.f / (dden0 + 1e-12f);
    const float z1 = 1.f / (dden1 + 1e-12f);

    // ---- epilogue: Y written as fp16 hi/lo split (out-proj is 2-pass fp16)
    {
        const size_t grow0 = tok0 + wid * 16 + g;
        #pragma unroll
        for (int j = 0; j < 8; j++) {
            const int col = h * VDIM + j * 8 + tg * 2;
            uint32_t h0, l0, h1, l1;
            split2h(acc[j][0] * z0, acc[j][1] * z0, h0, l0);
            split2h(acc[j][2] * z1, acc[j][3] * z1, h1, l1);
            *(uint32_t*)&g_Yh16[grow0 * DMODEL + col]       = h0;
            *(uint32_t*)&g_Yl16[grow0 * DMODEL + col]       = l0;
            *(uint32_t*)&g_Yh16[(grow0 + 8) * DMODEL + col] = h1;
            *(uint32_t*)&g_Yl16[(grow0 + 8) * DMODEL + col] = l1;
        }
    }
}

// ---------------------------------------------------------------------------
extern "C" void kernel_launch(void* const* d_in, const int* in_sizes, int n_in,
                              void* d_out, int out_size)
{
    const float* X  = (const float*)d_in[0];
    const float* Wq = (const float*)d_in[1];
    const float* Wk = (const float*)d_in[2];
    const float* Wv = (const float*)d_in[3];
    const float* Wo = (const float*)d_in[4];
    float* out = (float*)d_out;

    __half *Xhi, *Xlo, *Yhi, *Ylo;
    cudaGetSymbolAddress((void**)&Xhi, g_Xh16);
    cudaGetSymbolAddress((void**)&Xlo, g_Xl16);
    cudaGetSymbolAddress((void**)&Yhi, g_Yh16);
    cudaGetSymbolAddress((void**)&Ylo, g_Yl16);

    cudaFuncSetAttribute(gemm_qkv, cudaFuncAttributeMaxDynamicSharedMemorySize, GEMM_SMEM);
    cudaFuncSetAttribute(gemm_out, cudaFuncAttributeMaxDynamicSharedMemorySize, GEMM_SMEM);
    cudaFuncSetAttribute(attn_kernel, cudaFuncAttributeMaxDynamicSharedMemorySize, ATTN_SMEM);

    const int n4 = MTOT * DMODEL / 4;
    split_fp16<<<(n4 + 255) / 256, 256>>>((const float4*)X, (uint2*)Xhi, (uint2*)Xlo, n4);
    transpose_all<<<dim3(32, 32, 4), dim3(32, 32)>>>(Wq, Wk, Wv, Wo);

    // fused Q/K/V projections (V,K: 1-pass; Q: 2-pass input, fp16 out), KC=64
    gemm_qkv<<<384, 256, GEMM_SMEM>>>(Xhi, Xlo);
    // causal taylor-exp attention (both phases single-pass fp16)
    attn_kernel<<<dim3(L_SEQ / 128, NH, B_SZ), 256, ATTN_SMEM>>>();
    // output projection, 2-pass fp16, fp32 out -> d_out, KC=64
    gemm_out<<<dim3(DMODEL / 128, MTOT / 128), 256, GEMM_SMEM>>>(Yhi, Ylo, out);
}

// round 17
// speedup vs baseline: 5.1905x; 1.1447x over previous
#include <cuda_runtime.h>
#include <cuda_bf16.h>
#include <cuda_fp16.h>
#include <cstdint>

#define B_SZ   2
#define L_SEQ  2048
#define NH     16
#define FDIM   16
#define VDIM   64
#define DMODEL 1024
#define MTOT   (B_SZ * L_SEQ)   // 4096
#define NQK    (NH * FDIM)      // 256

// ------------------------------ scratch (device globals) -------------------
__device__ __half g_Q16[(size_t)MTOT * NQK];
__device__ __half g_K16[(size_t)MTOT * NQK];
__device__ __half g_V16[(size_t)MTOT * DMODEL];

__device__ __half g_Xh16[(size_t)MTOT * DMODEL];
__device__ __half g_Xl16[(size_t)MTOT * DMODEL];
__device__ __half g_Y16[(size_t)MTOT * DMODEL];

__device__ __half g_WqT16[(size_t)NQK * DMODEL];
__device__ __half g_WkT16[(size_t)NQK * DMODEL];
__device__ __half g_WvT16[(size_t)DMODEL * DMODEL];
__device__ __half g_WoT16[(size_t)DMODEL * DMODEL];

// ------------------------------ helpers ------------------------------------
__device__ __forceinline__ uint32_t smem_u32(const void* p) {
    uint32_t a;
    asm("{ .reg .u64 t; cvta.to.shared.u64 t, %1; cvt.u32.u64 %0, t; }" : "=r"(a) : "l"(p));
    return a;
}
__device__ __forceinline__ void cp_async16(uint32_t s, const void* g) {
    asm volatile("cp.async.cg.shared.global [%0], [%1], 16;" :: "r"(s), "l"(g));
}
#define CP_COMMIT() asm volatile("cp.async.commit_group;" ::: "memory")
#define CP_WAIT0()  asm volatile("cp.async.wait_group 0;" ::: "memory")

__device__ __forceinline__ void ldmatrix_x4(uint32_t& r0, uint32_t& r1, uint32_t& r2, uint32_t& r3,
                                            uint32_t addr) {
    asm volatile("ldmatrix.sync.aligned.m8n8.x4.shared.b16 {%0,%1,%2,%3}, [%4];"
                 : "=r"(r0), "=r"(r1), "=r"(r2), "=r"(r3) : "r"(addr));
}
__device__ __forceinline__ void ldmatrix_x4_t(uint32_t& r0, uint32_t& r1, uint32_t& r2, uint32_t& r3,
                                              uint32_t addr) {
    asm volatile("ldmatrix.sync.aligned.m8n8.x4.trans.shared.b16 {%0,%1,%2,%3}, [%4];"
                 : "=r"(r0), "=r"(r1), "=r"(r2), "=r"(r3) : "r"(addr));
}
__device__ __forceinline__ void mma16816h(float* d, const uint32_t* a, const uint32_t* b) {
    asm volatile(
        "mma.sync.aligned.m16n8k16.row.col.f32.f16.f16.f32 "
        "{%0,%1,%2,%3},{%4,%5,%6,%7},{%8,%9},{%0,%1,%2,%3};"
        : "+f"(d[0]), "+f"(d[1]), "+f"(d[2]), "+f"(d[3])
        : "r"(a[0]), "r"(a[1]), "r"(a[2]), "r"(a[3]), "r"(b[0]), "r"(b[1]));
}
// fp16 hi/lo split, packed pairwise (low half = y0)
__device__ __forceinline__ void split2h(float y0, float y1, uint32_t& hi, uint32_t& lo) {
    __half2 h = __floats2half2_rn(y0, y1);
    float2 f = __half22float2(h);
    __half2 l = __floats2half2_rn(y0 - f.x, y1 - f.y);
    hi = *(uint32_t*)&h;
    lo = *(uint32_t*)&l;
}
__device__ __forceinline__ uint32_t pack2h(float y0, float y1) {
    __half2 h = __floats2half2_rn(y0, y1);
    return *(uint32_t*)&h;
}

// ------------------------------ prep kernels -------------------------------
__global__ void split_fp16(const float4* __restrict__ x,
                           uint2* __restrict__ hi, uint2* __restrict__ lo, int n4)
{
    int i = blockIdx.x * blockDim.x + threadIdx.x;
    if (i >= n4) return;
    float4 v = x[i];
    uint32_t h0, l0, h1, l1;
    split2h(v.x, v.y, h0, l0);
    split2h(v.z, v.w, h1, l1);
    hi[i] = make_uint2(h0, h1);
    lo[i] = make_uint2(l0, l1);
}

// All 4 weight transposes fused: W (K x N) row-major -> T (N x K) single fp16.
__global__ void transpose_all(const float* __restrict__ Wq, const float* __restrict__ Wk,
                              const float* __restrict__ Wv, const float* __restrict__ Wo)
{
    __shared__ float t[32][33];
    const int z = blockIdx.z;
    const float* W;
    __half* Th;
    int N;
    if (z == 0)      { W = Wq; Th = g_WqT16; N = NQK; }
    else if (z == 1) { W = Wk; Th = g_WkT16; N = NQK; }
    else if (z == 2) { W = Wv; Th = g_WvT16; N = DMODEL; }
    else             { W = Wo; Th = g_WoT16; N = DMODEL; }
    const int n0 = blockIdx.x * 32;
    if (n0 >= N) return;
    const int k0 = blockIdx.y * 32;
    t[threadIdx.y][threadIdx.x] = W[(size_t)(k0 + threadIdx.y) * N + n0 + threadIdx.x];
    __syncthreads();
    float v = t[threadIdx.x][threadIdx.y];
    int n = n0 + threadIdx.y, k = k0 + threadIdx.x;
    Th[(size_t)n * DMODEL + k] = __float2half_rn(v);
}

// ------------------------------ HMMA GEMM body -----------------------------
// C(M x Nw) = A @ B16(Nw x K)^T, fp32 acc. KC=64 double-buffered cp.async.
// two_pass=1: A = Ahi + Alo (fp16 split, exact);  two_pass=0: A = Ahi only.
// modes: 0 = fp32 C, 3 = fp16 single out
#define KC        64
#define ROWB      144                   // 64 fp16 = 128B data + 16B pad
#define ARR_BYTES (128 * ROWB)          // 18432
#define BUF_BYTES (3 * ARR_BYTES)       // 55296: Ah, Al, B
#define GEMM_SMEM (2 * BUF_BYTES)       // 110592 (2 CTAs/SM)

__device__ __forceinline__ void gemm_body(
    const __half* __restrict__ Ahi, const __half* __restrict__ Alo,
    const __half* __restrict__ B16,
    float* __restrict__ C, void* __restrict__ Oh,
    int mode, int two_pass, int m0, int n0, int Nw, char* smem)
{
    const uint32_t sb = smem_u32(smem);
    const int tid = threadIdx.x, lane = tid & 31, wid = tid >> 5;
    const int warp_m = wid & 3, warp_n = wid >> 2;
    const int nchunk = DMODEL / KC;      // 16

    auto issue_chunk = [&](int c) {
        const uint32_t base = sb + (c & 1) * BUF_BYTES;
        const int k0 = c * KC;
        #pragma unroll
        for (int i = 0; i < 4; i++) {
            const int idx = tid + i * 256;
            const int row = idx >> 3, seg = idx & 7;
            const uint32_t soff = (uint32_t)row * ROWB + seg * 16;
            const size_t ga = (size_t)(m0 + row) * DMODEL + k0 + seg * 8;
            const size_t gb = (size_t)(n0 + row) * DMODEL + k0 + seg * 8;
            cp_async16(base + soff, Ahi + ga);
            if (two_pass) cp_async16(base + ARR_BYTES + soff, Alo + ga);
            cp_async16(base + 2 * ARR_BYTES + soff, B16 + gb);
        }
    };

    float acc[2][8][4];
    #pragma unroll
    for (int mt = 0; mt < 2; mt++)
        #pragma unroll
        for (int j = 0; j < 8; j++)
            #pragma unroll
            for (int q = 0; q < 4; q++) acc[mt][j][q] = 0.f;

    issue_chunk(0);
    CP_COMMIT();

    const int arow_l = (lane & 15);
    const int akc_l  = (lane >> 4) << 3;
    const int brow_l = (lane & 7) + ((lane & 16) ? 8 : 0);
    const int bkc_l  = (lane & 8) ? 8 : 0;

    for (int c = 0; c < nchunk; c++) {
        CP_WAIT0();
        __syncthreads();
        if (c + 1 < nchunk) { issue_chunk(c + 1); CP_COMMIT(); }

        const uint32_t base = sb + (c & 1) * BUF_BYTES;
        #pragma unroll
        for (int ks = 0; ks < 4; ks++) {
            uint32_t ah[2][4], al[2][4];
            #pragma unroll
            for (int mt = 0; mt < 2; mt++) {
                uint32_t addr = base + (uint32_t)(warp_m * 32 + mt * 16 + arow_l) * ROWB
                              + (ks * 16 + akc_l) * 2;
                ldmatrix_x4(ah[mt][0], ah[mt][1], ah[mt][2], ah[mt][3], addr);
                if (two_pass)
                    ldmatrix_x4(al[mt][0], al[mt][1], al[mt][2], al[mt][3], addr + ARR_BYTES);
            }
            #pragma unroll
            for (int jp = 0; jp < 4; jp++) {
                uint32_t baddr = base + 2 * ARR_BYTES
                               + (uint32_t)(warp_n * 64 + jp * 16 + brow_l) * ROWB
                               + (ks * 16 + bkc_l) * 2;
                uint32_t bh[4];
                ldmatrix_x4(bh[0], bh[1], bh[2], bh[3], baddr);
                #pragma unroll
                for (int sub = 0; sub < 2; sub++) {
                    const int j = jp * 2 + sub;
                    #pragma unroll
                    for (int mt = 0; mt < 2; mt++) {
                        mma16816h(acc[mt][j], ah[mt], &bh[sub * 2]);
                        if (two_pass) mma16816h(acc[mt][j], al[mt], &bh[sub * 2]);
                    }
                }
            }
        }
    }

    #pragma unroll
    for (int mt = 0; mt < 2; mt++) {
        const int r0 = m0 + warp_m * 32 + mt * 16 + (lane >> 2);
        #pragma unroll
        for (int j = 0; j < 8; j++) {
            const int col = n0 + warp_n * 64 + j * 8 + (lane & 3) * 2;
            const size_t i0 = (size_t)r0 * Nw + col;
            const size_t i1 = (size_t)(r0 + 8) * Nw + col;
            if (mode == 0) {
                *(float2*)&C[i0] = make_float2(acc[mt][j][0], acc[mt][j][1]);
                *(float2*)&C[i1] = make_float2(acc[mt][j][2], acc[mt][j][3]);
            } else {
                ((uint32_t*)((__half*)Oh + i0))[0] = pack2h(acc[mt][j][0], acc[mt][j][1]);
                ((uint32_t*)((__half*)Oh + i1))[0] = pack2h(acc[mt][j][2], acc[mt][j][3]);
            }
        }
    }
}

// Fused Q/K/V projection: 384 CTAs (V first).
// V & K: 1-pass (outputs fp16-rounded anyway). Q: 2-pass exact input, fp16 out.
__global__ __launch_bounds__(256, 2)
void gemm_qkv(const __half* __restrict__ Xhi, const __half* __restrict__ Xlo)
{
    extern __shared__ char smem[];
    const int bid = blockIdx.x;
    const __half* B16;
    void *oh = nullptr;
    int m0, n0, Nw, two_pass;
    if (bid < 256) {                       // V: 1-pass
        m0 = (bid >> 3) * 128; n0 = (bid & 7) * 128; Nw = DMODEL; two_pass = 0;
        B16 = g_WvT16; oh = g_V16;
    } else if (bid < 320) {                // Q: 2-pass input, single fp16 out
        const int t = bid - 256;
        m0 = (t >> 1) * 128; n0 = (t & 1) * 128; Nw = NQK; two_pass = 1;
        B16 = g_WqT16; oh = g_Q16;
    } else {                               // K: 1-pass
        const int t = bid - 320;
        m0 = (t >> 1) * 128; n0 = (t & 1) * 128; Nw = NQK; two_pass = 0;
        B16 = g_WkT16; oh = g_K16;
    }
    gemm_body(Xhi, Xlo, B16, nullptr, oh, 3, two_pass, m0, n0, Nw, smem);
}

// Output projection: 1-pass (Y single fp16), fp32 out.
__global__ __launch_bounds__(256, 2)
void gemm_out(const __half* __restrict__ Y16, float* __restrict__ out)
{
    extern __shared__ char smem[];
    gemm_body(Y16, nullptr, g_WoT16, out, nullptr, 0, 0,
              blockIdx.y * 128, blockIdx.x * 128, DMODEL, smem);
}

// ------------------------------ attention ----------------------------------
// 128-row q tiles, 8 warps x 16 rows. fp16 path:
//   phase 1: S = Q16 . K16      (1 MMA pass)
//   phase 2: acc += A16 . V16   (1 MMA pass; phi single fp16)
// phi = 1 + d/4 + d^2/32 folded into 2 FMAs from the raw dot d.
// Exact per-quarter causal break inside the diagonal tile.
// Y written as single fp16 (out-proj is 1-pass).
#define QPITCH   48
#define V_PITCH  144
#define SM_Q     0
#define SM_KBUF(b) (6144 + (b) * 24576)
#define SM_VBUF(b) (6144 + (b) * 24576 + 6144)
#define ATTN_SMEM 55296

__global__ __launch_bounds__(256, 3)
void attn_kernel()
{
    extern __shared__ char sm[];
    const uint32_t sb = smem_u32(sm);

    const int qt = gridDim.x - 1 - blockIdx.x;                   // heavy first
    const int h = blockIdx.y, b = blockIdx.z;
    const int tid = threadIdx.x, lane = tid & 31, wid = tid >> 5;
    const int g = lane >> 2, tg = lane & 3;

    const size_t tok0 = (size_t)(b * L_SEQ + qt * 128);
    const int row_base = qt * 128 + wid * 16;
    const int row_max  = row_base + 15;

    auto issue_q = [&]() {
        int row = tid >> 1, seg = tid & 1;
        uint32_t dst = sb + SM_Q + (uint32_t)row * QPITCH + seg * 16;
        cp_async16(dst, g_Q16 + (tok0 + row) * NQK + h * FDIM + seg * 8);
    };
    auto issue_kv = [&](int kt, int buf) {
        const size_t ktok = (size_t)(b * L_SEQ + kt * 128);
        {
            int row = tid >> 1, seg = tid & 1;
            uint32_t dst = sb + SM_KBUF(buf) + (uint32_t)row * QPITCH + seg * 16;
            cp_async16(dst, g_K16 + (ktok + row) * NQK + h * FDIM + seg * 8);
        }
        #pragma unroll
        for (int i = 0; i < 4; i++) {
            int idx = tid + i * 256, row = idx >> 3, seg = idx & 7;
            uint32_t dst = sb + SM_VBUF(buf) + (uint32_t)row * V_PITCH + seg * 16;
            cp_async16(dst, g_V16 + (ktok + row) * DMODEL + h * VDIM + seg * 8);
        }
    };

    issue_q();
    issue_kv(0, 0);
    CP_COMMIT();
    CP_WAIT0();
    __syncthreads();

    uint32_t q4r[4];
    {
        uint32_t off = (uint32_t)(wid * 16 + (lane & 15)) * QPITCH + ((lane >> 4) << 3) * 2;
        ldmatrix_x4(q4r[0], q4r[1], q4r[2], q4r[3], sb + SM_Q + off);
    }

    const int ktmax = qt;
    if (ktmax >= 1) { issue_kv(1, 1); CP_COMMIT(); }

    float acc[8][4];
    #pragma unroll
    for (int j = 0; j < 8; j++)
        #pragma unroll
        for (int q = 0; q < 4; q++) acc[j][q] = 0.f;
    float dden0 = 0.f, dden1 = 0.f;

    for (int kt = 0; kt <= ktmax; kt++) {
        const int buf = kt & 1;
        if (kt > 0) {
            CP_WAIT0();
            __syncthreads();
            if (kt < ktmax) { issue_kv(kt + 1, buf ^ 1); CP_COMMIT(); }
        }

        if (kt * 128 > row_max) continue;

        const uint32_t kh_b = sb + SM_KBUF(buf);
        const uint32_t vh_b = sb + SM_VBUF(buf);
        const bool need_mask = (kt * 128 + 127 > row_base);

        #pragma unroll
        for (int q4 = 0; q4 < 4; q4++) {
            if (kt * 128 + q4 * 32 > row_max) break;   // fully-masked quarter

            // ---- phase 1: S cols [q4*32, q4*32+32)
            float s_acc[4][4];
            #pragma unroll
            for (int jl = 0; jl < 4; jl++)
                #pragma unroll
                for (int e = 0; e < 4; e++) s_acc[jl][e] = 0.f;

            #pragma unroll
            for (int jj = 0; jj < 2; jj++) {
                uint32_t koff = (uint32_t)(q4 * 32 + jj * 16 + (lane & 7)
                                           + ((lane & 16) ? 8 : 0)) * QPITCH
                              + ((lane & 8) ? 16 : 0);
                uint32_t kh4[4];
                ldmatrix_x4(kh4[0], kh4[1], kh4[2], kh4[3], kh_b + koff);
                #pragma unroll
                for (int sub = 0; sub < 2; sub++)
                    mma16816h(s_acc[jj * 2 + sub], q4r, &kh4[sub * 2]);
            }

            // ---- phi = 1 + d/4 + d^2/32 (2 FMAs) + mask + denom + fp16 pack
            uint32_t pah[8];
            #pragma unroll
            for (int jl = 0; jl < 4; jl++) {
                const int j = q4 * 4 + jl;
                float ph[4];
                #pragma unroll
                for (int e = 0; e < 4; e++) {
                    float d = s_acc[jl][e];
                    float phi = fmaf(d, fmaf(d, 0.03125f, 0.25f), 1.f);
                    if (need_mask) {
                        int col = kt * 128 + j * 8 + tg * 2 + (e & 1);
                        int row = row_base + g + ((e >= 2) ? 8 : 0);
                        if (col > row) phi = 0.f;
                    }
                    ph[e] = phi;
                }
                dden0 += ph[0] + ph[1];
                dden1 += ph[2] + ph[3];
                pah[jl * 2 + 0] = pack2h(ph[0], ph[1]);
                pah[jl * 2 + 1] = pack2h(ph[2], ph[3]);
            }

            // ---- phase 2 (single pass): acc += A(16 x 32) @ V(32 x 64)
            #pragma unroll
            for (int ks2 = 0; ks2 < 2; ks2++) {
                const int ksi = q4 * 2 + ks2;
                const uint32_t* ah = &pah[ks2 * 4];
                #pragma unroll
                for (int jp = 0; jp < 4; jp++) {
                    uint32_t voff = (uint32_t)(ksi * 16 + (lane & 15)) * V_PITCH
                                  + (jp * 16 + ((lane >> 4) << 3)) * 2;
                    uint32_t vh4[4];
                    ldmatrix_x4_t(vh4[0], vh4[1], vh4[2], vh4[3], vh_b + voff);
                    mma16816h(acc[jp * 2 + 0], ah, &vh4[0]);
                    mma16816h(acc[jp * 2 + 1], ah, &vh4[2]);
                }
            }
        }
    }

    // ---- denominator: quad shuffle reduction
    dden0 += __shfl_xor_sync(0xffffffff, dden0, 1);
    dden0 += __shfl_xor_sync(0xffffffff, dden0, 2);
    dden1 += __shfl_xor_sync(0xffffffff, dden1, 1);
    dden1 += __shfl_xor_sync(0xffffffff, dden1, 2);
    const float z0 = 1.f / (dden0 + 1e-12f);
    const float z1 = 1.f / (dden1 + 1e-12f);

    // ---- epilogue: Y written as single fp16
    {
        const size_t grow0 = tok0 + wid * 16 + g;
        #pragma unroll
        for (int j = 0; j < 8; j++) {
            const int col = h * VDIM + j * 8 + tg * 2;
            *(uint32_t*)&g_Y16[grow0 * DMODEL + col]       = pack2h(acc[j][0] * z0, acc[j][1] * z0);
            *(uint32_t*)&g_Y16[(grow0 + 8) * DMODEL + col] = pack2h(acc[j][2] * z1, acc[j][3] * z1);
        }
    }
}

// ---------------------------------------------------------------------------
extern "C" void kernel_launch(void* const* d_in, const int* in_sizes, int n_in,
                              void* d_out, int out_size)
{
    const float* X  = (const float*)d_in[0];
    const float* Wq = (const float*)d_in[1];
    const float* Wk = (const float*)d_in[2];
    const float* Wv = (const float*)d_in[3];
    const float* Wo = (const float*)d_in[4];
    float* out = (float*)d_out;

    __half *Xhi, *Xlo, *Y16;
    cudaGetSymbolAddress((void**)&Xhi, g_Xh16);
    cudaGetSymbolAddress((void**)&Xlo, g_Xl16);
    cudaGetSymbolAddress((void**)&Y16, g_Y16);

    cudaFuncSetAttribute(gemm_qkv, cudaFuncAttributeMaxDynamicSharedMemorySize, GEMM_SMEM);
    cudaFuncSetAttribute(gemm_out, cudaFuncAttributeMaxDynamicSharedMemorySize, GEMM_SMEM);
    cudaFuncSetAttribute(attn_kernel, cudaFuncAttributeMaxDynamicSharedMemorySize, ATTN_SMEM);

    const int n4 = MTOT * DMODEL / 4;
    split_fp16<<<(n4 + 255) / 256, 256>>>((const float4*)X, (uint2*)Xhi, (uint2*)Xlo, n4);
    transpose_all<<<dim3(32, 32, 4), dim3(32, 32)>>>(Wq, Wk, Wv, Wo);

    // fused Q/K/V projections (V,K: 1-pass; Q: 2-pass input, fp16 out), KC=64
    gemm_qkv<<<384, 256, GEMM_SMEM>>>(Xhi, Xlo);
    // causal taylor-exp attention (both phases single-pass fp16)
    attn_kernel<<<dim3(L_SEQ / 128, NH, B_SZ), 256, ATTN_SMEM>>>();
    // output projection, 1-pass fp16 (Y single), fp32 out -> d_out
    gemm_out<<<dim3(DMODEL / 128, MTOT / 128), 256, GEMM_SMEM>>>(Y16, out);
}